// round 1
// baseline (speedup 1.0000x reference)
#include <cuda_runtime.h>
#include <math.h>

#define L_SEQ   2048
#define NBATCH  2
#define HIDDEN  2048
#define NH      64
#define PDIM    64
#define NDIM    128
#define CSZ     256
#define NC      8
#define D_INNER 4096
#define CONV_DIM 4352
#define PROJ    8512

// ---------------- scratch (device globals: allocation-free) ----------------
__device__ float g_proj  [NBATCH*L_SEQ*PROJ];          // [b,l,8512]
__device__ float g_xc    [NBATCH*L_SEQ*CONV_DIM];      // conv+silu output
__device__ float g_dtsp  [NBATCH*L_SEQ*NH];            // softplus(dt)
__device__ float g_Acum  [NBATCH*NH*NC*CSZ];           // inclusive cumsum of dt*A
__device__ float g_Gt    [NBATCH*NC*CSZ*CSZ];          // Gt[s,l] = B[s]·C[l]
__device__ float g_states[NBATCH*NC*NH*PDIM*NDIM];     // per-chunk states
__device__ float g_prev  [NBATCH*NC*NH*PDIM*NDIM];     // scanned prev states
__device__ float g_y     [NBATCH*L_SEQ*D_INNER];       // y, then normed in place

// ---------------- generic NT SGEMM: C[m,n] = sum_k A[m,k]*B[n,k] -----------
// BM=BN=128, BK=16, 256 threads, 8x8 per thread.
// Requires: M % 128 == 0, K % 16 == 0, N % 4 == 0 (N edge guarded).
__global__ __launch_bounds__(256) void sgemm_nt(
    const float* __restrict__ A, const float* __restrict__ B, float* __restrict__ C,
    int M, int N, int K, int lda, int ldb, int ldc,
    long long sA, long long sB, long long sC)
{
    __shared__ float As[16][128];
    __shared__ float Bs[16][128];
    A += (long long)blockIdx.z * sA;
    B += (long long)blockIdx.z * sB;
    C += (long long)blockIdx.z * sC;
    int tid = threadIdx.x;
    int bm = blockIdx.y * 128, bn = blockIdx.x * 128;
    int tx = (tid & 15) * 8, ty = (tid >> 4) * 8;
    float acc[8][8];
#pragma unroll
    for (int i = 0; i < 8; i++)
#pragma unroll
        for (int j = 0; j < 8; j++) acc[i][j] = 0.f;

    for (int kk = 0; kk < K; kk += 16) {
#pragma unroll
        for (int i = 0; i < 2; i++) {
            int f = tid + i * 256;          // 0..511 float4 slots
            int row = f >> 2, c4 = (f & 3) << 2;
            float4 va = *(const float4*)(A + (long long)(bm + row) * lda + kk + c4);
            As[c4+0][row] = va.x; As[c4+1][row] = va.y;
            As[c4+2][row] = va.z; As[c4+3][row] = va.w;
            float4 vb = make_float4(0.f,0.f,0.f,0.f);
            int gb = bn + row;
            if (gb < N) vb = *(const float4*)(B + (long long)gb * ldb + kk + c4);
            Bs[c4+0][row] = vb.x; Bs[c4+1][row] = vb.y;
            Bs[c4+2][row] = vb.z; Bs[c4+3][row] = vb.w;
        }
        __syncthreads();
#pragma unroll
        for (int k = 0; k < 16; k++) {
            float4 a0 = *(const float4*)&As[k][ty];
            float4 a1 = *(const float4*)&As[k][ty+4];
            float4 b0 = *(const float4*)&Bs[k][tx];
            float4 b1 = *(const float4*)&Bs[k][tx+4];
            float ra[8] = {a0.x,a0.y,a0.z,a0.w,a1.x,a1.y,a1.z,a1.w};
            float rb[8] = {b0.x,b0.y,b0.z,b0.w,b1.x,b1.y,b1.z,b1.w};
#pragma unroll
            for (int i = 0; i < 8; i++)
#pragma unroll
                for (int j = 0; j < 8; j++) acc[i][j] += ra[i]*rb[j];
        }
        __syncthreads();
    }
#pragma unroll
    for (int i = 0; i < 8; i++) {
        float* crow = C + (long long)(bm + ty + i) * ldc + bn + tx;
#pragma unroll
        for (int j = 0; j < 8; j += 4) {
            if (bn + tx + j < N)
                *(float4*)(crow + j) = make_float4(acc[i][j],acc[i][j+1],acc[i][j+2],acc[i][j+3]);
        }
    }
}

// ---------------- causal depthwise conv (K=4) + bias + SiLU ----------------
__global__ __launch_bounds__(256) void conv_silu_kernel(
    const float* __restrict__ cw, const float* __restrict__ cb)
{
    int idx = blockIdx.x * 256 + threadIdx.x;      // over B*L*CONV_DIM exactly
    int c = idx % CONV_DIM;
    int t = idx / CONV_DIM;
    int l = t % L_SEQ, b = t / L_SEQ;
    float acc = cb[c];
#pragma unroll
    for (int k = 0; k < 4; k++) {
        int ll = l - 3 + k;
        if (ll >= 0)
            acc += g_proj[((size_t)(b*L_SEQ + ll))*PROJ + D_INNER + c] * cw[c*4 + k];
    }
    acc = acc / (1.f + __expf(-acc));
    g_xc[(size_t)t*CONV_DIM + c] = acc;
}

// ---------------- dt softplus + per-chunk inclusive cumsum of dt*A ---------
__global__ __launch_bounds__(256) void dtscan_kernel(
    const float* __restrict__ dt_bias, const float* __restrict__ A_log)
{
    __shared__ float s[CSZ];
    int z = blockIdx.x;                         // b*512 + h*8 + c
    int c = z & 7, h = (z >> 3) & 63, b = z >> 9;
    int l = threadIdx.x;
    int gl = c*CSZ + l;
    float raw = g_proj[((size_t)(b*L_SEQ + gl))*PROJ + D_INNER + CONV_DIM + h] + dt_bias[h];
    float dts = (raw > 20.f) ? raw : log1pf(__expf(raw));
    g_dtsp[(size_t)(b*L_SEQ + gl)*NH + h] = dts;
    s[l] = -dts * __expf(A_log[h]);
    __syncthreads();
    for (int off = 1; off < CSZ; off <<= 1) {
        float v = (l >= off) ? s[l - off] : 0.f;
        __syncthreads();
        s[l] += v;
        __syncthreads();
    }
    g_Acum[((size_t)((b*NH + h)*NC + c))*CSZ + l] = s[l];
}

// ---------------- intra-chunk diagonal output (+ D*x), per (b,c,h) --------
// dyn smem: Xs[256*64] + Acs[256] + dts[256]
__global__ __launch_bounds__(256) void ydiag_kernel(const float* __restrict__ Dp)
{
    extern __shared__ float sm[];
    float* Xs    = sm;
    float* Acs   = sm + CSZ*PDIM;
    float* dts_s = Acs + CSZ;
    int z = blockIdx.x;
    int h = z & 63, c = (z >> 6) & 7, b = z >> 9;
    int tid = threadIdx.x;
    Acs[tid]   = g_Acum[((size_t)((b*NH + h)*NC + c))*CSZ + tid];
    dts_s[tid] = g_dtsp[(size_t)(b*L_SEQ + c*CSZ + tid)*NH + h];
    __syncthreads();
    int p = tid & 63, l0 = tid >> 6;
    for (int i = 0; i < 64; i++) {
        int l = l0*64 + i;
        float xv = g_xc[(size_t)(b*L_SEQ + c*CSZ + l)*CONV_DIM + h*64 + p];
        Xs[l*64 + p] = xv * dts_s[l];
    }
    __syncthreads();

    int l = tid;
    float al = Acs[l];
    float4 acc[16];
#pragma unroll
    for (int j = 0; j < 16; j++) acc[j] = make_float4(0.f,0.f,0.f,0.f);
    const float* gt = g_Gt + (size_t)(b*NC + c)*CSZ*CSZ + l;   // Gt[s,l], l fast
    for (int s = 0; s <= l; s++) {
        float w = gt[s*CSZ] * __expf(al - Acs[s]);
        const float4* xr = (const float4*)(Xs + s*64);
#pragma unroll
        for (int j = 0; j < 16; j++) {
            float4 v = xr[j];
            acc[j].x += w*v.x; acc[j].y += w*v.y; acc[j].z += w*v.z; acc[j].w += w*v.w;
        }
    }
    // + D_param[h] * x  (x = Xdt / dt)
    float dcoef = Dp[h] / fmaxf(dts_s[l], 1e-30f);
    {
        const float4* xr = (const float4*)(Xs + l*64);
#pragma unroll
        for (int j = 0; j < 16; j++) {
            float4 v = xr[j];
            acc[j].x += dcoef*v.x; acc[j].y += dcoef*v.y;
            acc[j].z += dcoef*v.z; acc[j].w += dcoef*v.w;
        }
    }
    __syncthreads();
    float4* xw = (float4*)(Xs + l*64);
#pragma unroll
    for (int j = 0; j < 16; j++) xw[j] = acc[j];
    __syncthreads();
    for (int i = 0; i < 64; i++) {
        int ll = l0*64 + i;
        g_y[(size_t)(b*L_SEQ + c*CSZ + ll)*D_INNER + h*64 + p] = Xs[ll*64 + p];
    }
}

// ---------------- per-chunk states: states[p,n]=sum_l B[l,n]*dec[l]*Xdt[l,p]
// dyn smem: Xs[256*64] + dec[256] + dts[256]
__global__ __launch_bounds__(256) void states_kernel()
{
    extern __shared__ float sm[];
    float* Xs    = sm;
    float* dec   = sm + CSZ*PDIM;
    float* dts_s = dec + CSZ;
    int z = blockIdx.x;
    int h = z & 63, c = (z >> 6) & 7, b = z >> 9;
    int tid = threadIdx.x;
    dec[tid]   = g_Acum[((size_t)((b*NH + h)*NC + c))*CSZ + tid];
    dts_s[tid] = g_dtsp[(size_t)(b*L_SEQ + c*CSZ + tid)*NH + h];
    __syncthreads();
    float alast = dec[CSZ-1];
    float aown  = dec[tid];
    __syncthreads();
    dec[tid] = __expf(alast - aown);
    int p = tid & 63, l0 = tid >> 6;
    for (int i = 0; i < 64; i++) {
        int l = l0*64 + i;
        float xv = g_xc[(size_t)(b*L_SEQ + c*CSZ + l)*CONV_DIM + h*64 + p];
        Xs[l*64 + p] = xv * dts_s[l];
    }
    __syncthreads();

    int n = tid & 127, ph = tid >> 7;
    float4 acc[8];
#pragma unroll
    for (int j = 0; j < 8; j++) acc[j] = make_float4(0.f,0.f,0.f,0.f);
    size_t brow = (size_t)(b*L_SEQ + c*CSZ)*CONV_DIM + D_INNER + n;
    for (int l = 0; l < CSZ; l++) {
        float w = g_xc[brow + (size_t)l*CONV_DIM] * dec[l];
        const float4* xr = (const float4*)(Xs + l*64 + ph*32);
#pragma unroll
        for (int j = 0; j < 8; j++) {
            float4 v = xr[j];
            acc[j].x += w*v.x; acc[j].y += w*v.y; acc[j].z += w*v.z; acc[j].w += w*v.w;
        }
    }
    size_t sb = ((size_t)((b*NC + c)*NH + h))*PDIM*NDIM;
#pragma unroll
    for (int j = 0; j < 8; j++) {
        int pb = ph*32 + j*4;
        g_states[sb + (size_t)(pb+0)*NDIM + n] = acc[j].x;
        g_states[sb + (size_t)(pb+1)*NDIM + n] = acc[j].y;
        g_states[sb + (size_t)(pb+2)*NDIM + n] = acc[j].z;
        g_states[sb + (size_t)(pb+3)*NDIM + n] = acc[j].w;
    }
}

// ---------------- inter-chunk scan (8 sequential chunks) -------------------
__global__ __launch_bounds__(256) void scan_kernel()
{
    int idx = blockIdx.x * 256 + threadIdx.x;   // over B*NH*P*N = 1,048,576
    int n = idx & 127;
    int p = (idx >> 7) & 63;
    int h = (idx >> 13) & 63;
    int b = idx >> 19;
    float carry = 0.f;
    for (int c = 0; c < NC; c++) {
        size_t off = ((size_t)((b*NC + c)*NH + h))*PDIM*NDIM + (size_t)p*NDIM + n;
        float dal = g_Acum[((size_t)((b*NH + h)*NC + c))*CSZ + (CSZ-1)];
        float s = g_states[off];
        g_prev[off] = carry;
        carry = carry * __expf(dal) + s;
    }
}

// ---------------- inter-chunk contribution: y += exp(Acum[l]) * C[l]·prev --
__global__ __launch_bounds__(256) void yoff_kernel()
{
    __shared__ float prevT[128*68];   // prevT[n][p], padded row 68
    __shared__ float Acs[CSZ];
    int z = blockIdx.x;
    int h = z & 63, c = (z >> 6) & 7, b = z >> 9;
    int tid = threadIdx.x;
    Acs[tid] = g_Acum[((size_t)((b*NH + h)*NC + c))*CSZ + tid];
    int n = tid & 127, p0 = tid >> 7;
    size_t sb = ((size_t)((b*NC + c)*NH + h))*PDIM*NDIM;
    for (int i = 0; i < 32; i++) {
        int p = p0*32 + i;
        prevT[n*68 + p] = g_prev[sb + (size_t)p*NDIM + n];
    }
    __syncthreads();

    int l = tid;
    float4 acc[16];
#pragma unroll
    for (int j = 0; j < 16; j++) acc[j] = make_float4(0.f,0.f,0.f,0.f);
    const float* crow = g_xc + (size_t)(b*L_SEQ + c*CSZ + l)*CONV_DIM + D_INNER + NDIM;
    for (int n4 = 0; n4 < 32; n4++) {
        float4 cv = *(const float4*)(crow + n4*4);
        float cvals[4] = {cv.x, cv.y, cv.z, cv.w};
#pragma unroll
        for (int u = 0; u < 4; u++) {
            float cval = cvals[u];
            const float4* pr = (const float4*)(prevT + (n4*4 + u)*68);
#pragma unroll
            for (int j = 0; j < 16; j++) {
                float4 v = pr[j];
                acc[j].x += cval*v.x; acc[j].y += cval*v.y;
                acc[j].z += cval*v.z; acc[j].w += cval*v.w;
            }
        }
    }
    float e = __expf(Acs[l]);
    float* yrow = g_y + (size_t)(b*L_SEQ + c*CSZ + l)*D_INNER + h*64;
#pragma unroll
    for (int j = 0; j < 16; j++) {
        float4 v = *(float4*)(yrow + j*4);
        v.x += e*acc[j].x; v.y += e*acc[j].y; v.z += e*acc[j].z; v.w += e*acc[j].w;
        *(float4*)(yrow + j*4) = v;
    }
}

// ---------------- gated RMSNorm (G=1 -> full 4096 group), in place ---------
__global__ __launch_bounds__(256) void norm_kernel(const float* __restrict__ norm_w)
{
    __shared__ float gs[D_INNER];
    __shared__ float red[8];
    int t = blockIdx.x;            // token 0..4095
    int tid = threadIdx.x;
    const float* zrow = g_proj + (size_t)t * PROJ;   // z = first 4096 of proj
    float* yrow = g_y + (size_t)t * D_INNER;
    float sum = 0.f;
    for (int i = tid; i < D_INNER; i += 256) {
        float zv = zrow[i];
        float g = yrow[i] * (zv / (1.f + __expf(-zv)));
        gs[i] = g;
        sum += g*g;
    }
#pragma unroll
    for (int o = 16; o; o >>= 1) sum += __shfl_xor_sync(0xffffffffu, sum, o);
    if ((tid & 31) == 0) red[tid >> 5] = sum;
    __syncthreads();
    if (tid < 8) {
        float v = red[tid];
#pragma unroll
        for (int o = 4; o; o >>= 1) v += __shfl_xor_sync(0xffu, v, o);
        if (tid == 0) red[0] = v;
    }
    __syncthreads();
    float r = rsqrtf(red[0] / (float)D_INNER + 1e-5f);
    for (int i = tid; i < D_INNER; i += 256) yrow[i] = gs[i] * r * norm_w[i];
}

// ---------------- launch ---------------------------------------------------
extern "C" void kernel_launch(void* const* d_in, const int* in_sizes, int n_in,
                              void* d_out, int out_size)
{
    const float* hs      = (const float*)d_in[0];
    const float* W_in    = (const float*)d_in[1];
    const float* conv_w  = (const float*)d_in[2];
    const float* conv_b  = (const float*)d_in[3];
    const float* dt_bias = (const float*)d_in[4];
    const float* A_log   = (const float*)d_in[5];
    const float* Dp      = (const float*)d_in[6];
    const float* norm_w  = (const float*)d_in[7];
    const float* W_out   = (const float*)d_in[8];
    float* out = (float*)d_out;

    float *proj, *xc, *y, *Gt;
    cudaGetSymbolAddress((void**)&proj, g_proj);
    cudaGetSymbolAddress((void**)&xc,   g_xc);
    cudaGetSymbolAddress((void**)&y,    g_y);
    cudaGetSymbolAddress((void**)&Gt,   g_Gt);

    const int dynsm = (CSZ*PDIM + 2*CSZ) * (int)sizeof(float);  // 67584 B
    cudaFuncSetAttribute(ydiag_kernel,  cudaFuncAttributeMaxDynamicSharedMemorySize, dynsm);
    cudaFuncSetAttribute(states_kernel, cudaFuncAttributeMaxDynamicSharedMemorySize, dynsm);

    const int M = NBATCH * L_SEQ;   // 4096 tokens

    // 1) in-proj: proj = hs @ W_in^T   [4096,2048] x [8512,2048]^T
    sgemm_nt<<<dim3((PROJ + 127)/128, M/128, 1), 256>>>(
        hs, W_in, proj, M, PROJ, HIDDEN, HIDDEN, HIDDEN, PROJ, 0, 0, 0);

    // 2) causal conv + SiLU
    conv_silu_kernel<<<(NBATCH*L_SEQ*CONV_DIM)/256, 256>>>(conv_w, conv_b);

    // 3) dt softplus + cumsum(dt*A) per chunk
    dtscan_kernel<<<NBATCH*NH*NC, 256>>>(dt_bias, A_log);

    // 4) Gt[s,l] = B[s]·C[l] per (b,chunk)   (shared across all 64 heads)
    sgemm_nt<<<dim3(2, 2, NBATCH*NC), 256>>>(
        xc + D_INNER, xc + D_INNER + NDIM, Gt,
        CSZ, CSZ, NDIM, CONV_DIM, CONV_DIM, CSZ,
        (long long)CSZ*CONV_DIM, (long long)CSZ*CONV_DIM, (long long)CSZ*CSZ);

    // 5) intra-chunk diag output (+ D*x) -> g_y
    ydiag_kernel<<<NBATCH*NC*NH, 256, dynsm>>>(Dp);

    // 6) per-chunk states
    states_kernel<<<NBATCH*NC*NH, 256, dynsm>>>();

    // 7) inter-chunk scan
    scan_kernel<<<(NBATCH*NH*PDIM*NDIM)/256, 256>>>();

    // 8) inter-chunk contribution into g_y
    yoff_kernel<<<NBATCH*NC*NH, 256>>>();

    // 9) gated RMSNorm in place
    norm_kernel<<<M, 256>>>(norm_w);

    // 10) out-proj: out = gn @ W_out^T   [4096,4096] x [2048,4096]^T
    sgemm_nt<<<dim3(HIDDEN/128, M/128, 1), 256>>>(
        y, W_out, out, M, HIDDEN, D_INNER, D_INNER, D_INNER, HIDDEN, 0, 0, 0);
}

// round 2
// speedup vs baseline: 1.5882x; 1.5882x over previous
#include <cuda_runtime.h>
#include <math.h>

#define L_SEQ   2048
#define NBATCH  2
#define HIDDEN  2048
#define NH      64
#define PDIM    64
#define NDIM    128
#define CSZ     256
#define NC      8
#define D_INNER 4096
#define CONV_DIM 4352
#define PROJ    8512

// ---------------- scratch (device globals: allocation-free) ----------------
__device__ float g_proj  [NBATCH*L_SEQ*PROJ];
__device__ float g_xc    [NBATCH*L_SEQ*CONV_DIM];
__device__ float g_dtsp  [NBATCH*L_SEQ*NH];
__device__ float g_Acum  [NBATCH*NH*NC*CSZ];
__device__ float g_Gt    [NBATCH*NC*CSZ*CSZ];
__device__ float g_states[NBATCH*NC*NH*PDIM*NDIM];
__device__ float g_prev  [NBATCH*NC*NH*PDIM*NDIM];
__device__ float g_y     [NBATCH*L_SEQ*D_INNER];

// ---------------- tf32 helpers --------------------------------------------
__device__ __forceinline__ float f2tf(float f) {
    unsigned r;
    asm("cvt.rna.tf32.f32 %0, %1;" : "=r"(r) : "f"(f));
    return __uint_as_float(r);
}

__device__ __forceinline__ void mma_tf32(
    float* c, const unsigned* a, const unsigned* b)
{
    asm volatile(
        "mma.sync.aligned.m16n8k8.row.col.f32.tf32.tf32.f32 "
        "{%0,%1,%2,%3}, {%4,%5,%6,%7}, {%8,%9}, {%0,%1,%2,%3};"
        : "+f"(c[0]), "+f"(c[1]), "+f"(c[2]), "+f"(c[3])
        : "r"(a[0]), "r"(a[1]), "r"(a[2]), "r"(a[3]),
          "r"(b[0]), "r"(b[1]));
}

// ---------------- tf32 tensor-core NT GEMM: C[m,n]=sum_k A[m,k]*B[n,k] ----
// BM=BN=128, BK=32. 256 threads = 8 warps (2 M x 4 N), warp tile 64x32.
// Requires M%128==0, K%32==0; N edge guarded.
__global__ __launch_bounds__(256) void gemm_tf32_nt(
    const float* __restrict__ A, const float* __restrict__ B, float* __restrict__ C,
    int M, int N, int K, int lda, int ldb, int ldc)
{
    __shared__ float As[128][36];   // [m][k], pad -> frag LDS conflict-free
    __shared__ float Bs[128][36];   // [n][k]
    int tid = threadIdx.x;
    int bm = blockIdx.y * 128, bn = blockIdx.x * 128;
    int warp = tid >> 5, lane = tid & 31;
    int g = lane >> 2, tg = lane & 3;
    int wm = (warp & 1) * 64, wn = (warp >> 1) * 32;

    float acc[4][4][4];
#pragma unroll
    for (int mi = 0; mi < 4; mi++)
#pragma unroll
        for (int ni = 0; ni < 4; ni++)
#pragma unroll
            for (int j = 0; j < 4; j++) acc[mi][ni][j] = 0.f;

    float4 pa[4], pb[4];

    auto prefetch = [&](int kk) {
#pragma unroll
        for (int i = 0; i < 4; i++) {
            int idx = tid + i * 256;
            int row = idx >> 3, c4 = (idx & 7) << 2;
            pa[i] = *(const float4*)(A + (size_t)(bm + row) * lda + kk + c4);
            int gb = bn + row;
            if (gb < N) pb[i] = *(const float4*)(B + (size_t)gb * ldb + kk + c4);
            else        pb[i] = make_float4(0.f, 0.f, 0.f, 0.f);
        }
    };

    prefetch(0);

    for (int kk = 0; kk < K; kk += 32) {
        __syncthreads();   // protect smem from previous iteration's readers
#pragma unroll
        for (int i = 0; i < 4; i++) {
            int idx = tid + i * 256;
            int row = idx >> 3, c4 = (idx & 7) << 2;
            *(float4*)&As[row][c4] = make_float4(f2tf(pa[i].x), f2tf(pa[i].y),
                                                 f2tf(pa[i].z), f2tf(pa[i].w));
            *(float4*)&Bs[row][c4] = make_float4(f2tf(pb[i].x), f2tf(pb[i].y),
                                                 f2tf(pb[i].z), f2tf(pb[i].w));
        }
        __syncthreads();

        if (kk + 32 < K) prefetch(kk + 32);

#pragma unroll
        for (int ks = 0; ks < 4; ks++) {
            unsigned af[4][4], bf[4][2];
#pragma unroll
            for (int mi = 0; mi < 4; mi++) {
                int r = wm + mi * 16;
                af[mi][0] = __float_as_uint(As[r + g    ][ks*8 + tg    ]);
                af[mi][1] = __float_as_uint(As[r + g + 8][ks*8 + tg    ]);
                af[mi][2] = __float_as_uint(As[r + g    ][ks*8 + tg + 4]);
                af[mi][3] = __float_as_uint(As[r + g + 8][ks*8 + tg + 4]);
            }
#pragma unroll
            for (int ni = 0; ni < 4; ni++) {
                int r = wn + ni * 8;
                bf[ni][0] = __float_as_uint(Bs[r + g][ks*8 + tg    ]);
                bf[ni][1] = __float_as_uint(Bs[r + g][ks*8 + tg + 4]);
            }
#pragma unroll
            for (int mi = 0; mi < 4; mi++)
#pragma unroll
                for (int ni = 0; ni < 4; ni++)
                    mma_tf32(acc[mi][ni], af[mi], bf[ni]);
        }
    }

#pragma unroll
    for (int mi = 0; mi < 4; mi++) {
        int row0 = bm + wm + mi * 16 + g;
#pragma unroll
        for (int ni = 0; ni < 4; ni++) {
            int col = bn + wn + ni * 8 + 2 * tg;
            if (col < N) {
                *(float2*)(C + (size_t)row0 * ldc + col) =
                    make_float2(acc[mi][ni][0], acc[mi][ni][1]);
                *(float2*)(C + (size_t)(row0 + 8) * ldc + col) =
                    make_float2(acc[mi][ni][2], acc[mi][ni][3]);
            }
        }
    }
}

// ---------------- fp32 NT SGEMM (kept for small batched Gt GEMM) ----------
__global__ __launch_bounds__(256) void sgemm_nt(
    const float* __restrict__ A, const float* __restrict__ B, float* __restrict__ C,
    int M, int N, int K, int lda, int ldb, int ldc,
    long long sA, long long sB, long long sC)
{
    __shared__ float As[16][128];
    __shared__ float Bs[16][128];
    A += (long long)blockIdx.z * sA;
    B += (long long)blockIdx.z * sB;
    C += (long long)blockIdx.z * sC;
    int tid = threadIdx.x;
    int bm = blockIdx.y * 128, bn = blockIdx.x * 128;
    int tx = (tid & 15) * 8, ty = (tid >> 4) * 8;
    float acc[8][8];
#pragma unroll
    for (int i = 0; i < 8; i++)
#pragma unroll
        for (int j = 0; j < 8; j++) acc[i][j] = 0.f;

    for (int kk = 0; kk < K; kk += 16) {
#pragma unroll
        for (int i = 0; i < 2; i++) {
            int f = tid + i * 256;
            int row = f >> 2, c4 = (f & 3) << 2;
            float4 va = *(const float4*)(A + (long long)(bm + row) * lda + kk + c4);
            As[c4+0][row] = va.x; As[c4+1][row] = va.y;
            As[c4+2][row] = va.z; As[c4+3][row] = va.w;
            float4 vb = make_float4(0.f,0.f,0.f,0.f);
            int gb = bn + row;
            if (gb < N) vb = *(const float4*)(B + (long long)gb * ldb + kk + c4);
            Bs[c4+0][row] = vb.x; Bs[c4+1][row] = vb.y;
            Bs[c4+2][row] = vb.z; Bs[c4+3][row] = vb.w;
        }
        __syncthreads();
#pragma unroll
        for (int k = 0; k < 16; k++) {
            float4 a0 = *(const float4*)&As[k][ty];
            float4 a1 = *(const float4*)&As[k][ty+4];
            float4 b0 = *(const float4*)&Bs[k][tx];
            float4 b1 = *(const float4*)&Bs[k][tx+4];
            float ra[8] = {a0.x,a0.y,a0.z,a0.w,a1.x,a1.y,a1.z,a1.w};
            float rb[8] = {b0.x,b0.y,b0.z,b0.w,b1.x,b1.y,b1.z,b1.w};
#pragma unroll
            for (int i = 0; i < 8; i++)
#pragma unroll
                for (int j = 0; j < 8; j++) acc[i][j] += ra[i]*rb[j];
        }
        __syncthreads();
    }
#pragma unroll
    for (int i = 0; i < 8; i++) {
        float* crow = C + (long long)(bm + ty + i) * ldc + bn + tx;
#pragma unroll
        for (int j = 0; j < 8; j += 4) {
            if (bn + tx + j < N)
                *(float4*)(crow + j) = make_float4(acc[i][j],acc[i][j+1],acc[i][j+2],acc[i][j+3]);
        }
    }
}

// ---------------- causal depthwise conv (K=4) + bias + SiLU ----------------
__global__ __launch_bounds__(256) void conv_silu_kernel(
    const float* __restrict__ cw, const float* __restrict__ cb)
{
    int idx = blockIdx.x * 256 + threadIdx.x;
    int c = idx % CONV_DIM;
    int t = idx / CONV_DIM;
    int l = t % L_SEQ, b = t / L_SEQ;
    float acc = cb[c];
#pragma unroll
    for (int k = 0; k < 4; k++) {
        int ll = l - 3 + k;
        if (ll >= 0)
            acc += g_proj[((size_t)(b*L_SEQ + ll))*PROJ + D_INNER + c] * cw[c*4 + k];
    }
    acc = acc / (1.f + __expf(-acc));
    g_xc[(size_t)t*CONV_DIM + c] = acc;
}

// ---------------- dt softplus + per-chunk inclusive cumsum of dt*A ---------
__global__ __launch_bounds__(256) void dtscan_kernel(
    const float* __restrict__ dt_bias, const float* __restrict__ A_log)
{
    __shared__ float s[CSZ];
    int z = blockIdx.x;
    int c = z & 7, h = (z >> 3) & 63, b = z >> 9;
    int l = threadIdx.x;
    int gl = c*CSZ + l;
    float raw = g_proj[((size_t)(b*L_SEQ + gl))*PROJ + D_INNER + CONV_DIM + h] + dt_bias[h];
    float dts = (raw > 20.f) ? raw : log1pf(__expf(raw));
    g_dtsp[(size_t)(b*L_SEQ + gl)*NH + h] = dts;
    s[l] = -dts * __expf(A_log[h]);
    __syncthreads();
    for (int off = 1; off < CSZ; off <<= 1) {
        float v = (l >= off) ? s[l - off] : 0.f;
        __syncthreads();
        s[l] += v;
        __syncthreads();
    }
    g_Acum[((size_t)((b*NH + h)*NC + c))*CSZ + l] = s[l];
}

// ---------------- intra-chunk diagonal output (+ D*x), per (b,c,h) --------
__global__ __launch_bounds__(256) void ydiag_kernel(const float* __restrict__ Dp)
{
    extern __shared__ float sm[];
    float* Xs    = sm;
    float* Acs   = sm + CSZ*PDIM;
    float* dts_s = Acs + CSZ;
    int z = blockIdx.x;
    int h = z & 63, c = (z >> 6) & 7, b = z >> 9;
    int tid = threadIdx.x;
    Acs[tid]   = g_Acum[((size_t)((b*NH + h)*NC + c))*CSZ + tid];
    dts_s[tid] = g_dtsp[(size_t)(b*L_SEQ + c*CSZ + tid)*NH + h];
    __syncthreads();
    int p = tid & 63, l0 = tid >> 6;
    for (int i = 0; i < 64; i++) {
        int l = l0*64 + i;
        float xv = g_xc[(size_t)(b*L_SEQ + c*CSZ + l)*CONV_DIM + h*64 + p];
        Xs[l*64 + p] = xv * dts_s[l];
    }
    __syncthreads();

    int l = tid;
    float al = Acs[l];
    float4 acc[16];
#pragma unroll
    for (int j = 0; j < 16; j++) acc[j] = make_float4(0.f,0.f,0.f,0.f);
    const float* gt = g_Gt + (size_t)(b*NC + c)*CSZ*CSZ + l;
    for (int s = 0; s <= l; s++) {
        float w = gt[s*CSZ] * __expf(al - Acs[s]);
        const float4* xr = (const float4*)(Xs + s*64);
#pragma unroll
        for (int j = 0; j < 16; j++) {
            float4 v = xr[j];
            acc[j].x += w*v.x; acc[j].y += w*v.y; acc[j].z += w*v.z; acc[j].w += w*v.w;
        }
    }
    float dcoef = Dp[h] / fmaxf(dts_s[l], 1e-30f);
    {
        const float4* xr = (const float4*)(Xs + l*64);
#pragma unroll
        for (int j = 0; j < 16; j++) {
            float4 v = xr[j];
            acc[j].x += dcoef*v.x; acc[j].y += dcoef*v.y;
            acc[j].z += dcoef*v.z; acc[j].w += dcoef*v.w;
        }
    }
    __syncthreads();
    float4* xw = (float4*)(Xs + l*64);
#pragma unroll
    for (int j = 0; j < 16; j++) xw[j] = acc[j];
    __syncthreads();
    for (int i = 0; i < 64; i++) {
        int ll = l0*64 + i;
        g_y[(size_t)(b*L_SEQ + c*CSZ + ll)*D_INNER + h*64 + p] = Xs[ll*64 + p];
    }
}

// ---------------- per-chunk states ----------------------------------------
__global__ __launch_bounds__(256) void states_kernel()
{
    extern __shared__ float sm[];
    float* Xs    = sm;
    float* dec   = sm + CSZ*PDIM;
    float* dts_s = dec + CSZ;
    int z = blockIdx.x;
    int h = z & 63, c = (z >> 6) & 7, b = z >> 9;
    int tid = threadIdx.x;
    dec[tid]   = g_Acum[((size_t)((b*NH + h)*NC + c))*CSZ + tid];
    dts_s[tid] = g_dtsp[(size_t)(b*L_SEQ + c*CSZ + tid)*NH + h];
    __syncthreads();
    float alast = dec[CSZ-1];
    float aown  = dec[tid];
    __syncthreads();
    dec[tid] = __expf(alast - aown);
    int p = tid & 63, l0 = tid >> 6;
    for (int i = 0; i < 64; i++) {
        int l = l0*64 + i;
        float xv = g_xc[(size_t)(b*L_SEQ + c*CSZ + l)*CONV_DIM + h*64 + p];
        Xs[l*64 + p] = xv * dts_s[l];
    }
    __syncthreads();

    int n = tid & 127, ph = tid >> 7;
    float4 acc[8];
#pragma unroll
    for (int j = 0; j < 8; j++) acc[j] = make_float4(0.f,0.f,0.f,0.f);
    size_t brow = (size_t)(b*L_SEQ + c*CSZ)*CONV_DIM + D_INNER + n;
    for (int l = 0; l < CSZ; l++) {
        float w = g_xc[brow + (size_t)l*CONV_DIM] * dec[l];
        const float4* xr = (const float4*)(Xs + l*64 + ph*32);
#pragma unroll
        for (int j = 0; j < 8; j++) {
            float4 v = xr[j];
            acc[j].x += w*v.x; acc[j].y += w*v.y; acc[j].z += w*v.z; acc[j].w += w*v.w;
        }
    }
    size_t sb = ((size_t)((b*NC + c)*NH + h))*PDIM*NDIM;
#pragma unroll
    for (int j = 0; j < 8; j++) {
        int pb = ph*32 + j*4;
        g_states[sb + (size_t)(pb+0)*NDIM + n] = acc[j].x;
        g_states[sb + (size_t)(pb+1)*NDIM + n] = acc[j].y;
        g_states[sb + (size_t)(pb+2)*NDIM + n] = acc[j].z;
        g_states[sb + (size_t)(pb+3)*NDIM + n] = acc[j].w;
    }
}

// ---------------- inter-chunk scan ----------------------------------------
__global__ __launch_bounds__(256) void scan_kernel()
{
    int idx = blockIdx.x * 256 + threadIdx.x;
    int n = idx & 127;
    int p = (idx >> 7) & 63;
    int h = (idx >> 13) & 63;
    int b = idx >> 19;
    float carry = 0.f;
    for (int c = 0; c < NC; c++) {
        size_t off = ((size_t)((b*NC + c)*NH + h))*PDIM*NDIM + (size_t)p*NDIM + n;
        float dal = g_Acum[((size_t)((b*NH + h)*NC + c))*CSZ + (CSZ-1)];
        float s = g_states[off];
        g_prev[off] = carry;
        carry = carry * __expf(dal) + s;
    }
}

// ---------------- inter-chunk contribution --------------------------------
__global__ __launch_bounds__(256) void yoff_kernel()
{
    __shared__ float prevT[128*68];
    __shared__ float Acs[CSZ];
    int z = blockIdx.x;
    int h = z & 63, c = (z >> 6) & 7, b = z >> 9;
    int tid = threadIdx.x;
    Acs[tid] = g_Acum[((size_t)((b*NH + h)*NC + c))*CSZ + tid];
    int n = tid & 127, p0 = tid >> 7;
    size_t sb = ((size_t)((b*NC + c)*NH + h))*PDIM*NDIM;
    for (int i = 0; i < 32; i++) {
        int p = p0*32 + i;
        prevT[n*68 + p] = g_prev[sb + (size_t)p*NDIM + n];
    }
    __syncthreads();

    int l = tid;
    float4 acc[16];
#pragma unroll
    for (int j = 0; j < 16; j++) acc[j] = make_float4(0.f,0.f,0.f,0.f);
    const float* crow = g_xc + (size_t)(b*L_SEQ + c*CSZ + l)*CONV_DIM + D_INNER + NDIM;
    for (int n4 = 0; n4 < 32; n4++) {
        float4 cv = *(const float4*)(crow + n4*4);
        float cvals[4] = {cv.x, cv.y, cv.z, cv.w};
#pragma unroll
        for (int u = 0; u < 4; u++) {
            float cval = cvals[u];
            const float4* pr = (const float4*)(prevT + (n4*4 + u)*68);
#pragma unroll
            for (int j = 0; j < 16; j++) {
                float4 v = pr[j];
                acc[j].x += cval*v.x; acc[j].y += cval*v.y;
                acc[j].z += cval*v.z; acc[j].w += cval*v.w;
            }
        }
    }
    float e = __expf(Acs[l]);
    float* yrow = g_y + (size_t)(b*L_SEQ + c*CSZ + l)*D_INNER + h*64;
#pragma unroll
    for (int j = 0; j < 16; j++) {
        float4 v = *(float4*)(yrow + j*4);
        v.x += e*acc[j].x; v.y += e*acc[j].y; v.z += e*acc[j].z; v.w += e*acc[j].w;
        *(float4*)(yrow + j*4) = v;
    }
}

// ---------------- gated RMSNorm -------------------------------------------
__global__ __launch_bounds__(256) void norm_kernel(const float* __restrict__ norm_w)
{
    __shared__ float gs[D_INNER];
    __shared__ float red[8];
    int t = blockIdx.x;
    int tid = threadIdx.x;
    const float* zrow = g_proj + (size_t)t * PROJ;
    float* yrow = g_y + (size_t)t * D_INNER;
    float sum = 0.f;
    for (int i = tid; i < D_INNER; i += 256) {
        float zv = zrow[i];
        float g = yrow[i] * (zv / (1.f + __expf(-zv)));
        gs[i] = g;
        sum += g*g;
    }
#pragma unroll
    for (int o = 16; o; o >>= 1) sum += __shfl_xor_sync(0xffffffffu, sum, o);
    if ((tid & 31) == 0) red[tid >> 5] = sum;
    __syncthreads();
    if (tid < 8) {
        float v = red[tid];
#pragma unroll
        for (int o = 4; o; o >>= 1) v += __shfl_xor_sync(0xffu, v, o);
        if (tid == 0) red[0] = v;
    }
    __syncthreads();
    float r = rsqrtf(red[0] / (float)D_INNER + 1e-5f);
    for (int i = tid; i < D_INNER; i += 256) yrow[i] = gs[i] * r * norm_w[i];
}

// ---------------- launch ---------------------------------------------------
extern "C" void kernel_launch(void* const* d_in, const int* in_sizes, int n_in,
                              void* d_out, int out_size)
{
    const float* hs      = (const float*)d_in[0];
    const float* W_in    = (const float*)d_in[1];
    const float* conv_w  = (const float*)d_in[2];
    const float* conv_b  = (const float*)d_in[3];
    const float* dt_bias = (const float*)d_in[4];
    const float* A_log   = (const float*)d_in[5];
    const float* Dp      = (const float*)d_in[6];
    const float* norm_w  = (const float*)d_in[7];
    const float* W_out   = (const float*)d_in[8];
    float* out = (float*)d_out;

    float *proj, *xc, *y, *Gt;
    cudaGetSymbolAddress((void**)&proj, g_proj);
    cudaGetSymbolAddress((void**)&xc,   g_xc);
    cudaGetSymbolAddress((void**)&y,    g_y);
    cudaGetSymbolAddress((void**)&Gt,   g_Gt);

    const int dynsm = (CSZ*PDIM + 2*CSZ) * (int)sizeof(float);
    cudaFuncSetAttribute(ydiag_kernel,  cudaFuncAttributeMaxDynamicSharedMemorySize, dynsm);
    cudaFuncSetAttribute(states_kernel, cudaFuncAttributeMaxDynamicSharedMemorySize, dynsm);

    const int M = NBATCH * L_SEQ;   // 4096 tokens

    // 1) in-proj: proj = hs @ W_in^T   (tf32 tensor cores)
    gemm_tf32_nt<<<dim3((PROJ + 127)/128, M/128), 256>>>(
        hs, W_in, proj, M, PROJ, HIDDEN, HIDDEN, HIDDEN, PROJ);

    // 2) causal conv + SiLU
    conv_silu_kernel<<<(NBATCH*L_SEQ*CONV_DIM)/256, 256>>>(conv_w, conv_b);

    // 3) dt softplus + cumsum(dt*A) per chunk
    dtscan_kernel<<<NBATCH*NH*NC, 256>>>(dt_bias, A_log);

    // 4) Gt[s,l] = B[s]·C[l] per (b,chunk)
    sgemm_nt<<<dim3(2, 2, NBATCH*NC), 256>>>(
        xc + D_INNER, xc + D_INNER + NDIM, Gt,
        CSZ, CSZ, NDIM, CONV_DIM, CONV_DIM, CSZ,
        (long long)CSZ*CONV_DIM, (long long)CSZ*CONV_DIM, (long long)CSZ*CSZ);

    // 5) intra-chunk diag output (+ D*x) -> g_y
    ydiag_kernel<<<NBATCH*NC*NH, 256, dynsm>>>(Dp);

    // 6) per-chunk states
    states_kernel<<<NBATCH*NC*NH, 256, dynsm>>>();

    // 7) inter-chunk scan
    scan_kernel<<<(NBATCH*NH*PDIM*NDIM)/256, 256>>>();

    // 8) inter-chunk contribution into g_y
    yoff_kernel<<<NBATCH*NC*NH, 256>>>();

    // 9) gated RMSNorm in place
    norm_kernel<<<M, 256>>>(norm_w);

    // 10) out-proj: out = gn @ W_out^T  (tf32 tensor cores)
    gemm_tf32_nt<<<dim3(HIDDEN/128, M/128), 256>>>(
        y, W_out, out, M, HIDDEN, D_INNER, D_INNER, D_INNER, HIDDEN);
}

// round 3
// speedup vs baseline: 2.2613x; 1.4239x over previous
#include <cuda_runtime.h>
#include <math.h>

#define L_SEQ   2048
#define NBATCH  2
#define HIDDEN  2048
#define NH      64
#define PDIM    64
#define NDIM    128
#define CSZ     256
#define NC      8
#define D_INNER 4096
#define CONV_DIM 4352
#define PROJ    8512
#define PROJ_PAD 8576   // 67 * 128

// ---------------- scratch (device globals: allocation-free) ----------------
__device__ float g_proj  [NBATCH*L_SEQ*PROJ];
__device__ float g_xc    [NBATCH*L_SEQ*CONV_DIM];
__device__ float g_dtsp  [NBATCH*L_SEQ*NH];
__device__ float g_Acum  [NBATCH*NH*NC*CSZ];
__device__ float g_Gt    [NBATCH*NC*CSZ*CSZ];
__device__ float g_states[NBATCH*NC*NH*PDIM*NDIM];
__device__ float g_prev  [NBATCH*NC*NH*PDIM*NDIM];
__device__ float g_y     [NBATCH*L_SEQ*D_INNER];
// tf32-pre-rounded operand copies
__device__ float g_hsr   [NBATCH*L_SEQ*HIDDEN];
__device__ float g_Wir   [PROJ_PAD*HIDDEN];
__device__ float g_Wor   [HIDDEN*D_INNER];

// ---------------- tf32 helpers --------------------------------------------
__device__ __forceinline__ float f2tf(float f) {
    unsigned r;
    asm("cvt.rna.tf32.f32 %0, %1;" : "=r"(r) : "f"(f));
    return __uint_as_float(r);
}

__device__ __forceinline__ void mma_tf32(
    float* c, const unsigned* a, const unsigned* b)
{
    asm volatile(
        "mma.sync.aligned.m16n8k8.row.col.f32.tf32.tf32.f32 "
        "{%0,%1,%2,%3}, {%4,%5,%6,%7}, {%8,%9}, {%0,%1,%2,%3};"
        : "+f"(c[0]), "+f"(c[1]), "+f"(c[2]), "+f"(c[3])
        : "r"(a[0]), "r"(a[1]), "r"(a[2]), "r"(a[3]),
          "r"(b[0]), "r"(b[1]));
}

__device__ __forceinline__ void cp16(unsigned smem, const float* g) {
    asm volatile("cp.async.cg.shared.global [%0], [%1], 16;\n" :: "r"(smem), "l"(g));
}
__device__ __forceinline__ void cp_commit() {
    asm volatile("cp.async.commit_group;\n");
}
template<int N> __device__ __forceinline__ void cp_wait() {
    asm volatile("cp.async.wait_group %0;\n" :: "n"(N));
}

// ---------------- pre-round kernels ----------------------------------------
__global__ __launch_bounds__(256) void round_kernel(
    const float* __restrict__ src, float* __restrict__ dst, int n)
{
    int i = blockIdx.x * 256 + threadIdx.x;
    if (i < n) dst[i] = f2tf(src[i]);
}
// round + zero-pad rows beyond 'rows' (src rows x cols -> dst rows_pad x cols)
__global__ __launch_bounds__(256) void round_pad_kernel(
    const float* __restrict__ src, float* __restrict__ dst, int rows, int rows_pad, int cols)
{
    int i = blockIdx.x * 256 + threadIdx.x;
    if (i < rows_pad * cols) {
        int r = i / cols;
        dst[i] = (r < rows) ? f2tf(src[i]) : 0.f;
    }
}

// ---------------- pipelined tf32 tensor-core NT GEMM ------------------------
// C[m,n] = sum_k A[m,k]*B[n,k].  A: M x K (rounded), B: NB x K (rounded, padded),
// stores guarded to n < N.  BM=BN=128, BK=32, 3-stage cp.async.
// Requires M%128==0, K%32==0, NB >= ceil(N/128)*128.
#define STAGES 3
__global__ __launch_bounds__(256) void gemm_tf32_pipe(
    const float* __restrict__ A, const float* __restrict__ B, float* __restrict__ C,
    int M, int N, int K, int lda, int ldb, int ldc)
{
    extern __shared__ float sm[];
    float* As = sm;                       // [STAGES][128][36]
    float* Bs = sm + STAGES * 128 * 36;   // [STAGES][128][36]
    int tid = threadIdx.x;
    int bm = blockIdx.y * 128, bn = blockIdx.x * 128;
    int warp = tid >> 5, lane = tid & 31;
    int g = lane >> 2, tg = lane & 3;
    int wm = (warp & 1) * 64, wn = (warp >> 1) * 32;

    float acc[4][4][4];
#pragma unroll
    for (int mi = 0; mi < 4; mi++)
#pragma unroll
        for (int ni = 0; ni < 4; ni++)
#pragma unroll
            for (int j = 0; j < 4; j++) acc[mi][ni][j] = 0.f;

    // per-thread load slots: 4 x 16B for A, 4 x 16B for B per stage
    int row_ = tid >> 1;                 // not used directly; compute per chunk
    (void)row_;
    unsigned asBase = (unsigned)__cvta_generic_to_shared(As);
    unsigned bsBase = (unsigned)__cvta_generic_to_shared(Bs);

    const int KT = K >> 5;               // k-tiles of 32

    auto issue_stage = [&](int stage, int kt) {
        int kk = kt << 5;
        unsigned aS = asBase + (unsigned)(stage * 128 * 36) * 4u;
        unsigned bS = bsBase + (unsigned)(stage * 128 * 36) * 4u;
#pragma unroll
        for (int i = 0; i < 4; i++) {
            int id = tid + i * 256;          // 0..1023
            int row = id >> 3, c16 = id & 7; // 128 rows x 8 chunks
            cp16(aS + (unsigned)(row * 36 + c16 * 4) * 4u,
                 A + (size_t)(bm + row) * lda + kk + c16 * 4);
            cp16(bS + (unsigned)(row * 36 + c16 * 4) * 4u,
                 B + (size_t)(bn + row) * ldb + kk + c16 * 4);
        }
        cp_commit();
    };

    issue_stage(0, 0);
    if (KT > 1) issue_stage(1, 1);

    for (int kt = 0; kt < KT; kt++) {
        if (kt < KT - 1) cp_wait<1>(); else cp_wait<0>();
        __syncthreads();
        if (kt + 2 < KT) issue_stage((kt + 2) % STAGES, kt + 2);

        const float* Asb = As + (kt % STAGES) * 128 * 36;
        const float* Bsb = Bs + (kt % STAGES) * 128 * 36;
#pragma unroll
        for (int ks = 0; ks < 4; ks++) {
            unsigned af[4][4], bf[4][2];
#pragma unroll
            for (int mi = 0; mi < 4; mi++) {
                int r = wm + mi * 16;
                af[mi][0] = __float_as_uint(Asb[(r + g    ) * 36 + ks*8 + tg    ]);
                af[mi][1] = __float_as_uint(Asb[(r + g + 8) * 36 + ks*8 + tg    ]);
                af[mi][2] = __float_as_uint(Asb[(r + g    ) * 36 + ks*8 + tg + 4]);
                af[mi][3] = __float_as_uint(Asb[(r + g + 8) * 36 + ks*8 + tg + 4]);
            }
#pragma unroll
            for (int ni = 0; ni < 4; ni++) {
                int r = wn + ni * 8;
                bf[ni][0] = __float_as_uint(Bsb[(r + g) * 36 + ks*8 + tg    ]);
                bf[ni][1] = __float_as_uint(Bsb[(r + g) * 36 + ks*8 + tg + 4]);
            }
#pragma unroll
            for (int mi = 0; mi < 4; mi++)
#pragma unroll
                for (int ni = 0; ni < 4; ni++)
                    mma_tf32(acc[mi][ni], af[mi], bf[ni]);
        }
        __syncthreads();
    }

#pragma unroll
    for (int mi = 0; mi < 4; mi++) {
        int row0 = bm + wm + mi * 16 + g;
#pragma unroll
        for (int ni = 0; ni < 4; ni++) {
            int col = bn + wn + ni * 8 + 2 * tg;
            if (col < N) {
                *(float2*)(C + (size_t)row0 * ldc + col) =
                    make_float2(acc[mi][ni][0], acc[mi][ni][1]);
                *(float2*)(C + (size_t)(row0 + 8) * ldc + col) =
                    make_float2(acc[mi][ni][2], acc[mi][ni][3]);
            }
        }
    }
}

// ---------------- fp32 NT SGEMM (small batched Gt GEMM) --------------------
__global__ __launch_bounds__(256) void sgemm_nt(
    const float* __restrict__ A, const float* __restrict__ B, float* __restrict__ C,
    int M, int N, int K, int lda, int ldb, int ldc,
    long long sA, long long sB, long long sC)
{
    __shared__ float As[16][128];
    __shared__ float Bs[16][128];
    A += (long long)blockIdx.z * sA;
    B += (long long)blockIdx.z * sB;
    C += (long long)blockIdx.z * sC;
    int tid = threadIdx.x;
    int bm = blockIdx.y * 128, bn = blockIdx.x * 128;
    int tx = (tid & 15) * 8, ty = (tid >> 4) * 8;
    float acc[8][8];
#pragma unroll
    for (int i = 0; i < 8; i++)
#pragma unroll
        for (int j = 0; j < 8; j++) acc[i][j] = 0.f;

    for (int kk = 0; kk < K; kk += 16) {
#pragma unroll
        for (int i = 0; i < 2; i++) {
            int f = tid + i * 256;
            int row = f >> 2, c4 = (f & 3) << 2;
            float4 va = *(const float4*)(A + (long long)(bm + row) * lda + kk + c4);
            As[c4+0][row] = va.x; As[c4+1][row] = va.y;
            As[c4+2][row] = va.z; As[c4+3][row] = va.w;
            float4 vb = make_float4(0.f,0.f,0.f,0.f);
            int gb = bn + row;
            if (gb < N) vb = *(const float4*)(B + (long long)gb * ldb + kk + c4);
            Bs[c4+0][row] = vb.x; Bs[c4+1][row] = vb.y;
            Bs[c4+2][row] = vb.z; Bs[c4+3][row] = vb.w;
        }
        __syncthreads();
#pragma unroll
        for (int k = 0; k < 16; k++) {
            float4 a0 = *(const float4*)&As[k][ty];
            float4 a1 = *(const float4*)&As[k][ty+4];
            float4 b0 = *(const float4*)&Bs[k][tx];
            float4 b1 = *(const float4*)&Bs[k][tx+4];
            float ra[8] = {a0.x,a0.y,a0.z,a0.w,a1.x,a1.y,a1.z,a1.w};
            float rb[8] = {b0.x,b0.y,b0.z,b0.w,b1.x,b1.y,b1.z,b1.w};
#pragma unroll
            for (int i = 0; i < 8; i++)
#pragma unroll
                for (int j = 0; j < 8; j++) acc[i][j] += ra[i]*rb[j];
        }
        __syncthreads();
    }
#pragma unroll
    for (int i = 0; i < 8; i++) {
        float* crow = C + (long long)(bm + ty + i) * ldc + bn + tx;
#pragma unroll
        for (int j = 0; j < 8; j += 4) {
            if (bn + tx + j < N)
                *(float4*)(crow + j) = make_float4(acc[i][j],acc[i][j+1],acc[i][j+2],acc[i][j+3]);
        }
    }
}

// ---------------- causal depthwise conv (K=4) + bias + SiLU ----------------
__global__ __launch_bounds__(256) void conv_silu_kernel(
    const float* __restrict__ cw, const float* __restrict__ cb)
{
    int idx = blockIdx.x * 256 + threadIdx.x;
    int c = idx % CONV_DIM;
    int t = idx / CONV_DIM;
    int l = t % L_SEQ, b = t / L_SEQ;
    float acc = cb[c];
#pragma unroll
    for (int k = 0; k < 4; k++) {
        int ll = l - 3 + k;
        if (ll >= 0)
            acc += g_proj[((size_t)(b*L_SEQ + ll))*PROJ + D_INNER + c] * cw[c*4 + k];
    }
    acc = acc / (1.f + __expf(-acc));
    g_xc[(size_t)t*CONV_DIM + c] = acc;
}

// ---------------- dt softplus + per-chunk inclusive cumsum of dt*A ---------
__global__ __launch_bounds__(256) void dtscan_kernel(
    const float* __restrict__ dt_bias, const float* __restrict__ A_log)
{
    __shared__ float s[CSZ];
    int z = blockIdx.x;
    int c = z & 7, h = (z >> 3) & 63, b = z >> 9;
    int l = threadIdx.x;
    int gl = c*CSZ + l;
    float raw = g_proj[((size_t)(b*L_SEQ + gl))*PROJ + D_INNER + CONV_DIM + h] + dt_bias[h];
    float dts = (raw > 20.f) ? raw : log1pf(__expf(raw));
    g_dtsp[(size_t)(b*L_SEQ + gl)*NH + h] = dts;
    s[l] = -dts * __expf(A_log[h]);
    __syncthreads();
    for (int off = 1; off < CSZ; off <<= 1) {
        float v = (l >= off) ? s[l - off] : 0.f;
        __syncthreads();
        s[l] += v;
        __syncthreads();
    }
    g_Acum[((size_t)((b*NH + h)*NC + c))*CSZ + l] = s[l];
}

// ---------------- intra-chunk diagonal output (+ D*x), per (b,c,h) --------
__global__ __launch_bounds__(256) void ydiag_kernel(const float* __restrict__ Dp)
{
    extern __shared__ float smy[];
    float* Xs    = smy;
    float* Acs   = smy + CSZ*PDIM;
    float* dts_s = Acs + CSZ;
    int z = blockIdx.x;
    int h = z & 63, c = (z >> 6) & 7, b = z >> 9;
    int tid = threadIdx.x;
    Acs[tid]   = g_Acum[((size_t)((b*NH + h)*NC + c))*CSZ + tid];
    dts_s[tid] = g_dtsp[(size_t)(b*L_SEQ + c*CSZ + tid)*NH + h];
    __syncthreads();
    int p = tid & 63, l0 = tid >> 6;
    for (int i = 0; i < 64; i++) {
        int l = l0*64 + i;
        float xv = g_xc[(size_t)(b*L_SEQ + c*CSZ + l)*CONV_DIM + h*64 + p];
        Xs[l*64 + p] = xv * dts_s[l];
    }
    __syncthreads();

    int l = tid;
    float al = Acs[l];
    float4 acc[16];
#pragma unroll
    for (int j = 0; j < 16; j++) acc[j] = make_float4(0.f,0.f,0.f,0.f);
    const float* gt = g_Gt + (size_t)(b*NC + c)*CSZ*CSZ + l;
    for (int s = 0; s <= l; s++) {
        float w = gt[s*CSZ] * __expf(al - Acs[s]);
        const float4* xr = (const float4*)(Xs + s*64);
#pragma unroll
        for (int j = 0; j < 16; j++) {
            float4 v = xr[j];
            acc[j].x += w*v.x; acc[j].y += w*v.y; acc[j].z += w*v.z; acc[j].w += w*v.w;
        }
    }
    float dcoef = Dp[h] / fmaxf(dts_s[l], 1e-30f);
    {
        const float4* xr = (const float4*)(Xs + l*64);
#pragma unroll
        for (int j = 0; j < 16; j++) {
            float4 v = xr[j];
            acc[j].x += dcoef*v.x; acc[j].y += dcoef*v.y;
            acc[j].z += dcoef*v.z; acc[j].w += dcoef*v.w;
        }
    }
    __syncthreads();
    float4* xw = (float4*)(Xs + l*64);
#pragma unroll
    for (int j = 0; j < 16; j++) xw[j] = acc[j];
    __syncthreads();
    for (int i = 0; i < 64; i++) {
        int ll = l0*64 + i;
        g_y[(size_t)(b*L_SEQ + c*CSZ + ll)*D_INNER + h*64 + p] = Xs[ll*64 + p];
    }
}

// ---------------- per-chunk states ----------------------------------------
__global__ __launch_bounds__(256) void states_kernel()
{
    extern __shared__ float sms[];
    float* Xs    = sms;
    float* dec   = sms + CSZ*PDIM;
    float* dts_s = dec + CSZ;
    int z = blockIdx.x;
    int h = z & 63, c = (z >> 6) & 7, b = z >> 9;
    int tid = threadIdx.x;
    dec[tid]   = g_Acum[((size_t)((b*NH + h)*NC + c))*CSZ + tid];
    dts_s[tid] = g_dtsp[(size_t)(b*L_SEQ + c*CSZ + tid)*NH + h];
    __syncthreads();
    float alast = dec[CSZ-1];
    float aown  = dec[tid];
    __syncthreads();
    dec[tid] = __expf(alast - aown);
    int p = tid & 63, l0 = tid >> 6;
    for (int i = 0; i < 64; i++) {
        int l = l0*64 + i;
        float xv = g_xc[(size_t)(b*L_SEQ + c*CSZ + l)*CONV_DIM + h*64 + p];
        Xs[l*64 + p] = xv * dts_s[l];
    }
    __syncthreads();

    int n = tid & 127, ph = tid >> 7;
    float4 acc[8];
#pragma unroll
    for (int j = 0; j < 8; j++) acc[j] = make_float4(0.f,0.f,0.f,0.f);
    size_t brow = (size_t)(b*L_SEQ + c*CSZ)*CONV_DIM + D_INNER + n;
    for (int l = 0; l < CSZ; l++) {
        float w = g_xc[brow + (size_t)l*CONV_DIM] * dec[l];
        const float4* xr = (const float4*)(Xs + l*64 + ph*32);
#pragma unroll
        for (int j = 0; j < 8; j++) {
            float4 v = xr[j];
            acc[j].x += w*v.x; acc[j].y += w*v.y; acc[j].z += w*v.z; acc[j].w += w*v.w;
        }
    }
    size_t sb = ((size_t)((b*NC + c)*NH + h))*PDIM*NDIM;
#pragma unroll
    for (int j = 0; j < 8; j++) {
        int pb = ph*32 + j*4;
        g_states[sb + (size_t)(pb+0)*NDIM + n] = acc[j].x;
        g_states[sb + (size_t)(pb+1)*NDIM + n] = acc[j].y;
        g_states[sb + (size_t)(pb+2)*NDIM + n] = acc[j].z;
        g_states[sb + (size_t)(pb+3)*NDIM + n] = acc[j].w;
    }
}

// ---------------- inter-chunk scan ----------------------------------------
__global__ __launch_bounds__(256) void scan_kernel()
{
    int idx = blockIdx.x * 256 + threadIdx.x;
    int n = idx & 127;
    int p = (idx >> 7) & 63;
    int h = (idx >> 13) & 63;
    int b = idx >> 19;
    float carry = 0.f;
    for (int c = 0; c < NC; c++) {
        size_t off = ((size_t)((b*NC + c)*NH + h))*PDIM*NDIM + (size_t)p*NDIM + n;
        float dal = g_Acum[((size_t)((b*NH + h)*NC + c))*CSZ + (CSZ-1)];
        float s = g_states[off];
        g_prev[off] = carry;
        carry = carry * __expf(dal) + s;
    }
}

// ---------------- inter-chunk contribution --------------------------------
__global__ __launch_bounds__(256) void yoff_kernel()
{
    __shared__ float prevT[128*68];
    __shared__ float Acs[CSZ];
    int z = blockIdx.x;
    int h = z & 63, c = (z >> 6) & 7, b = z >> 9;
    int tid = threadIdx.x;
    Acs[tid] = g_Acum[((size_t)((b*NH + h)*NC + c))*CSZ + tid];
    int n = tid & 127, p0 = tid >> 7;
    size_t sb = ((size_t)((b*NC + c)*NH + h))*PDIM*NDIM;
    for (int i = 0; i < 32; i++) {
        int p = p0*32 + i;
        prevT[n*68 + p] = g_prev[sb + (size_t)p*NDIM + n];
    }
    __syncthreads();

    int l = tid;
    float4 acc[16];
#pragma unroll
    for (int j = 0; j < 16; j++) acc[j] = make_float4(0.f,0.f,0.f,0.f);
    const float* crow = g_xc + (size_t)(b*L_SEQ + c*CSZ + l)*CONV_DIM + D_INNER + NDIM;
    for (int n4 = 0; n4 < 32; n4++) {
        float4 cv = *(const float4*)(crow + n4*4);
        float cvals[4] = {cv.x, cv.y, cv.z, cv.w};
#pragma unroll
        for (int u = 0; u < 4; u++) {
            float cval = cvals[u];
            const float4* pr = (const float4*)(prevT + (n4*4 + u)*68);
#pragma unroll
            for (int j = 0; j < 16; j++) {
                float4 v = pr[j];
                acc[j].x += cval*v.x; acc[j].y += cval*v.y;
                acc[j].z += cval*v.z; acc[j].w += cval*v.w;
            }
        }
    }
    float e = __expf(Acs[l]);
    float* yrow = g_y + (size_t)(b*L_SEQ + c*CSZ + l)*D_INNER + h*64;
#pragma unroll
    for (int j = 0; j < 16; j++) {
        float4 v = *(float4*)(yrow + j*4);
        v.x += e*acc[j].x; v.y += e*acc[j].y; v.z += e*acc[j].z; v.w += e*acc[j].w;
        *(float4*)(yrow + j*4) = v;
    }
}

// ---------------- gated RMSNorm (writes tf32-rounded output) ---------------
__global__ __launch_bounds__(256) void norm_kernel(const float* __restrict__ norm_w)
{
    __shared__ float gs[D_INNER];
    __shared__ float red[8];
    int t = blockIdx.x;
    int tid = threadIdx.x;
    const float* zrow = g_proj + (size_t)t * PROJ;
    float* yrow = g_y + (size_t)t * D_INNER;
    float sum = 0.f;
    for (int i = tid; i < D_INNER; i += 256) {
        float zv = zrow[i];
        float g = yrow[i] * (zv / (1.f + __expf(-zv)));
        gs[i] = g;
        sum += g*g;
    }
#pragma unroll
    for (int o = 16; o; o >>= 1) sum += __shfl_xor_sync(0xffffffffu, sum, o);
    if ((tid & 31) == 0) red[tid >> 5] = sum;
    __syncthreads();
    if (tid < 8) {
        float v = red[tid];
#pragma unroll
        for (int o = 4; o; o >>= 1) v += __shfl_xor_sync(0xffu, v, o);
        if (tid == 0) red[0] = v;
    }
    __syncthreads();
    float r = rsqrtf(red[0] / (float)D_INNER + 1e-5f);
    for (int i = tid; i < D_INNER; i += 256) yrow[i] = f2tf(gs[i] * r * norm_w[i]);
}

// ---------------- launch ---------------------------------------------------
extern "C" void kernel_launch(void* const* d_in, const int* in_sizes, int n_in,
                              void* d_out, int out_size)
{
    const float* hs      = (const float*)d_in[0];
    const float* W_in    = (const float*)d_in[1];
    const float* conv_w  = (const float*)d_in[2];
    const float* conv_b  = (const float*)d_in[3];
    const float* dt_bias = (const float*)d_in[4];
    const float* A_log   = (const float*)d_in[5];
    const float* Dp      = (const float*)d_in[6];
    const float* norm_w  = (const float*)d_in[7];
    const float* W_out   = (const float*)d_in[8];
    float* out = (float*)d_out;

    float *proj, *xc, *y, *Gt, *hsr, *Wir, *Wor;
    cudaGetSymbolAddress((void**)&proj, g_proj);
    cudaGetSymbolAddress((void**)&xc,   g_xc);
    cudaGetSymbolAddress((void**)&y,    g_y);
    cudaGetSymbolAddress((void**)&Gt,   g_Gt);
    cudaGetSymbolAddress((void**)&hsr,  g_hsr);
    cudaGetSymbolAddress((void**)&Wir,  g_Wir);
    cudaGetSymbolAddress((void**)&Wor,  g_Wor);

    const int dynsm = (CSZ*PDIM + 2*CSZ) * (int)sizeof(float);
    cudaFuncSetAttribute(ydiag_kernel,  cudaFuncAttributeMaxDynamicSharedMemorySize, dynsm);
    cudaFuncSetAttribute(states_kernel, cudaFuncAttributeMaxDynamicSharedMemorySize, dynsm);
    const int gemmsm = STAGES * 2 * 128 * 36 * (int)sizeof(float);   // 110,592 B
    cudaFuncSetAttribute(gemm_tf32_pipe, cudaFuncAttributeMaxDynamicSharedMemorySize, gemmsm);

    const int M = NBATCH * L_SEQ;   // 4096 tokens

    // 0) pre-round operands to tf32
    {
        int n1 = M * HIDDEN;
        round_kernel<<<(n1 + 255)/256, 256>>>(hs, hsr, n1);
        int n2 = PROJ_PAD * HIDDEN;
        round_pad_kernel<<<(n2 + 255)/256, 256>>>(W_in, Wir, PROJ, PROJ_PAD, HIDDEN);
        int n3 = HIDDEN * D_INNER;
        round_kernel<<<(n3 + 255)/256, 256>>>(W_out, Wor, n3);
    }

    // 1) in-proj: proj = hs @ W_in^T   (pipelined tf32 tensor cores)
    gemm_tf32_pipe<<<dim3(PROJ_PAD/128, M/128), 256, gemmsm>>>(
        hsr, Wir, proj, M, PROJ, HIDDEN, HIDDEN, HIDDEN, PROJ);

    // 2) causal conv + SiLU
    conv_silu_kernel<<<(NBATCH*L_SEQ*CONV_DIM)/256, 256>>>(conv_w, conv_b);

    // 3) dt softplus + cumsum(dt*A) per chunk
    dtscan_kernel<<<NBATCH*NH*NC, 256>>>(dt_bias, A_log);

    // 4) Gt[s,l] = B[s]·C[l] per (b,chunk)
    sgemm_nt<<<dim3(2, 2, NBATCH*NC), 256>>>(
        xc + D_INNER, xc + D_INNER + NDIM, Gt,
        CSZ, CSZ, NDIM, CONV_DIM, CONV_DIM, CSZ,
        (long long)CSZ*CONV_DIM, (long long)CSZ*CONV_DIM, (long long)CSZ*CSZ);

    // 5) intra-chunk diag output (+ D*x) -> g_y
    ydiag_kernel<<<NBATCH*NC*NH, 256, dynsm>>>(Dp);

    // 6) per-chunk states
    states_kernel<<<NBATCH*NC*NH, 256, dynsm>>>();

    // 7) inter-chunk scan
    scan_kernel<<<(NBATCH*NH*PDIM*NDIM)/256, 256>>>();

    // 8) inter-chunk contribution into g_y
    yoff_kernel<<<NBATCH*NC*NH, 256>>>();

    // 9) gated RMSNorm in place (emits tf32-rounded y)
    norm_kernel<<<M, 256>>>(norm_w);

    // 10) out-proj: out = gn @ W_out^T  (pipelined tf32 tensor cores)
    gemm_tf32_pipe<<<dim3(HIDDEN/128, M/128), 256, gemmsm>>>(
        y, Wor, out, M, HIDDEN, D_INNER, D_INNER, D_INNER, HIDDEN);
}

// round 4
// speedup vs baseline: 2.7000x; 1.1940x over previous
#include <cuda_runtime.h>
#include <math.h>

#define L_SEQ   2048
#define NBATCH  2
#define HIDDEN  2048
#define NH      64
#define PDIM    64
#define NDIM    128
#define CSZ     256
#define NC      8
#define D_INNER 4096
#define CONV_DIM 4352
#define PROJ    8512
#define PROJ_PAD 8576   // 67 * 128

// ---------------- scratch (device globals: allocation-free) ----------------
__device__ float g_proj  [NBATCH*L_SEQ*PROJ];
__device__ float g_xc    [NBATCH*L_SEQ*CONV_DIM];
__device__ float g_dtsp  [NBATCH*L_SEQ*NH];
__device__ float g_Acum  [NBATCH*NH*NC*CSZ];
__device__ float g_Gt    [NBATCH*NC*CSZ*CSZ];
__device__ float g_states[NBATCH*NC*NH*PDIM*NDIM];
__device__ float g_prev  [NBATCH*NC*NH*PDIM*NDIM];
__device__ float g_y     [NBATCH*L_SEQ*D_INNER];
// tf32-pre-rounded operand copies
__device__ float g_hsr   [NBATCH*L_SEQ*HIDDEN];
__device__ float g_Wir   [PROJ_PAD*HIDDEN];
__device__ float g_Wor   [HIDDEN*D_INNER];

// ---------------- tf32 helpers --------------------------------------------
__device__ __forceinline__ float f2tf(float f) {
    unsigned r;
    asm("cvt.rna.tf32.f32 %0, %1;" : "=r"(r) : "f"(f));
    return __uint_as_float(r);
}

__device__ __forceinline__ void mma_tf32(
    float* c, const unsigned* a, const unsigned* b)
{
    asm volatile(
        "mma.sync.aligned.m16n8k8.row.col.f32.tf32.tf32.f32 "
        "{%0,%1,%2,%3}, {%4,%5,%6,%7}, {%8,%9}, {%0,%1,%2,%3};"
        : "+f"(c[0]), "+f"(c[1]), "+f"(c[2]), "+f"(c[3])
        : "r"(a[0]), "r"(a[1]), "r"(a[2]), "r"(a[3]),
          "r"(b[0]), "r"(b[1]));
}

__device__ __forceinline__ void cp16(unsigned smem, const float* g) {
    asm volatile("cp.async.cg.shared.global [%0], [%1], 16;\n" :: "r"(smem), "l"(g));
}
__device__ __forceinline__ void cp_commit() {
    asm volatile("cp.async.commit_group;\n");
}
template<int N> __device__ __forceinline__ void cp_wait() {
    asm volatile("cp.async.wait_group %0;\n" :: "n"(N));
}

// ---------------- pre-round kernels ----------------------------------------
__global__ __launch_bounds__(256) void round_kernel(
    const float* __restrict__ src, float* __restrict__ dst, int n)
{
    int i = blockIdx.x * 256 + threadIdx.x;
    if (i < n) dst[i] = f2tf(src[i]);
}
__global__ __launch_bounds__(256) void round_pad_kernel(
    const float* __restrict__ src, float* __restrict__ dst, int rows, int rows_pad, int cols)
{
    int i = blockIdx.x * 256 + threadIdx.x;
    if (i < rows_pad * cols) {
        int r = i / cols;
        dst[i] = (r < rows) ? f2tf(src[i]) : 0.f;
    }
}

// ---------------- pipelined tf32 tensor-core NT GEMM ------------------------
// C[m,n] = sum_k A[m,k]*B[n,k].  BM=BN=128, BK=32, 3-stage cp.async.
// Smem rows are 32 floats with XOR-swizzled 16B chunks (chunk^(row&7)):
//   98,304 B total -> 2 blocks/SM.  Requires M%128==0, K%32==0,
//   B padded to >= ceil(N/128)*128 rows; C stores guarded to n<N.
#define STAGES 3
#define SSTRIDE (128*32)
__global__ __launch_bounds__(256) void gemm_tf32_pipe(
    const float* __restrict__ A, const float* __restrict__ B, float* __restrict__ C,
    int M, int N, int K, int lda, int ldb, int ldc)
{
    extern __shared__ float sm[];
    float* As = sm;                        // [STAGES][128][32] swizzled
    float* Bs = sm + STAGES * SSTRIDE;
    int tid = threadIdx.x;
    int bm = blockIdx.y * 128, bn = blockIdx.x * 128;
    int warp = tid >> 5, lane = tid & 31;
    int g = lane >> 2, tg = lane & 3;
    int wm = (warp & 1) * 64, wn = (warp >> 1) * 32;

    float acc[4][4][4];
#pragma unroll
    for (int mi = 0; mi < 4; mi++)
#pragma unroll
        for (int ni = 0; ni < 4; ni++)
#pragma unroll
            for (int j = 0; j < 4; j++) acc[mi][ni][j] = 0.f;

    unsigned asBase = (unsigned)__cvta_generic_to_shared(As);
    unsigned bsBase = (unsigned)__cvta_generic_to_shared(Bs);

    const int KT = K >> 5;               // k-tiles of 32

    auto issue_stage = [&](int stage, int kt) {
        int kk = kt << 5;
        unsigned aS = asBase + (unsigned)(stage * SSTRIDE) * 4u;
        unsigned bS = bsBase + (unsigned)(stage * SSTRIDE) * 4u;
#pragma unroll
        for (int i = 0; i < 4; i++) {
            int id = tid + i * 256;              // 0..1023
            int row = id >> 3, c16 = id & 7;     // 128 rows x 8 chunks
            int pc = c16 ^ (row & 7);            // swizzled chunk
            unsigned off = (unsigned)(row * 32 + pc * 4) * 4u;
            cp16(aS + off, A + (size_t)(bm + row) * lda + kk + c16 * 4);
            cp16(bS + off, B + (size_t)(bn + row) * ldb + kk + c16 * 4);
        }
        cp_commit();
    };

    issue_stage(0, 0);
    if (KT > 1) issue_stage(1, 1);

    for (int kt = 0; kt < KT; kt++) {
        if (kt < KT - 1) cp_wait<1>(); else cp_wait<0>();
        __syncthreads();
        if (kt + 2 < KT) issue_stage((kt + 2) % STAGES, kt + 2);

        const float* Asb = As + (kt % STAGES) * SSTRIDE;
        const float* Bsb = Bs + (kt % STAGES) * SSTRIDE;
#pragma unroll
        for (int ks = 0; ks < 4; ks++) {
            // logical chunks 2ks (cols ks*8+0..3) and 2ks+1 (cols ks*8+4..7),
            // swizzled by row&7 == g for all fragment rows used here.
            int c0 = ((2*ks) ^ g) * 4 + tg;
            int c1 = ((2*ks + 1) ^ g) * 4 + tg;
            unsigned af[4][4], bf[4][2];
#pragma unroll
            for (int mi = 0; mi < 4; mi++) {
                int r = wm + mi * 16;
                af[mi][0] = __float_as_uint(Asb[(r + g    ) * 32 + c0]);
                af[mi][1] = __float_as_uint(Asb[(r + g + 8) * 32 + c0]);
                af[mi][2] = __float_as_uint(Asb[(r + g    ) * 32 + c1]);
                af[mi][3] = __float_as_uint(Asb[(r + g + 8) * 32 + c1]);
            }
#pragma unroll
            for (int ni = 0; ni < 4; ni++) {
                int r = wn + ni * 8;
                bf[ni][0] = __float_as_uint(Bsb[(r + g) * 32 + c0]);
                bf[ni][1] = __float_as_uint(Bsb[(r + g) * 32 + c1]);
            }
#pragma unroll
            for (int mi = 0; mi < 4; mi++)
#pragma unroll
                for (int ni = 0; ni < 4; ni++)
                    mma_tf32(acc[mi][ni], af[mi], bf[ni]);
        }
        __syncthreads();
    }

#pragma unroll
    for (int mi = 0; mi < 4; mi++) {
        int row0 = bm + wm + mi * 16 + g;
#pragma unroll
        for (int ni = 0; ni < 4; ni++) {
            int col = bn + wn + ni * 8 + 2 * tg;
            if (col < N) {
                *(float2*)(C + (size_t)row0 * ldc + col) =
                    make_float2(acc[mi][ni][0], acc[mi][ni][1]);
                *(float2*)(C + (size_t)(row0 + 8) * ldc + col) =
                    make_float2(acc[mi][ni][2], acc[mi][ni][3]);
            }
        }
    }
}

// ---------------- fp32 NT SGEMM (small batched Gt GEMM) --------------------
__global__ __launch_bounds__(256) void sgemm_nt(
    const float* __restrict__ A, const float* __restrict__ B, float* __restrict__ C,
    int M, int N, int K, int lda, int ldb, int ldc,
    long long sA, long long sB, long long sC)
{
    __shared__ float As[16][128];
    __shared__ float Bs[16][128];
    A += (long long)blockIdx.z * sA;
    B += (long long)blockIdx.z * sB;
    C += (long long)blockIdx.z * sC;
    int tid = threadIdx.x;
    int bm = blockIdx.y * 128, bn = blockIdx.x * 128;
    int tx = (tid & 15) * 8, ty = (tid >> 4) * 8;
    float acc[8][8];
#pragma unroll
    for (int i = 0; i < 8; i++)
#pragma unroll
        for (int j = 0; j < 8; j++) acc[i][j] = 0.f;

    for (int kk = 0; kk < K; kk += 16) {
#pragma unroll
        for (int i = 0; i < 2; i++) {
            int f = tid + i * 256;
            int row = f >> 2, c4 = (f & 3) << 2;
            float4 va = *(const float4*)(A + (long long)(bm + row) * lda + kk + c4);
            As[c4+0][row] = va.x; As[c4+1][row] = va.y;
            As[c4+2][row] = va.z; As[c4+3][row] = va.w;
            float4 vb = make_float4(0.f,0.f,0.f,0.f);
            int gb = bn + row;
            if (gb < N) vb = *(const float4*)(B + (long long)gb * ldb + kk + c4);
            Bs[c4+0][row] = vb.x; Bs[c4+1][row] = vb.y;
            Bs[c4+2][row] = vb.z; Bs[c4+3][row] = vb.w;
        }
        __syncthreads();
#pragma unroll
        for (int k = 0; k < 16; k++) {
            float4 a0 = *(const float4*)&As[k][ty];
            float4 a1 = *(const float4*)&As[k][ty+4];
            float4 b0 = *(const float4*)&Bs[k][tx];
            float4 b1 = *(const float4*)&Bs[k][tx+4];
            float ra[8] = {a0.x,a0.y,a0.z,a0.w,a1.x,a1.y,a1.z,a1.w};
            float rb[8] = {b0.x,b0.y,b0.z,b0.w,b1.x,b1.y,b1.z,b1.w};
#pragma unroll
            for (int i = 0; i < 8; i++)
#pragma unroll
                for (int j = 0; j < 8; j++) acc[i][j] += ra[i]*rb[j];
        }
        __syncthreads();
    }
#pragma unroll
    for (int i = 0; i < 8; i++) {
        float* crow = C + (long long)(bm + ty + i) * ldc + bn + tx;
#pragma unroll
        for (int j = 0; j < 8; j += 4) {
            if (bn + tx + j < N)
                *(float4*)(crow + j) = make_float4(acc[i][j],acc[i][j+1],acc[i][j+2],acc[i][j+3]);
        }
    }
}

// ---------------- causal depthwise conv (K=4) + bias + SiLU ----------------
__global__ __launch_bounds__(256) void conv_silu_kernel(
    const float* __restrict__ cw, const float* __restrict__ cb)
{
    int idx = blockIdx.x * 256 + threadIdx.x;
    int c = idx % CONV_DIM;
    int t = idx / CONV_DIM;
    int l = t % L_SEQ, b = t / L_SEQ;
    float acc = cb[c];
#pragma unroll
    for (int k = 0; k < 4; k++) {
        int ll = l - 3 + k;
        if (ll >= 0)
            acc += g_proj[((size_t)(b*L_SEQ + ll))*PROJ + D_INNER + c] * cw[c*4 + k];
    }
    acc = acc / (1.f + __expf(-acc));
    g_xc[(size_t)t*CONV_DIM + c] = acc;
}

// ---------------- dt softplus + per-chunk inclusive cumsum of dt*A ---------
__global__ __launch_bounds__(256) void dtscan_kernel(
    const float* __restrict__ dt_bias, const float* __restrict__ A_log)
{
    __shared__ float s[CSZ];
    int z = blockIdx.x;
    int c = z & 7, h = (z >> 3) & 63, b = z >> 9;
    int l = threadIdx.x;
    int gl = c*CSZ + l;
    float raw = g_proj[((size_t)(b*L_SEQ + gl))*PROJ + D_INNER + CONV_DIM + h] + dt_bias[h];
    float dts = (raw > 20.f) ? raw : log1pf(__expf(raw));
    g_dtsp[(size_t)(b*L_SEQ + gl)*NH + h] = dts;
    s[l] = -dts * __expf(A_log[h]);
    __syncthreads();
    for (int off = 1; off < CSZ; off <<= 1) {
        float v = (l >= off) ? s[l - off] : 0.f;
        __syncthreads();
        s[l] += v;
        __syncthreads();
    }
    g_Acum[((size_t)((b*NH + h)*NC + c))*CSZ + l] = s[l];
}

// ---------------- intra-chunk diagonal output (+ D*x), per (b,c,h) --------
__global__ __launch_bounds__(256) void ydiag_kernel(const float* __restrict__ Dp)
{
    extern __shared__ float smy[];
    float* Xs    = smy;
    float* Acs   = smy + CSZ*PDIM;
    float* dts_s = Acs + CSZ;
    int z = blockIdx.x;
    int h = z & 63, c = (z >> 6) & 7, b = z >> 9;
    int tid = threadIdx.x;
    Acs[tid]   = g_Acum[((size_t)((b*NH + h)*NC + c))*CSZ + tid];
    dts_s[tid] = g_dtsp[(size_t)(b*L_SEQ + c*CSZ + tid)*NH + h];
    __syncthreads();
    int p = tid & 63, l0 = tid >> 6;
    for (int i = 0; i < 64; i++) {
        int l = l0*64 + i;
        float xv = g_xc[(size_t)(b*L_SEQ + c*CSZ + l)*CONV_DIM + h*64 + p];
        Xs[l*64 + p] = xv * dts_s[l];
    }
    __syncthreads();

    int l = tid;
    float al = Acs[l];
    float4 acc[16];
#pragma unroll
    for (int j = 0; j < 16; j++) acc[j] = make_float4(0.f,0.f,0.f,0.f);
    const float* gt = g_Gt + (size_t)(b*NC + c)*CSZ*CSZ + l;
    for (int s = 0; s <= l; s++) {
        float w = gt[s*CSZ] * __expf(al - Acs[s]);
        const float4* xr = (const float4*)(Xs + s*64);
#pragma unroll
        for (int j = 0; j < 16; j++) {
            float4 v = xr[j];
            acc[j].x += w*v.x; acc[j].y += w*v.y; acc[j].z += w*v.z; acc[j].w += w*v.w;
        }
    }
    float dcoef = Dp[h] / fmaxf(dts_s[l], 1e-30f);
    {
        const float4* xr = (const float4*)(Xs + l*64);
#pragma unroll
        for (int j = 0; j < 16; j++) {
            float4 v = xr[j];
            acc[j].x += dcoef*v.x; acc[j].y += dcoef*v.y;
            acc[j].z += dcoef*v.z; acc[j].w += dcoef*v.w;
        }
    }
    __syncthreads();
    float4* xw = (float4*)(Xs + l*64);
#pragma unroll
    for (int j = 0; j < 16; j++) xw[j] = acc[j];
    __syncthreads();
    for (int i = 0; i < 64; i++) {
        int ll = l0*64 + i;
        g_y[(size_t)(b*L_SEQ + c*CSZ + ll)*D_INNER + h*64 + p] = Xs[ll*64 + p];
    }
}

// ---------------- per-chunk states ----------------------------------------
__global__ __launch_bounds__(256) void states_kernel()
{
    extern __shared__ float sms[];
    float* Xs    = sms;
    float* dec   = sms + CSZ*PDIM;
    float* dts_s = dec + CSZ;
    int z = blockIdx.x;
    int h = z & 63, c = (z >> 6) & 7, b = z >> 9;
    int tid = threadIdx.x;
    dec[tid]   = g_Acum[((size_t)((b*NH + h)*NC + c))*CSZ + tid];
    dts_s[tid] = g_dtsp[(size_t)(b*L_SEQ + c*CSZ + tid)*NH + h];
    __syncthreads();
    float alast = dec[CSZ-1];
    float aown  = dec[tid];
    __syncthreads();
    dec[tid] = __expf(alast - aown);
    int p = tid & 63, l0 = tid >> 6;
    for (int i = 0; i < 64; i++) {
        int l = l0*64 + i;
        float xv = g_xc[(size_t)(b*L_SEQ + c*CSZ + l)*CONV_DIM + h*64 + p];
        Xs[l*64 + p] = xv * dts_s[l];
    }
    __syncthreads();

    int n = tid & 127, ph = tid >> 7;
    float4 acc[8];
#pragma unroll
    for (int j = 0; j < 8; j++) acc[j] = make_float4(0.f,0.f,0.f,0.f);
    size_t brow = (size_t)(b*L_SEQ + c*CSZ)*CONV_DIM + D_INNER + n;
    for (int l = 0; l < CSZ; l++) {
        float w = g_xc[brow + (size_t)l*CONV_DIM] * dec[l];
        const float4* xr = (const float4*)(Xs + l*64 + ph*32);
#pragma unroll
        for (int j = 0; j < 8; j++) {
            float4 v = xr[j];
            acc[j].x += w*v.x; acc[j].y += w*v.y; acc[j].z += w*v.z; acc[j].w += w*v.w;
        }
    }
    size_t sb = ((size_t)((b*NC + c)*NH + h))*PDIM*NDIM;
#pragma unroll
    for (int j = 0; j < 8; j++) {
        int pb = ph*32 + j*4;
        g_states[sb + (size_t)(pb+0)*NDIM + n] = acc[j].x;
        g_states[sb + (size_t)(pb+1)*NDIM + n] = acc[j].y;
        g_states[sb + (size_t)(pb+2)*NDIM + n] = acc[j].z;
        g_states[sb + (size_t)(pb+3)*NDIM + n] = acc[j].w;
    }
}

// ---------------- inter-chunk scan ----------------------------------------
__global__ __launch_bounds__(256) void scan_kernel()
{
    int idx = blockIdx.x * 256 + threadIdx.x;
    int n = idx & 127;
    int p = (idx >> 7) & 63;
    int h = (idx >> 13) & 63;
    int b = idx >> 19;
    float carry = 0.f;
    for (int c = 0; c < NC; c++) {
        size_t off = ((size_t)((b*NC + c)*NH + h))*PDIM*NDIM + (size_t)p*NDIM + n;
        float dal = g_Acum[((size_t)((b*NH + h)*NC + c))*CSZ + (CSZ-1)];
        float s = g_states[off];
        g_prev[off] = carry;
        carry = carry * __expf(dal) + s;
    }
}

// ---------------- inter-chunk contribution --------------------------------
__global__ __launch_bounds__(256) void yoff_kernel()
{
    __shared__ float prevT[128*68];
    __shared__ float Acs[CSZ];
    int z = blockIdx.x;
    int h = z & 63, c = (z >> 6) & 7, b = z >> 9;
    int tid = threadIdx.x;
    Acs[tid] = g_Acum[((size_t)((b*NH + h)*NC + c))*CSZ + tid];
    int n = tid & 127, p0 = tid >> 7;
    size_t sb = ((size_t)((b*NC + c)*NH + h))*PDIM*NDIM;
    for (int i = 0; i < 32; i++) {
        int p = p0*32 + i;
        prevT[n*68 + p] = g_prev[sb + (size_t)p*NDIM + n];
    }
    __syncthreads();

    int l = tid;
    float4 acc[16];
#pragma unroll
    for (int j = 0; j < 16; j++) acc[j] = make_float4(0.f,0.f,0.f,0.f);
    const float* crow = g_xc + (size_t)(b*L_SEQ + c*CSZ + l)*CONV_DIM + D_INNER + NDIM;
    for (int n4 = 0; n4 < 32; n4++) {
        float4 cv = *(const float4*)(crow + n4*4);
        float cvals[4] = {cv.x, cv.y, cv.z, cv.w};
#pragma unroll
        for (int u = 0; u < 4; u++) {
            float cval = cvals[u];
            const float4* pr = (const float4*)(prevT + (n4*4 + u)*68);
#pragma unroll
            for (int j = 0; j < 16; j++) {
                float4 v = pr[j];
                acc[j].x += cval*v.x; acc[j].y += cval*v.y;
                acc[j].z += cval*v.z; acc[j].w += cval*v.w;
            }
        }
    }
    float e = __expf(Acs[l]);
    float* yrow = g_y + (size_t)(b*L_SEQ + c*CSZ + l)*D_INNER + h*64;
#pragma unroll
    for (int j = 0; j < 16; j++) {
        float4 v = *(float4*)(yrow + j*4);
        v.x += e*acc[j].x; v.y += e*acc[j].y; v.z += e*acc[j].z; v.w += e*acc[j].w;
        *(float4*)(yrow + j*4) = v;
    }
}

// ---------------- gated RMSNorm (writes tf32-rounded output) ---------------
__global__ __launch_bounds__(256) void norm_kernel(const float* __restrict__ norm_w)
{
    __shared__ float gs[D_INNER];
    __shared__ float red[8];
    int t = blockIdx.x;
    int tid = threadIdx.x;
    const float* zrow = g_proj + (size_t)t * PROJ;
    float* yrow = g_y + (size_t)t * D_INNER;
    float sum = 0.f;
    for (int i = tid; i < D_INNER; i += 256) {
        float zv = zrow[i];
        float g = yrow[i] * (zv / (1.f + __expf(-zv)));
        gs[i] = g;
        sum += g*g;
    }
#pragma unroll
    for (int o = 16; o; o >>= 1) sum += __shfl_xor_sync(0xffffffffu, sum, o);
    if ((tid & 31) == 0) red[tid >> 5] = sum;
    __syncthreads();
    if (tid < 8) {
        float v = red[tid];
#pragma unroll
        for (int o = 4; o; o >>= 1) v += __shfl_xor_sync(0xffu, v, o);
        if (tid == 0) red[0] = v;
    }
    __syncthreads();
    float r = rsqrtf(red[0] / (float)D_INNER + 1e-5f);
    for (int i = tid; i < D_INNER; i += 256) yrow[i] = f2tf(gs[i] * r * norm_w[i]);
}

// ---------------- launch ---------------------------------------------------
extern "C" void kernel_launch(void* const* d_in, const int* in_sizes, int n_in,
                              void* d_out, int out_size)
{
    const float* hs      = (const float*)d_in[0];
    const float* W_in    = (const float*)d_in[1];
    const float* conv_w  = (const float*)d_in[2];
    const float* conv_b  = (const float*)d_in[3];
    const float* dt_bias = (const float*)d_in[4];
    const float* A_log   = (const float*)d_in[5];
    const float* Dp      = (const float*)d_in[6];
    const float* norm_w  = (const float*)d_in[7];
    const float* W_out   = (const float*)d_in[8];
    float* out = (float*)d_out;

    float *proj, *xc, *y, *Gt, *hsr, *Wir, *Wor;
    cudaGetSymbolAddress((void**)&proj, g_proj);
    cudaGetSymbolAddress((void**)&xc,   g_xc);
    cudaGetSymbolAddress((void**)&y,    g_y);
    cudaGetSymbolAddress((void**)&Gt,   g_Gt);
    cudaGetSymbolAddress((void**)&hsr,  g_hsr);
    cudaGetSymbolAddress((void**)&Wir,  g_Wir);
    cudaGetSymbolAddress((void**)&Wor,  g_Wor);

    const int dynsm = (CSZ*PDIM + 2*CSZ) * (int)sizeof(float);
    cudaFuncSetAttribute(ydiag_kernel,  cudaFuncAttributeMaxDynamicSharedMemorySize, dynsm);
    cudaFuncSetAttribute(states_kernel, cudaFuncAttributeMaxDynamicSharedMemorySize, dynsm);
    const int gemmsm = STAGES * 2 * SSTRIDE * (int)sizeof(float);   // 98,304 B
    cudaFuncSetAttribute(gemm_tf32_pipe, cudaFuncAttributeMaxDynamicSharedMemorySize, gemmsm);

    const int M = NBATCH * L_SEQ;   // 4096 tokens

    // 0) pre-round operands to tf32
    {
        int n1 = M * HIDDEN;
        round_kernel<<<(n1 + 255)/256, 256>>>(hs, hsr, n1);
        int n2 = PROJ_PAD * HIDDEN;
        round_pad_kernel<<<(n2 + 255)/256, 256>>>(W_in, Wir, PROJ, PROJ_PAD, HIDDEN);
        int n3 = HIDDEN * D_INNER;
        round_kernel<<<(n3 + 255)/256, 256>>>(W_out, Wor, n3);
    }

    // 1) in-proj: proj = hs @ W_in^T   (pipelined tf32 tensor cores)
    gemm_tf32_pipe<<<dim3(PROJ_PAD/128, M/128), 256, gemmsm>>>(
        hsr, Wir, proj, M, PROJ, HIDDEN, HIDDEN, HIDDEN, PROJ);

    // 2) causal conv + SiLU
    conv_silu_kernel<<<(NBATCH*L_SEQ*CONV_DIM)/256, 256>>>(conv_w, conv_b);

    // 3) dt softplus + cumsum(dt*A) per chunk
    dtscan_kernel<<<NBATCH*NH*NC, 256>>>(dt_bias, A_log);

    // 4) Gt[s,l] = B[s]·C[l] per (b,chunk)
    sgemm_nt<<<dim3(2, 2, NBATCH*NC), 256>>>(
        xc + D_INNER, xc + D_INNER + NDIM, Gt,
        CSZ, CSZ, NDIM, CONV_DIM, CONV_DIM, CSZ,
        (long long)CSZ*CONV_DIM, (long long)CSZ*CONV_DIM, (long long)CSZ*CSZ);

    // 5) intra-chunk diag output (+ D*x) -> g_y
    ydiag_kernel<<<NBATCH*NC*NH, 256, dynsm>>>(Dp);

    // 6) per-chunk states
    states_kernel<<<NBATCH*NC*NH, 256, dynsm>>>();

    // 7) inter-chunk scan
    scan_kernel<<<(NBATCH*NH*PDIM*NDIM)/256, 256>>>();

    // 8) inter-chunk contribution into g_y
    yoff_kernel<<<NBATCH*NC*NH, 256>>>();

    // 9) gated RMSNorm in place (emits tf32-rounded y)
    norm_kernel<<<M, 256>>>(norm_w);

    // 10) out-proj: out = gn @ W_out^T  (pipelined tf32 tensor cores)
    gemm_tf32_pipe<<<dim3(HIDDEN/128, M/128), 256, gemmsm>>>(
        y, Wor, out, M, HIDDEN, D_INNER, D_INNER, D_INNER, HIDDEN);
}

// round 5
// speedup vs baseline: 3.0649x; 1.1351x over previous
#include <cuda_runtime.h>
#include <math.h>

#define L_SEQ   2048
#define NBATCH  2
#define HIDDEN  2048
#define NH      64
#define PDIM    64
#define NDIM    128
#define CS      64          // chunk size (was 256)
#define NC      32          // chunks per sequence
#define D_INNER 4096
#define CONV_DIM 4352
#define PROJ    8512
#define PROJ_PAD 8576   // 67 * 128

// ---------------- scratch (device globals: allocation-free) ----------------
__device__ float g_proj  [NBATCH*L_SEQ*PROJ];
__device__ float g_xc    [NBATCH*L_SEQ*CONV_DIM];
__device__ float g_dtsp  [NBATCH*L_SEQ*NH];
__device__ float g_Acum  [NBATCH*NH*NC*CS];
__device__ float g_Gt    [NBATCH*NC*CS*CS];        // G[l][s] = C[l]·B[s]
__device__ float g_states[NBATCH*NC*NH*PDIM*NDIM];
__device__ float g_prev  [NBATCH*NC*NH*PDIM*NDIM];
__device__ float g_y     [NBATCH*L_SEQ*D_INNER];
// tf32-pre-rounded operand copies
__device__ float g_hsr   [NBATCH*L_SEQ*HIDDEN];
__device__ float g_Wir   [PROJ_PAD*HIDDEN];
__device__ float g_Wor   [HIDDEN*D_INNER];

// ---------------- tf32 helpers --------------------------------------------
__device__ __forceinline__ float f2tf(float f) {
    unsigned r;
    asm("cvt.rna.tf32.f32 %0, %1;" : "=r"(r) : "f"(f));
    return __uint_as_float(r);
}

__device__ __forceinline__ void mma_tf32(
    float* c, const unsigned* a, const unsigned* b)
{
    asm volatile(
        "mma.sync.aligned.m16n8k8.row.col.f32.tf32.tf32.f32 "
        "{%0,%1,%2,%3}, {%4,%5,%6,%7}, {%8,%9}, {%0,%1,%2,%3};"
        : "+f"(c[0]), "+f"(c[1]), "+f"(c[2]), "+f"(c[3])
        : "r"(a[0]), "r"(a[1]), "r"(a[2]), "r"(a[3]),
          "r"(b[0]), "r"(b[1]));
}

__device__ __forceinline__ void cp16(unsigned smem, const float* g) {
    asm volatile("cp.async.cg.shared.global [%0], [%1], 16;\n" :: "r"(smem), "l"(g));
}
__device__ __forceinline__ void cp_commit() {
    asm volatile("cp.async.commit_group;\n");
}
template<int N> __device__ __forceinline__ void cp_wait() {
    asm volatile("cp.async.wait_group %0;\n" :: "n"(N));
}

// ---------------- pre-round kernels ----------------------------------------
__global__ __launch_bounds__(256) void round_kernel(
    const float* __restrict__ src, float* __restrict__ dst, int n)
{
    int i = blockIdx.x * 256 + threadIdx.x;
    if (i < n) dst[i] = f2tf(src[i]);
}
__global__ __launch_bounds__(256) void round_pad_kernel(
    const float* __restrict__ src, float* __restrict__ dst, int rows, int rows_pad, int cols)
{
    int i = blockIdx.x * 256 + threadIdx.x;
    if (i < rows_pad * cols) {
        int r = i / cols;
        dst[i] = (r < rows) ? f2tf(src[i]) : 0.f;
    }
}

// ---------------- pipelined tf32 tensor-core NT GEMM (unchanged) -----------
#define STAGES 3
#define SSTRIDE (128*32)
__global__ __launch_bounds__(256) void gemm_tf32_pipe(
    const float* __restrict__ A, const float* __restrict__ B, float* __restrict__ C,
    int M, int N, int K, int lda, int ldb, int ldc)
{
    extern __shared__ float sm[];
    float* As = sm;
    float* Bs = sm + STAGES * SSTRIDE;
    int tid = threadIdx.x;
    int bm = blockIdx.y * 128, bn = blockIdx.x * 128;
    int warp = tid >> 5, lane = tid & 31;
    int g = lane >> 2, tg = lane & 3;
    int wm = (warp & 1) * 64, wn = (warp >> 1) * 32;

    float acc[4][4][4];
#pragma unroll
    for (int mi = 0; mi < 4; mi++)
#pragma unroll
        for (int ni = 0; ni < 4; ni++)
#pragma unroll
            for (int j = 0; j < 4; j++) acc[mi][ni][j] = 0.f;

    unsigned asBase = (unsigned)__cvta_generic_to_shared(As);
    unsigned bsBase = (unsigned)__cvta_generic_to_shared(Bs);

    const int KT = K >> 5;

    auto issue_stage = [&](int stage, int kt) {
        int kk = kt << 5;
        unsigned aS = asBase + (unsigned)(stage * SSTRIDE) * 4u;
        unsigned bS = bsBase + (unsigned)(stage * SSTRIDE) * 4u;
#pragma unroll
        for (int i = 0; i < 4; i++) {
            int id = tid + i * 256;
            int row = id >> 3, c16 = id & 7;
            int pc = c16 ^ (row & 7);
            unsigned off = (unsigned)(row * 32 + pc * 4) * 4u;
            cp16(aS + off, A + (size_t)(bm + row) * lda + kk + c16 * 4);
            cp16(bS + off, B + (size_t)(bn + row) * ldb + kk + c16 * 4);
        }
        cp_commit();
    };

    issue_stage(0, 0);
    if (KT > 1) issue_stage(1, 1);

    for (int kt = 0; kt < KT; kt++) {
        if (kt < KT - 1) cp_wait<1>(); else cp_wait<0>();
        __syncthreads();
        if (kt + 2 < KT) issue_stage((kt + 2) % STAGES, kt + 2);

        const float* Asb = As + (kt % STAGES) * SSTRIDE;
        const float* Bsb = Bs + (kt % STAGES) * SSTRIDE;
#pragma unroll
        for (int ks = 0; ks < 4; ks++) {
            int c0 = ((2*ks) ^ g) * 4 + tg;
            int c1 = ((2*ks + 1) ^ g) * 4 + tg;
            unsigned af[4][4], bf[4][2];
#pragma unroll
            for (int mi = 0; mi < 4; mi++) {
                int r = wm + mi * 16;
                af[mi][0] = __float_as_uint(Asb[(r + g    ) * 32 + c0]);
                af[mi][1] = __float_as_uint(Asb[(r + g + 8) * 32 + c0]);
                af[mi][2] = __float_as_uint(Asb[(r + g    ) * 32 + c1]);
                af[mi][3] = __float_as_uint(Asb[(r + g + 8) * 32 + c1]);
            }
#pragma unroll
            for (int ni = 0; ni < 4; ni++) {
                int r = wn + ni * 8;
                bf[ni][0] = __float_as_uint(Bsb[(r + g) * 32 + c0]);
                bf[ni][1] = __float_as_uint(Bsb[(r + g) * 32 + c1]);
            }
#pragma unroll
            for (int mi = 0; mi < 4; mi++)
#pragma unroll
                for (int ni = 0; ni < 4; ni++)
                    mma_tf32(acc[mi][ni], af[mi], bf[ni]);
        }
        __syncthreads();
    }

#pragma unroll
    for (int mi = 0; mi < 4; mi++) {
        int row0 = bm + wm + mi * 16 + g;
#pragma unroll
        for (int ni = 0; ni < 4; ni++) {
            int col = bn + wn + ni * 8 + 2 * tg;
            if (col < N) {
                *(float2*)(C + (size_t)row0 * ldc + col) =
                    make_float2(acc[mi][ni][0], acc[mi][ni][1]);
                *(float2*)(C + (size_t)(row0 + 8) * ldc + col) =
                    make_float2(acc[mi][ni][2], acc[mi][ni][3]);
            }
        }
    }
}

// ---------------- causal depthwise conv (K=4) + bias + SiLU ----------------
__global__ __launch_bounds__(256) void conv_silu_kernel(
    const float* __restrict__ cw, const float* __restrict__ cb)
{
    int idx = blockIdx.x * 256 + threadIdx.x;
    int c = idx % CONV_DIM;
    int t = idx / CONV_DIM;
    int l = t % L_SEQ, b = t / L_SEQ;
    float acc = cb[c];
#pragma unroll
    for (int k = 0; k < 4; k++) {
        int ll = l - 3 + k;
        if (ll >= 0)
            acc += g_proj[((size_t)(b*L_SEQ + ll))*PROJ + D_INNER + c] * cw[c*4 + k];
    }
    acc = acc / (1.f + __expf(-acc));
    g_xc[(size_t)t*CONV_DIM + c] = acc;
}

// ------- dt softplus + per-64-chunk inclusive cumsum of dt*A ---------------
// block = 256 threads covering 4 chunks of 64; grid = NBATCH*NH*8
__global__ __launch_bounds__(256) void dtscan_kernel(
    const float* __restrict__ dt_bias, const float* __restrict__ A_log)
{
    __shared__ float s[256];
    int z = blockIdx.x;
    int q = z & 7, h = (z >> 3) & 63, b = z >> 9;
    int t = threadIdx.x;
    int gl = q*256 + t;
    float raw = g_proj[((size_t)(b*L_SEQ + gl))*PROJ + D_INNER + CONV_DIM + h] + dt_bias[h];
    float dts = (raw > 20.f) ? raw : log1pf(__expf(raw));
    g_dtsp[(size_t)(b*L_SEQ + gl)*NH + h] = dts;
    s[t] = -dts * __expf(A_log[h]);
    __syncthreads();
    // segmented inclusive scan within 64-aligned segments
    for (int off = 1; off < 64; off <<= 1) {
        float v = ((t & 63) >= off) ? s[t - off] : 0.f;
        __syncthreads();
        s[t] += v;
        __syncthreads();
    }
    int c = gl >> 6;
    g_Acum[((size_t)((b*NH + h)*NC + c))*CS + (gl & 63)] = s[t];
}

// ---------------- G[l][s] = C[l]·B[s] per (b,chunk), fp32 ------------------
// grid = NBATCH*NC, 256 threads. dyn smem: Bs[64][132] + Cs[64][132]
__global__ __launch_bounds__(256) void gt_kernel()
{
    extern __shared__ float smg[];
    float* Bs = smg;              // [64][132]
    float* Cs = smg + 64*132;
    int z = blockIdx.x;
    int c = z & 31, b = z >> 5;
    int tid = threadIdx.x;
    size_t t0 = (size_t)(b*L_SEQ + c*CS);
    for (int idx = tid; idx < 64*128; idx += 256) {
        int l = idx >> 7, n = idx & 127;
        Bs[l*132 + n] = g_xc[(t0 + l)*CONV_DIM + D_INNER + n];
        Cs[l*132 + n] = g_xc[(t0 + l)*CONV_DIM + D_INNER + NDIM + n];
    }
    __syncthreads();
    int l = tid >> 2, sb = tid & 3;
    float acc[16];
#pragma unroll
    for (int i = 0; i < 16; i++) acc[i] = 0.f;
    for (int k = 0; k < 128; k++) {
        float cl = Cs[l*132 + k];
#pragma unroll
        for (int i = 0; i < 16; i++)
            acc[i] += cl * Bs[(sb*16 + i)*132 + k];
    }
    float* gout = g_Gt + (size_t)(b*NC + c)*CS*CS + l*CS + sb*16;
#pragma unroll
    for (int i = 0; i < 16; i++) gout[i] = acc[i];
}

// ---------------- fused chunk forward: Y_diag (+D*x) and states ------------
// block per (b,c,h): grid NBATCH*NC*NH = 4096, 256 threads.
// GEMM1: Y[64,64] = W @ Xdt        (W[l,s] masked-decay G, D/dt on diagonal)
// GEMM2: S[64,128] = Xdt^T @ (dec·B)
__global__ __launch_bounds__(256) void chunk_fwd_kernel(const float* __restrict__ Dp)
{
    extern __shared__ float smc[];
    float* XdtT = smc;             // [64][68]  XdtT[p][l]
    float* W    = smc + 64*68;     // [64][68]  W[l][s]
    float* BT   = smc + 2*64*68;   // [128][68] BT[n][l] (dec folded)
    float* Acs  = smc + 2*64*68 + 128*68;        // [64]
    float* dts  = Acs + 64;                       // [64]
    float* dec  = dts + 64;                       // [64]

    int z = blockIdx.x;
    int h = z & 63, c = (z >> 6) & 31, b = z >> 11;
    int tid = threadIdx.x;
    size_t t0 = (size_t)(b*L_SEQ + c*CS);

    if (tid < 64) {
        Acs[tid] = g_Acum[((size_t)((b*NH + h)*NC + c))*CS + tid];
        dts[tid] = g_dtsp[(t0 + tid)*NH + h];
    }
    __syncthreads();
    if (tid < 64) dec[tid] = __expf(Acs[63] - Acs[tid]);

    // XdtT[p][l] = tf32( x[l, h*64+p] * dt[l] )
    {
        int p = tid & 63, lg = tid >> 6;
#pragma unroll
        for (int i = 0; i < 16; i++) {
            int l = lg*16 + i;
            float v = g_xc[(t0 + l)*CONV_DIM + h*64 + p] * dts[l];
            XdtT[p*68 + l] = f2tf(v);
        }
    }
    // W[l][s]
    {
        int l = tid >> 2, sb = tid & 3;
        const float* grow = g_Gt + (size_t)(b*NC + c)*CS*CS + l*CS;
        float al = Acs[l];
        float dg = Dp[h] / fmaxf(dts[l], 1e-30f);
#pragma unroll
        for (int i = 0; i < 16; i++) {
            int s = sb*16 + i;
            float wv;
            if (s < l)       wv = f2tf(grow[s] * __expf(al - Acs[s]));
            else if (s == l) wv = f2tf(grow[s] + dg);
            else             wv = 0.f;
            W[l*68 + s] = wv;
        }
    }
    __syncthreads();   // dec, XdtT, W ready
    // BT[n][l] = tf32( B[l,n] * dec[l] )
    {
        int n = tid & 127, lg = tid >> 7;
#pragma unroll
        for (int i = 0; i < 32; i++) {
            int l = lg*32 + i;
            float v = g_xc[(t0 + l)*CONV_DIM + D_INNER + n] * dec[l];
            BT[n*68 + l] = f2tf(v);
        }
    }
    __syncthreads();

    int warp = tid >> 5, lane = tid & 31;
    int g = lane >> 2, tg = lane & 3;

    // GEMM1: Y = W @ Xdt   (M=64 l, N=64 p, K=64 s); warp tile 16x32
    {
        int wm = (warp & 3) * 16, wn = (warp >> 2) * 32;
        float acc[4][4];
#pragma unroll
        for (int ni = 0; ni < 4; ni++)
#pragma unroll
            for (int j = 0; j < 4; j++) acc[ni][j] = 0.f;
#pragma unroll
        for (int ks = 0; ks < 8; ks++) {
            int k0 = ks*8 + tg;
            unsigned a[4];
            a[0] = __float_as_uint(W[(wm + g    )*68 + k0    ]);
            a[1] = __float_as_uint(W[(wm + g + 8)*68 + k0    ]);
            a[2] = __float_as_uint(W[(wm + g    )*68 + k0 + 4]);
            a[3] = __float_as_uint(W[(wm + g + 8)*68 + k0 + 4]);
#pragma unroll
            for (int ni = 0; ni < 4; ni++) {
                unsigned bb[2];
                bb[0] = __float_as_uint(XdtT[(wn + ni*8 + g)*68 + k0    ]);
                bb[1] = __float_as_uint(XdtT[(wn + ni*8 + g)*68 + k0 + 4]);
                mma_tf32(acc[ni], a, bb);
            }
        }
        int r0 = wm + g, r1 = wm + g + 8;
#pragma unroll
        for (int ni = 0; ni < 4; ni++) {
            int col = wn + ni*8 + 2*tg;
            *(float2*)(g_y + (t0 + r0)*D_INNER + h*64 + col) =
                make_float2(acc[ni][0], acc[ni][1]);
            *(float2*)(g_y + (t0 + r1)*D_INNER + h*64 + col) =
                make_float2(acc[ni][2], acc[ni][3]);
        }
    }

    // GEMM2: S = XdtT @ BT  (M=64 p, N=128 n, K=64 l); warp tile 16x64
    {
        int wm = (warp & 3) * 16, wn = (warp >> 2) * 64;
        float acc[8][4];
#pragma unroll
        for (int ni = 0; ni < 8; ni++)
#pragma unroll
            for (int j = 0; j < 4; j++) acc[ni][j] = 0.f;
#pragma unroll
        for (int ks = 0; ks < 8; ks++) {
            int k0 = ks*8 + tg;
            unsigned a[4];
            a[0] = __float_as_uint(XdtT[(wm + g    )*68 + k0    ]);
            a[1] = __float_as_uint(XdtT[(wm + g + 8)*68 + k0    ]);
            a[2] = __float_as_uint(XdtT[(wm + g    )*68 + k0 + 4]);
            a[3] = __float_as_uint(XdtT[(wm + g + 8)*68 + k0 + 4]);
#pragma unroll
            for (int ni = 0; ni < 8; ni++) {
                unsigned bb[2];
                bb[0] = __float_as_uint(BT[(wn + ni*8 + g)*68 + k0    ]);
                bb[1] = __float_as_uint(BT[(wn + ni*8 + g)*68 + k0 + 4]);
                mma_tf32(acc[ni], a, bb);
            }
        }
        float* sb = g_states + ((size_t)((b*NC + c)*NH + h))*PDIM*NDIM;
        int r0 = wm + g, r1 = wm + g + 8;
#pragma unroll
        for (int ni = 0; ni < 8; ni++) {
            int col = wn + ni*8 + 2*tg;
            *(float2*)(sb + (size_t)r0*NDIM + col) = make_float2(acc[ni][0], acc[ni][1]);
            *(float2*)(sb + (size_t)r1*NDIM + col) = make_float2(acc[ni][2], acc[ni][3]);
        }
    }
}

// ---------------- inter-chunk scan (32 sequential chunks) ------------------
__global__ __launch_bounds__(256) void scan_kernel()
{
    int idx = blockIdx.x * 256 + threadIdx.x;
    int n = idx & 127;
    int p = (idx >> 7) & 63;
    int h = (idx >> 13) & 63;
    int b = idx >> 19;
    float carry = 0.f;
    for (int c = 0; c < NC; c++) {
        size_t off = ((size_t)((b*NC + c)*NH + h))*PDIM*NDIM + (size_t)p*NDIM + n;
        float dal = g_Acum[((size_t)((b*NH + h)*NC + c))*CS + (CS-1)];
        float s = g_states[off];
        g_prev[off] = carry;
        carry = carry * __expf(dal) + s;
    }
}

// ---------------- inter-chunk contribution (fp32 SIMT) ---------------------
// block per (b,c,h): grid 4096, 256 threads.
__global__ __launch_bounds__(256) void yoff_kernel()
{
    extern __shared__ float smo[];
    float* prevT = smo;             // [128][68]  prevT[n][p]
    float* Cs    = smo + 128*68;    // [64][132]
    float* Acs   = smo + 128*68 + 64*132;   // [64]
    int z = blockIdx.x;
    int h = z & 63, c = (z >> 6) & 31, b = z >> 11;
    int tid = threadIdx.x;
    size_t t0 = (size_t)(b*L_SEQ + c*CS);

    if (tid < 64) Acs[tid] = g_Acum[((size_t)((b*NH + h)*NC + c))*CS + tid];
    {
        int n = tid & 127, pg = tid >> 7;
        const float* pb = g_prev + ((size_t)((b*NC + c)*NH + h))*PDIM*NDIM;
#pragma unroll
        for (int i = 0; i < 32; i++) {
            int p = pg*32 + i;
            prevT[n*68 + p] = pb[(size_t)p*NDIM + n];
        }
    }
    {
        int n = tid & 127, lg = tid >> 7;
#pragma unroll
        for (int i = 0; i < 32; i++) {
            int l = lg*32 + i;
            Cs[l*132 + n] = g_xc[(t0 + l)*CONV_DIM + D_INNER + NDIM + n];
        }
    }
    __syncthreads();

    int l = tid >> 2, q = tid & 3;
    float4 acc[4];
#pragma unroll
    for (int j = 0; j < 4; j++) acc[j] = make_float4(0.f,0.f,0.f,0.f);
    for (int n = 0; n < 128; n++) {
        float cval = Cs[l*132 + n];
        const float4* pr = (const float4*)(prevT + n*68 + q*16);
#pragma unroll
        for (int j = 0; j < 4; j++) {
            float4 v = pr[j];
            acc[j].x += cval*v.x; acc[j].y += cval*v.y;
            acc[j].z += cval*v.z; acc[j].w += cval*v.w;
        }
    }
    float e = __expf(Acs[l]);
    float* yrow = g_y + (t0 + l)*D_INNER + h*64 + q*16;
#pragma unroll
    for (int j = 0; j < 4; j++) {
        float4 v = *(float4*)(yrow + j*4);
        v.x += e*acc[j].x; v.y += e*acc[j].y; v.z += e*acc[j].z; v.w += e*acc[j].w;
        *(float4*)(yrow + j*4) = v;
    }
}

// ---------------- gated RMSNorm (writes tf32-rounded output) ---------------
__global__ __launch_bounds__(256) void norm_kernel(const float* __restrict__ norm_w)
{
    __shared__ float gs[D_INNER];
    __shared__ float red[8];
    int t = blockIdx.x;
    int tid = threadIdx.x;
    const float* zrow = g_proj + (size_t)t * PROJ;
    float* yrow = g_y + (size_t)t * D_INNER;
    float sum = 0.f;
    for (int i = tid; i < D_INNER; i += 256) {
        float zv = zrow[i];
        float g = yrow[i] * (zv / (1.f + __expf(-zv)));
        gs[i] = g;
        sum += g*g;
    }
#pragma unroll
    for (int o = 16; o; o >>= 1) sum += __shfl_xor_sync(0xffffffffu, sum, o);
    if ((tid & 31) == 0) red[tid >> 5] = sum;
    __syncthreads();
    if (tid < 8) {
        float v = red[tid];
#pragma unroll
        for (int o = 4; o; o >>= 1) v += __shfl_xor_sync(0xffu, v, o);
        if (tid == 0) red[0] = v;
    }
    __syncthreads();
    float r = rsqrtf(red[0] / (float)D_INNER + 1e-5f);
    for (int i = tid; i < D_INNER; i += 256) yrow[i] = f2tf(gs[i] * r * norm_w[i]);
}

// ---------------- launch ---------------------------------------------------
extern "C" void kernel_launch(void* const* d_in, const int* in_sizes, int n_in,
                              void* d_out, int out_size)
{
    const float* hs      = (const float*)d_in[0];
    const float* W_in    = (const float*)d_in[1];
    const float* conv_w  = (const float*)d_in[2];
    const float* conv_b  = (const float*)d_in[3];
    const float* dt_bias = (const float*)d_in[4];
    const float* A_log   = (const float*)d_in[5];
    const float* Dp      = (const float*)d_in[6];
    const float* norm_w  = (const float*)d_in[7];
    const float* W_out   = (const float*)d_in[8];
    float* out = (float*)d_out;

    float *proj, *y, *hsr, *Wir, *Wor;
    cudaGetSymbolAddress((void**)&proj, g_proj);
    cudaGetSymbolAddress((void**)&y,    g_y);
    cudaGetSymbolAddress((void**)&hsr,  g_hsr);
    cudaGetSymbolAddress((void**)&Wir,  g_Wir);
    cudaGetSymbolAddress((void**)&Wor,  g_Wor);

    const int gemmsm  = STAGES * 2 * SSTRIDE * (int)sizeof(float);          // 98,304 B
    const int gtsm    = 2 * 64 * 132 * (int)sizeof(float);                  // 67,584 B
    const int chunksm = (2*64*68 + 128*68 + 3*64) * (int)sizeof(float);     // 70,400 B
    const int yoffsm  = (128*68 + 64*132 + 64) * (int)sizeof(float);        // 68,864 B
    cudaFuncSetAttribute(gemm_tf32_pipe,   cudaFuncAttributeMaxDynamicSharedMemorySize, gemmsm);
    cudaFuncSetAttribute(gt_kernel,        cudaFuncAttributeMaxDynamicSharedMemorySize, gtsm);
    cudaFuncSetAttribute(chunk_fwd_kernel, cudaFuncAttributeMaxDynamicSharedMemorySize, chunksm);
    cudaFuncSetAttribute(yoff_kernel,      cudaFuncAttributeMaxDynamicSharedMemorySize, yoffsm);

    const int M = NBATCH * L_SEQ;   // 4096 tokens

    // 0) pre-round operands to tf32
    {
        int n1 = M * HIDDEN;
        round_kernel<<<(n1 + 255)/256, 256>>>(hs, hsr, n1);
        int n2 = PROJ_PAD * HIDDEN;
        round_pad_kernel<<<(n2 + 255)/256, 256>>>(W_in, Wir, PROJ, PROJ_PAD, HIDDEN);
        int n3 = HIDDEN * D_INNER;
        round_kernel<<<(n3 + 255)/256, 256>>>(W_out, Wor, n3);
    }

    // 1) in-proj
    gemm_tf32_pipe<<<dim3(PROJ_PAD/128, M/128), 256, gemmsm>>>(
        hsr, Wir, proj, M, PROJ, HIDDEN, HIDDEN, HIDDEN, PROJ);

    // 2) causal conv + SiLU
    conv_silu_kernel<<<(NBATCH*L_SEQ*CONV_DIM)/256, 256>>>(conv_w, conv_b);

    // 3) dt softplus + per-64-chunk cumsum
    dtscan_kernel<<<NBATCH*NH*8, 256>>>(dt_bias, A_log);

    // 4) G[l][s] = C[l]·B[s] per (b,chunk)
    gt_kernel<<<NBATCH*NC, 256, gtsm>>>();

    // 5) fused Y_diag (+D*x) and per-chunk states (tf32 mma)
    chunk_fwd_kernel<<<NBATCH*NC*NH, 256, chunksm>>>(Dp);

    // 6) inter-chunk scan
    scan_kernel<<<(NBATCH*NH*PDIM*NDIM)/256, 256>>>();

    // 7) inter-chunk contribution into g_y (fp32)
    yoff_kernel<<<NBATCH*NC*NH, 256, yoffsm>>>();

    // 8) gated RMSNorm (emits tf32-rounded y)
    norm_kernel<<<M, 256>>>(norm_w);

    // 9) out-proj
    gemm_tf32_pipe<<<dim3(HIDDEN/128, M/128), 256, gemmsm>>>(
        y, Wor, out, M, HIDDEN, D_INNER, D_INNER, D_INNER, HIDDEN);
}

// round 7
// speedup vs baseline: 3.1473x; 1.0269x over previous
#include <cuda_runtime.h>
#include <math.h>
#include <stdint.h>

#define L_SEQ   2048
#define NBATCH  2
#define HIDDEN  2048
#define NH      64
#define PDIM    64
#define NDIM    128
#define CS      64
#define NC      32
#define D_INNER 4096
#define CONV_DIM 4352
#define PROJ    8512
#define PROJ_PAD 8576   // 67 * 128

// ---------------- scratch (device globals: allocation-free) ----------------
__device__ float g_proj  [NBATCH*L_SEQ*PROJ];
__device__ float g_xc    [NBATCH*L_SEQ*CONV_DIM];
__device__ float g_dtsp  [NBATCH*L_SEQ*NH];
__device__ float g_Acum  [NBATCH*NH*NC*CS];
__device__ float g_Gt    [NBATCH*NC*CS*CS];
__device__ float g_states[NBATCH*NC*NH*PDIM*NDIM];
__device__ float g_prev  [NBATCH*NC*NH*PDIM*NDIM];
__device__ float g_y     [NBATCH*L_SEQ*D_INNER];
__device__ float g_hsr   [NBATCH*L_SEQ*HIDDEN];
__device__ float g_Wir   [PROJ_PAD*HIDDEN];
__device__ float g_Wor   [HIDDEN*D_INNER];

// ---------------- tf32 helpers --------------------------------------------
__device__ __forceinline__ float f2tf(float f) {
    unsigned r;
    asm("cvt.rna.tf32.f32 %0, %1;" : "=r"(r) : "f"(f));
    return __uint_as_float(r);
}

__device__ __forceinline__ void mma_tf32(
    float* c, const unsigned* a, const unsigned* b)
{
    asm volatile(
        "mma.sync.aligned.m16n8k8.row.col.f32.tf32.tf32.f32 "
        "{%0,%1,%2,%3}, {%4,%5,%6,%7}, {%8,%9}, {%0,%1,%2,%3};"
        : "+f"(c[0]), "+f"(c[1]), "+f"(c[2]), "+f"(c[3])
        : "r"(a[0]), "r"(a[1]), "r"(a[2]), "r"(a[3]),
          "r"(b[0]), "r"(b[1]));
}

__device__ __forceinline__ void ldsm4(unsigned* r, uint32_t addr) {
    asm volatile(
        "ldmatrix.sync.aligned.m8n8.x4.shared.b16 {%0,%1,%2,%3}, [%4];"
        : "=r"(r[0]), "=r"(r[1]), "=r"(r[2]), "=r"(r[3]) : "r"(addr));
}

__device__ __forceinline__ void cp16(unsigned smem, const float* g) {
    asm volatile("cp.async.cg.shared.global [%0], [%1], 16;\n" :: "r"(smem), "l"(g));
}
__device__ __forceinline__ void cp_commit() {
    asm volatile("cp.async.commit_group;\n");
}
template<int N> __device__ __forceinline__ void cp_wait() {
    asm volatile("cp.async.wait_group %0;\n" :: "n"(N));
}

// ---------------- pre-round kernels ----------------------------------------
__global__ __launch_bounds__(256) void round_kernel(
    const float* __restrict__ src, float* __restrict__ dst, int n)
{
    int i = blockIdx.x * 256 + threadIdx.x;
    if (i < n) dst[i] = f2tf(src[i]);
}
__global__ __launch_bounds__(256) void round_pad_kernel(
    const float* __restrict__ src, float* __restrict__ dst, int rows, int rows_pad, int cols)
{
    int i = blockIdx.x * 256 + threadIdx.x;
    if (i < rows_pad * cols) {
        int r = i / cols;
        dst[i] = (r < rows) ? f2tf(src[i]) : 0.f;
    }
}

// ---------------- pipelined tf32 tensor-core NT GEMM (ldmatrix feed) -------
// C[m,n] = sum_k A[m,k]*B[n,k].  BM=BN=128, BK=32, 3-stage cp.async.
// Smem rows are 128 B with XOR-swizzled 16B chunks (chunk^(row&7)).
// Fragments fed by ldmatrix.m8n8.x4.b16 (8x4-f32 tiles == tf32 frag layout).
#define STAGES 3
#define SSTRIDE (128*32)
__global__ __launch_bounds__(256) void gemm_tf32_pipe(
    const float* __restrict__ A, const float* __restrict__ B, float* __restrict__ C,
    int M, int N, int K, int lda, int ldb, int ldc)
{
    extern __shared__ float sm[];
    float* As = sm;                        // [STAGES][128][32] swizzled
    float* Bs = sm + STAGES * SSTRIDE;
    int tid = threadIdx.x;
    int bm = blockIdx.y * 128, bn = blockIdx.x * 128;
    int warp = tid >> 5, lane = tid & 31;
    int g = lane >> 2, tg = lane & 3;
    int wm = (warp & 1) * 64, wn = (warp >> 1) * 32;

    // ldmatrix per-thread address components
    int grp = lane >> 3, rin = lane & 7;
    int rowA = (grp & 1) * 8 + rin;   // A: +8 rows on grp bit0
    int bitA = grp >> 1;              // A: +4 cols (next 16B chunk) on grp bit1
    int rowB = (grp >> 1) * 8 + rin;  // B: +8 rows on grp bit1
    int bitB = grp & 1;               // B: +4 cols on grp bit0

    float acc[4][4][4];
#pragma unroll
    for (int mi = 0; mi < 4; mi++)
#pragma unroll
        for (int ni = 0; ni < 4; ni++)
#pragma unroll
            for (int j = 0; j < 4; j++) acc[mi][ni][j] = 0.f;

    unsigned asBase = (unsigned)__cvta_generic_to_shared(As);
    unsigned bsBase = (unsigned)__cvta_generic_to_shared(Bs);

    const int KT = K >> 5;

    auto issue_stage = [&](int stage, int kt) {
        int kk = kt << 5;
        unsigned aS = asBase + (unsigned)(stage * SSTRIDE) * 4u;
        unsigned bS = bsBase + (unsigned)(stage * SSTRIDE) * 4u;
#pragma unroll
        for (int i = 0; i < 4; i++) {
            int id = tid + i * 256;
            int row = id >> 3, c16 = id & 7;
            int pc = c16 ^ (row & 7);
            unsigned off = (unsigned)(row * 32 + pc * 4) * 4u;
            cp16(aS + off, A + (size_t)(bm + row) * lda + kk + c16 * 4);
            cp16(bS + off, B + (size_t)(bn + row) * ldb + kk + c16 * 4);
        }
        cp_commit();
    };

    issue_stage(0, 0);
    if (KT > 1) issue_stage(1, 1);

    for (int kt = 0; kt < KT; kt++) {
        if (kt < KT - 1) cp_wait<1>(); else cp_wait<0>();
        __syncthreads();
        if (kt + 2 < KT) issue_stage((kt + 2) % STAGES, kt + 2);

        unsigned aS = asBase + (unsigned)((kt % STAGES) * SSTRIDE) * 4u;
        unsigned bS = bsBase + (unsigned)((kt % STAGES) * SSTRIDE) * 4u;
#pragma unroll
        for (int ks = 0; ks < 4; ks++) {
            unsigned af[4][4], bf[2][4];
#pragma unroll
            for (int mi = 0; mi < 4; mi++) {
                unsigned addr = aS
                    + (unsigned)((wm + mi * 16 + rowA) * 128)
                    + (unsigned)((((2*ks + bitA) ^ rin) & 7) << 4);
                ldsm4(af[mi], addr);
            }
#pragma unroll
            for (int np = 0; np < 2; np++) {
                unsigned addr = bS
                    + (unsigned)((wn + np * 16 + rowB) * 128)
                    + (unsigned)((((2*ks + bitB) ^ rin) & 7) << 4);
                ldsm4(bf[np], addr);
            }
#pragma unroll
            for (int mi = 0; mi < 4; mi++) {
#pragma unroll
                for (int np = 0; np < 2; np++) {
                    mma_tf32(acc[mi][np*2    ], af[mi], &bf[np][0]);
                    mma_tf32(acc[mi][np*2 + 1], af[mi], &bf[np][2]);
                }
            }
        }
        __syncthreads();
    }

#pragma unroll
    for (int mi = 0; mi < 4; mi++) {
        int row0 = bm + wm + mi * 16 + g;
#pragma unroll
        for (int ni = 0; ni < 4; ni++) {
            int col = bn + wn + ni * 8 + 2 * tg;
            if (col < N) {
                *(float2*)(C + (size_t)row0 * ldc + col) =
                    make_float2(acc[mi][ni][0], acc[mi][ni][1]);
                *(float2*)(C + (size_t)(row0 + 8) * ldc + col) =
                    make_float2(acc[mi][ni][2], acc[mi][ni][3]);
            }
        }
    }
}

// ---------------- causal depthwise conv (K=4) + bias + SiLU ----------------
__global__ __launch_bounds__(256) void conv_silu_kernel(
    const float* __restrict__ cw, const float* __restrict__ cb)
{
    int idx = blockIdx.x * 256 + threadIdx.x;
    int c = idx % CONV_DIM;
    int t = idx / CONV_DIM;
    int l = t % L_SEQ, b = t / L_SEQ;
    float acc = cb[c];
#pragma unroll
    for (int k = 0; k < 4; k++) {
        int ll = l - 3 + k;
        if (ll >= 0)
            acc += g_proj[((size_t)(b*L_SEQ + ll))*PROJ + D_INNER + c] * cw[c*4 + k];
    }
    acc = acc / (1.f + __expf(-acc));
    g_xc[(size_t)t*CONV_DIM + c] = acc;
}

// ------- dt softplus + per-64-chunk inclusive cumsum of dt*A ---------------
__global__ __launch_bounds__(256) void dtscan_kernel(
    const float* __restrict__ dt_bias, const float* __restrict__ A_log)
{
    __shared__ float s[256];
    int z = blockIdx.x;
    int q = z & 7, h = (z >> 3) & 63, b = z >> 9;
    int t = threadIdx.x;
    int gl = q*256 + t;
    float raw = g_proj[((size_t)(b*L_SEQ + gl))*PROJ + D_INNER + CONV_DIM + h] + dt_bias[h];
    float dts = (raw > 20.f) ? raw : log1pf(__expf(raw));
    g_dtsp[(size_t)(b*L_SEQ + gl)*NH + h] = dts;
    s[t] = -dts * __expf(A_log[h]);
    __syncthreads();
    for (int off = 1; off < 64; off <<= 1) {
        float v = ((t & 63) >= off) ? s[t - off] : 0.f;
        __syncthreads();
        s[t] += v;
        __syncthreads();
    }
    int c = gl >> 6;
    g_Acum[((size_t)((b*NH + h)*NC + c))*CS + (gl & 63)] = s[t];
}

// ---------------- G[l][s] = C[l]·B[s] per (b,chunk), fp32 ------------------
__global__ __launch_bounds__(256) void gt_kernel()
{
    extern __shared__ float smg[];
    float* Bs = smg;              // [64][132]
    float* Cs = smg + 64*132;
    int z = blockIdx.x;
    int c = z & 31, b = z >> 5;
    int tid = threadIdx.x;
    size_t t0 = (size_t)(b*L_SEQ + c*CS);
    for (int idx = tid; idx < 64*128; idx += 256) {
        int l = idx >> 7, n = idx & 127;
        Bs[l*132 + n] = g_xc[(t0 + l)*CONV_DIM + D_INNER + n];
        Cs[l*132 + n] = g_xc[(t0 + l)*CONV_DIM + D_INNER + NDIM + n];
    }
    __syncthreads();
    int l = tid >> 2, sb = tid & 3;
    float acc[16];
#pragma unroll
    for (int i = 0; i < 16; i++) acc[i] = 0.f;
    for (int k = 0; k < 128; k++) {
        float cl = Cs[l*132 + k];
#pragma unroll
        for (int i = 0; i < 16; i++)
            acc[i] += cl * Bs[(sb*16 + i)*132 + k];
    }
    float* gout = g_Gt + (size_t)(b*NC + c)*CS*CS + l*CS + sb*16;
#pragma unroll
    for (int i = 0; i < 16; i++) gout[i] = acc[i];
}

// ---------------- fused chunk forward: Y_diag (+D*x) and states ------------
__global__ __launch_bounds__(256) void chunk_fwd_kernel(const float* __restrict__ Dp)
{
    extern __shared__ float smc[];
    float* XdtT = smc;             // [64][68]
    float* W    = smc + 64*68;     // [64][68]
    float* BT   = smc + 2*64*68;   // [128][68]
    float* Acs  = smc + 2*64*68 + 128*68;
    float* dts  = Acs + 64;
    float* dec  = dts + 64;

    int z = blockIdx.x;
    int h = z & 63, c = (z >> 6) & 31, b = z >> 11;
    int tid = threadIdx.x;
    size_t t0 = (size_t)(b*L_SEQ + c*CS);

    if (tid < 64) {
        Acs[tid] = g_Acum[((size_t)((b*NH + h)*NC + c))*CS + tid];
        dts[tid] = g_dtsp[(t0 + tid)*NH + h];
    }
    __syncthreads();
    if (tid < 64) dec[tid] = __expf(Acs[63] - Acs[tid]);

    {
        int p = tid & 63, lg = tid >> 6;
#pragma unroll
        for (int i = 0; i < 16; i++) {
            int l = lg*16 + i;
            float v = g_xc[(t0 + l)*CONV_DIM + h*64 + p] * dts[l];
            XdtT[p*68 + l] = f2tf(v);
        }
    }
    {
        int l = tid >> 2, sb = tid & 3;
        const float* grow = g_Gt + (size_t)(b*NC + c)*CS*CS + l*CS;
        float al = Acs[l];
        float dg = Dp[h] / fmaxf(dts[l], 1e-30f);
#pragma unroll
        for (int i = 0; i < 16; i++) {
            int s = sb*16 + i;
            float wv;
            if (s < l)       wv = f2tf(grow[s] * __expf(al - Acs[s]));
            else if (s == l) wv = f2tf(grow[s] + dg);
            else             wv = 0.f;
            W[l*68 + s] = wv;
        }
    }
    __syncthreads();
    {
        int n = tid & 127, lg = tid >> 7;
#pragma unroll
        for (int i = 0; i < 32; i++) {
            int l = lg*32 + i;
            float v = g_xc[(t0 + l)*CONV_DIM + D_INNER + n] * dec[l];
            BT[n*68 + l] = f2tf(v);
        }
    }
    __syncthreads();

    int warp = tid >> 5, lane = tid & 31;
    int g = lane >> 2, tg = lane & 3;

    {
        int wm = (warp & 3) * 16, wn = (warp >> 2) * 32;
        float acc[4][4];
#pragma unroll
        for (int ni = 0; ni < 4; ni++)
#pragma unroll
            for (int j = 0; j < 4; j++) acc[ni][j] = 0.f;
#pragma unroll
        for (int ks = 0; ks < 8; ks++) {
            int k0 = ks*8 + tg;
            unsigned a[4];
            a[0] = __float_as_uint(W[(wm + g    )*68 + k0    ]);
            a[1] = __float_as_uint(W[(wm + g + 8)*68 + k0    ]);
            a[2] = __float_as_uint(W[(wm + g    )*68 + k0 + 4]);
            a[3] = __float_as_uint(W[(wm + g + 8)*68 + k0 + 4]);
#pragma unroll
            for (int ni = 0; ni < 4; ni++) {
                unsigned bb[2];
                bb[0] = __float_as_uint(XdtT[(wn + ni*8 + g)*68 + k0    ]);
                bb[1] = __float_as_uint(XdtT[(wn + ni*8 + g)*68 + k0 + 4]);
                mma_tf32(acc[ni], a, bb);
            }
        }
        int r0 = wm + g, r1 = wm + g + 8;
#pragma unroll
        for (int ni = 0; ni < 4; ni++) {
            int col = wn + ni*8 + 2*tg;
            *(float2*)(g_y + (t0 + r0)*D_INNER + h*64 + col) =
                make_float2(acc[ni][0], acc[ni][1]);
            *(float2*)(g_y + (t0 + r1)*D_INNER + h*64 + col) =
                make_float2(acc[ni][2], acc[ni][3]);
        }
    }

    {
        int wm = (warp & 3) * 16, wn = (warp >> 2) * 64;
        float acc[8][4];
#pragma unroll
        for (int ni = 0; ni < 8; ni++)
#pragma unroll
            for (int j = 0; j < 4; j++) acc[ni][j] = 0.f;
#pragma unroll
        for (int ks = 0; ks < 8; ks++) {
            int k0 = ks*8 + tg;
            unsigned a[4];
            a[0] = __float_as_uint(XdtT[(wm + g    )*68 + k0    ]);
            a[1] = __float_as_uint(XdtT[(wm + g + 8)*68 + k0    ]);
            a[2] = __float_as_uint(XdtT[(wm + g    )*68 + k0 + 4]);
            a[3] = __float_as_uint(XdtT[(wm + g + 8)*68 + k0 + 4]);
#pragma unroll
            for (int ni = 0; ni < 8; ni++) {
                unsigned bb[2];
                bb[0] = __float_as_uint(BT[(wn + ni*8 + g)*68 + k0    ]);
                bb[1] = __float_as_uint(BT[(wn + ni*8 + g)*68 + k0 + 4]);
                mma_tf32(acc[ni], a, bb);
            }
        }
        float* sb = g_states + ((size_t)((b*NC + c)*NH + h))*PDIM*NDIM;
        int r0 = wm + g, r1 = wm + g + 8;
#pragma unroll
        for (int ni = 0; ni < 8; ni++) {
            int col = wn + ni*8 + 2*tg;
            *(float2*)(sb + (size_t)r0*NDIM + col) = make_float2(acc[ni][0], acc[ni][1]);
            *(float2*)(sb + (size_t)r1*NDIM + col) = make_float2(acc[ni][2], acc[ni][3]);
        }
    }
}

// ---------------- inter-chunk scan ------------------------------------------
__global__ __launch_bounds__(256) void scan_kernel()
{
    int idx = blockIdx.x * 256 + threadIdx.x;
    int n = idx & 127;
    int p = (idx >> 7) & 63;
    int h = (idx >> 13) & 63;
    int b = idx >> 19;
    float carry = 0.f;
    for (int c = 0; c < NC; c++) {
        size_t off = ((size_t)((b*NC + c)*NH + h))*PDIM*NDIM + (size_t)p*NDIM + n;
        float dal = g_Acum[((size_t)((b*NH + h)*NC + c))*CS + (CS-1)];
        float s = g_states[off];
        g_prev[off] = carry;
        carry = carry * __expf(dal) + s;
    }
}

// ---------------- inter-chunk contribution (fp32 SIMT) ---------------------
__global__ __launch_bounds__(256) void yoff_kernel()
{
    extern __shared__ float smo[];
    float* prevT = smo;             // [128][68]
    float* Cs    = smo + 128*68;    // [64][132]
    float* Acs   = smo + 128*68 + 64*132;
    int z = blockIdx.x;
    int h = z & 63, c = (z >> 6) & 31, b = z >> 11;
    int tid = threadIdx.x;
    size_t t0 = (size_t)(b*L_SEQ + c*CS);

    if (tid < 64) Acs[tid] = g_Acum[((size_t)((b*NH + h)*NC + c))*CS + tid];
    {
        int n = tid & 127, pg = tid >> 7;
        const float* pb = g_prev + ((size_t)((b*NC + c)*NH + h))*PDIM*NDIM;
#pragma unroll
        for (int i = 0; i < 32; i++) {
            int p = pg*32 + i;
            prevT[n*68 + p] = pb[(size_t)p*NDIM + n];
        }
    }
    {
        int n = tid & 127, lg = tid >> 7;
#pragma unroll
        for (int i = 0; i < 32; i++) {
            int l = lg*32 + i;
            Cs[l*132 + n] = g_xc[(t0 + l)*CONV_DIM + D_INNER + NDIM + n];
        }
    }
    __syncthreads();

    int l = tid >> 2, q = tid & 3;
    float4 acc[4];
#pragma unroll
    for (int j = 0; j < 4; j++) acc[j] = make_float4(0.f,0.f,0.f,0.f);
    for (int n = 0; n < 128; n++) {
        float cval = Cs[l*132 + n];
        const float4* pr = (const float4*)(prevT + n*68 + q*16);
#pragma unroll
        for (int j = 0; j < 4; j++) {
            float4 v = pr[j];
            acc[j].x += cval*v.x; acc[j].y += cval*v.y;
            acc[j].z += cval*v.z; acc[j].w += cval*v.w;
        }
    }
    float e = __expf(Acs[l]);
    float* yrow = g_y + (t0 + l)*D_INNER + h*64 + q*16;
#pragma unroll
    for (int j = 0; j < 4; j++) {
        float4 v = *(float4*)(yrow + j*4);
        v.x += e*acc[j].x; v.y += e*acc[j].y; v.z += e*acc[j].z; v.w += e*acc[j].w;
        *(float4*)(yrow + j*4) = v;
    }
}

// ---------------- gated RMSNorm (writes tf32-rounded output) ---------------
__global__ __launch_bounds__(256) void norm_kernel(const float* __restrict__ norm_w)
{
    __shared__ float gs[D_INNER];
    __shared__ float red[8];
    int t = blockIdx.x;
    int tid = threadIdx.x;
    const float* zrow = g_proj + (size_t)t * PROJ;
    float* yrow = g_y + (size_t)t * D_INNER;
    float sum = 0.f;
    for (int i = tid; i < D_INNER; i += 256) {
        float zv = zrow[i];
        float g = yrow[i] * (zv / (1.f + __expf(-zv)));
        gs[i] = g;
        sum += g*g;
    }
#pragma unroll
    for (int o = 16; o; o >>= 1) sum += __shfl_xor_sync(0xffffffffu, sum, o);
    if ((tid & 31) == 0) red[tid >> 5] = sum;
    __syncthreads();
    if (tid < 8) {
        float v = red[tid];
#pragma unroll
        for (int o = 4; o; o >>= 1) v += __shfl_xor_sync(0xffu, v, o);
        if (tid == 0) red[0] = v;
    }
    __syncthreads();
    float r = rsqrtf(red[0] / (float)D_INNER + 1e-5f);
    for (int i = tid; i < D_INNER; i += 256) yrow[i] = f2tf(gs[i] * r * norm_w[i]);
}

// ---------------- launch ---------------------------------------------------
extern "C" void kernel_launch(void* const* d_in, const int* in_sizes, int n_in,
                              void* d_out, int out_size)
{
    const float* hs      = (const float*)d_in[0];
    const float* W_in    = (const float*)d_in[1];
    const float* conv_w  = (const float*)d_in[2];
    const float* conv_b  = (const float*)d_in[3];
    const float* dt_bias = (const float*)d_in[4];
    const float* A_log   = (const float*)d_in[5];
    const float* Dp      = (const float*)d_in[6];
    const float* norm_w  = (const float*)d_in[7];
    const float* W_out   = (const float*)d_in[8];
    float* out = (float*)d_out;

    float *proj, *y, *hsr, *Wir, *Wor;
    cudaGetSymbolAddress((void**)&proj, g_proj);
    cudaGetSymbolAddress((void**)&y,    g_y);
    cudaGetSymbolAddress((void**)&hsr,  g_hsr);
    cudaGetSymbolAddress((void**)&Wir,  g_Wir);
    cudaGetSymbolAddress((void**)&Wor,  g_Wor);

    const int gemmsm  = STAGES * 2 * SSTRIDE * (int)sizeof(float);          // 98,304 B
    const int gtsm    = 2 * 64 * 132 * (int)sizeof(float);
    const int chunksm = (2*64*68 + 128*68 + 3*64) * (int)sizeof(float);
    const int yoffsm  = (128*68 + 64*132 + 64) * (int)sizeof(float);
    cudaFuncSetAttribute(gemm_tf32_pipe,   cudaFuncAttributeMaxDynamicSharedMemorySize, gemmsm);
    cudaFuncSetAttribute(gt_kernel,        cudaFuncAttributeMaxDynamicSharedMemorySize, gtsm);
    cudaFuncSetAttribute(chunk_fwd_kernel, cudaFuncAttributeMaxDynamicSharedMemorySize, chunksm);
    cudaFuncSetAttribute(yoff_kernel,      cudaFuncAttributeMaxDynamicSharedMemorySize, yoffsm);

    const int M = NBATCH * L_SEQ;   // 4096 tokens

    // 0) pre-round operands to tf32
    {
        int n1 = M * HIDDEN;
        round_kernel<<<(n1 + 255)/256, 256>>>(hs, hsr, n1);
        int n2 = PROJ_PAD * HIDDEN;
        round_pad_kernel<<<(n2 + 255)/256, 256>>>(W_in, Wir, PROJ, PROJ_PAD, HIDDEN);
        int n3 = HIDDEN * D_INNER;
        round_kernel<<<(n3 + 255)/256, 256>>>(W_out, Wor, n3);
    }

    // 1) in-proj
    gemm_tf32_pipe<<<dim3(PROJ_PAD/128, M/128), 256, gemmsm>>>(
        hsr, Wir, proj, M, PROJ, HIDDEN, HIDDEN, HIDDEN, PROJ);

    // 2) causal conv + SiLU
    conv_silu_kernel<<<(NBATCH*L_SEQ*CONV_DIM)/256, 256>>>(conv_w, conv_b);

    // 3) dt softplus + per-64-chunk cumsum
    dtscan_kernel<<<NBATCH*NH*8, 256>>>(dt_bias, A_log);

    // 4) G[l][s] = C[l]·B[s] per (b,chunk)
    gt_kernel<<<NBATCH*NC, 256, gtsm>>>();

    // 5) fused Y_diag (+D*x) and per-chunk states
    chunk_fwd_kernel<<<NBATCH*NC*NH, 256, chunksm>>>(Dp);

    // 6) inter-chunk scan
    scan_kernel<<<(NBATCH*NH*PDIM*NDIM)/256, 256>>>();

    // 7) inter-chunk contribution
    yoff_kernel<<<NBATCH*NC*NH, 256, yoffsm>>>();

    // 8) gated RMSNorm (emits tf32-rounded y)
    norm_kernel<<<M, 256>>>(norm_w);

    // 9) out-proj
    gemm_tf32_pipe<<<dim3(HIDDEN/128, M/128), 256, gemmsm>>>(
        y, Wor, out, M, HIDDEN, D_INNER, D_INNER, D_INNER, HIDDEN);
}

// round 8
// speedup vs baseline: 3.1606x; 1.0042x over previous
#include <cuda_runtime.h>
#include <math.h>
#include <stdint.h>

#define L_SEQ   2048
#define NBATCH  2
#define HIDDEN  2048
#define NH      64
#define PDIM    64
#define NDIM    128
#define CS      64
#define NC      32
#define D_INNER 4096
#define CONV_DIM 4352
#define PROJ    8512
#define PROJ_PAD 8576   // 67 * 128

// ---------------- scratch (device globals: allocation-free) ----------------
__device__ float g_proj  [NBATCH*L_SEQ*PROJ];
__device__ float g_xc    [NBATCH*L_SEQ*CONV_DIM];
__device__ float g_dtsp  [NBATCH*L_SEQ*NH];
__device__ float g_Acum  [NBATCH*NH*NC*CS];
__device__ float g_Gt    [NBATCH*NC*CS*CS];
__device__ float g_states[NBATCH*NC*NH*PDIM*NDIM];
__device__ float g_prev  [NBATCH*NC*NH*PDIM*NDIM];
__device__ float g_y     [NBATCH*L_SEQ*D_INNER];
__device__ float g_hsr   [NBATCH*L_SEQ*HIDDEN];
__device__ float g_Wir   [PROJ_PAD*HIDDEN];
__device__ float g_Wor   [HIDDEN*D_INNER];

// ---------------- tf32 helpers --------------------------------------------
__device__ __forceinline__ float f2tf(float f) {
    unsigned r;
    asm("cvt.rna.tf32.f32 %0, %1;" : "=r"(r) : "f"(f));
    return __uint_as_float(r);
}

__device__ __forceinline__ void mma_tf32(
    float* c, const unsigned* a, const unsigned* b)
{
    asm volatile(
        "mma.sync.aligned.m16n8k8.row.col.f32.tf32.tf32.f32 "
        "{%0,%1,%2,%3}, {%4,%5,%6,%7}, {%8,%9}, {%0,%1,%2,%3};"
        : "+f"(c[0]), "+f"(c[1]), "+f"(c[2]), "+f"(c[3])
        : "r"(a[0]), "r"(a[1]), "r"(a[2]), "r"(a[3]),
          "r"(b[0]), "r"(b[1]));
}

__device__ __forceinline__ void ldsm4(unsigned* r, uint32_t addr) {
    asm volatile(
        "ldmatrix.sync.aligned.m8n8.x4.shared.b16 {%0,%1,%2,%3}, [%4];"
        : "=r"(r[0]), "=r"(r[1]), "=r"(r[2]), "=r"(r[3]) : "r"(addr));
}

__device__ __forceinline__ void cp16(unsigned smem, const float* g) {
    asm volatile("cp.async.cg.shared.global [%0], [%1], 16;\n" :: "r"(smem), "l"(g));
}
__device__ __forceinline__ void cp_commit() {
    asm volatile("cp.async.commit_group;\n");
}
template<int N> __device__ __forceinline__ void cp_wait() {
    asm volatile("cp.async.wait_group %0;\n" :: "n"(N));
}

// ---------------- pre-round kernels ----------------------------------------
__global__ __launch_bounds__(256) void round_kernel(
    const float* __restrict__ src, float* __restrict__ dst, int n)
{
    int i = blockIdx.x * 256 + threadIdx.x;
    if (i < n) dst[i] = f2tf(src[i]);
}
__global__ __launch_bounds__(256) void round_pad_kernel(
    const float* __restrict__ src, float* __restrict__ dst, int rows, int rows_pad, int cols)
{
    int i = blockIdx.x * 256 + threadIdx.x;
    if (i < rows_pad * cols) {
        int r = i / cols;
        dst[i] = (r < rows) ? f2tf(src[i]) : 0.f;
    }
}

// ---------------- persistent pipelined tf32 NT GEMM -------------------------
// C[m,n] = sum_k A[m,k]*B[n,k].  BM=BN=128, BK=32, 3-stage cp.async,
// 4 warps (128 thr), warp tile 64x64.  Persistent: grid=NBLK, tile loop.
// Smem rows 128 B, XOR-swizzled 16B chunks (chunk^(row&7)).
#define STAGES 3
#define SSTRIDE (128*32)
#define GEMM_THREADS 128
__global__ __launch_bounds__(GEMM_THREADS, 2) void gemm_tf32_pipe(
    const float* __restrict__ A, const float* __restrict__ B, float* __restrict__ C,
    int M, int N, int K, int lda, int ldb, int ldc)
{
    extern __shared__ float sm[];
    float* As = sm;                        // [STAGES][128][32] swizzled
    float* Bs = sm + STAGES * SSTRIDE;
    int tid = threadIdx.x;
    int warp = tid >> 5, lane = tid & 31;
    int g = lane >> 2, tg = lane & 3;
    int wm = (warp & 1) * 64, wn = (warp >> 1) * 64;

    // ldmatrix per-thread address components
    int grp = lane >> 3, rin = lane & 7;
    int rowA = (grp & 1) * 8 + rin;
    int bitA = grp >> 1;
    int rowB = (grp >> 1) * 8 + rin;
    int bitB = grp & 1;

    unsigned asBase = (unsigned)__cvta_generic_to_shared(As);
    unsigned bsBase = (unsigned)__cvta_generic_to_shared(Bs);

    const int KT = K >> 5;
    const int ntn = (N + 127) >> 7;
    const int ntiles = (M >> 7) * ntn;

    for (int tile = blockIdx.x; tile < ntiles; tile += gridDim.x) {
        int bm = (tile / ntn) * 128;
        int bn = (tile % ntn) * 128;

        float acc[4][8][4];
#pragma unroll
        for (int mi = 0; mi < 4; mi++)
#pragma unroll
            for (int ni = 0; ni < 8; ni++)
#pragma unroll
                for (int j = 0; j < 4; j++) acc[mi][ni][j] = 0.f;

        auto issue_stage = [&](int stage, int kt) {
            int kk = kt << 5;
            unsigned aS = asBase + (unsigned)(stage * SSTRIDE) * 4u;
            unsigned bS = bsBase + (unsigned)(stage * SSTRIDE) * 4u;
#pragma unroll
            for (int i = 0; i < 8; i++) {
                int id = tid + i * GEMM_THREADS;     // 0..1023
                int row = id >> 3, c16 = id & 7;
                int pc = c16 ^ (row & 7);
                unsigned off = (unsigned)(row * 32 + pc * 4) * 4u;
                cp16(aS + off, A + (size_t)(bm + row) * lda + kk + c16 * 4);
                cp16(bS + off, B + (size_t)(bn + row) * ldb + kk + c16 * 4);
            }
            cp_commit();
        };

        issue_stage(0, 0);
        if (KT > 1) issue_stage(1, 1);

        for (int kt = 0; kt < KT; kt++) {
            if (kt < KT - 1) cp_wait<1>(); else cp_wait<0>();
            __syncthreads();
            if (kt + 2 < KT) issue_stage((kt + 2) % STAGES, kt + 2);

            unsigned aS = asBase + (unsigned)((kt % STAGES) * SSTRIDE) * 4u;
            unsigned bS = bsBase + (unsigned)((kt % STAGES) * SSTRIDE) * 4u;
#pragma unroll
            for (int ks = 0; ks < 4; ks++) {
                unsigned af[4][4], bf[4][4];
#pragma unroll
                for (int mi = 0; mi < 4; mi++) {
                    unsigned addr = aS
                        + (unsigned)((wm + mi * 16 + rowA) * 128)
                        + (unsigned)((((2*ks + bitA) ^ rin) & 7) << 4);
                    ldsm4(af[mi], addr);
                }
#pragma unroll
                for (int np = 0; np < 4; np++) {
                    unsigned addr = bS
                        + (unsigned)((wn + np * 16 + rowB) * 128)
                        + (unsigned)((((2*ks + bitB) ^ rin) & 7) << 4);
                    ldsm4(bf[np], addr);
                }
#pragma unroll
                for (int mi = 0; mi < 4; mi++) {
#pragma unroll
                    for (int np = 0; np < 4; np++) {
                        mma_tf32(acc[mi][np*2    ], af[mi], &bf[np][0]);
                        mma_tf32(acc[mi][np*2 + 1], af[mi], &bf[np][2]);
                    }
                }
            }
            __syncthreads();
        }

#pragma unroll
        for (int mi = 0; mi < 4; mi++) {
            int row0 = bm + wm + mi * 16 + g;
#pragma unroll
            for (int ni = 0; ni < 8; ni++) {
                int col = bn + wn + ni * 8 + 2 * tg;
                if (col < N) {
                    *(float2*)(C + (size_t)row0 * ldc + col) =
                        make_float2(acc[mi][ni][0], acc[mi][ni][1]);
                    *(float2*)(C + (size_t)(row0 + 8) * ldc + col) =
                        make_float2(acc[mi][ni][2], acc[mi][ni][3]);
                }
            }
        }
        __syncthreads();   // protect smem stages before next tile's cp.async
    }
}

// ---------------- causal depthwise conv (K=4) + bias + SiLU ----------------
__global__ __launch_bounds__(256) void conv_silu_kernel(
    const float* __restrict__ cw, const float* __restrict__ cb)
{
    int idx = blockIdx.x * 256 + threadIdx.x;
    int c = idx % CONV_DIM;
    int t = idx / CONV_DIM;
    int l = t % L_SEQ, b = t / L_SEQ;
    float acc = cb[c];
#pragma unroll
    for (int k = 0; k < 4; k++) {
        int ll = l - 3 + k;
        if (ll >= 0)
            acc += g_proj[((size_t)(b*L_SEQ + ll))*PROJ + D_INNER + c] * cw[c*4 + k];
    }
    acc = acc / (1.f + __expf(-acc));
    g_xc[(size_t)t*CONV_DIM + c] = acc;
}

// ------- dt softplus + per-64-chunk inclusive cumsum of dt*A ---------------
__global__ __launch_bounds__(256) void dtscan_kernel(
    const float* __restrict__ dt_bias, const float* __restrict__ A_log)
{
    __shared__ float s[256];
    int z = blockIdx.x;
    int q = z & 7, h = (z >> 3) & 63, b = z >> 9;
    int t = threadIdx.x;
    int gl = q*256 + t;
    float raw = g_proj[((size_t)(b*L_SEQ + gl))*PROJ + D_INNER + CONV_DIM + h] + dt_bias[h];
    float dts = (raw > 20.f) ? raw : log1pf(__expf(raw));
    g_dtsp[(size_t)(b*L_SEQ + gl)*NH + h] = dts;
    s[t] = -dts * __expf(A_log[h]);
    __syncthreads();
    for (int off = 1; off < 64; off <<= 1) {
        float v = ((t & 63) >= off) ? s[t - off] : 0.f;
        __syncthreads();
        s[t] += v;
        __syncthreads();
    }
    int c = gl >> 6;
    g_Acum[((size_t)((b*NH + h)*NC + c))*CS + (gl & 63)] = s[t];
}

// ---------------- G[l][s] = C[l]·B[s] per (b,chunk), fp32 ------------------
__global__ __launch_bounds__(256) void gt_kernel()
{
    extern __shared__ float smg[];
    float* Bs = smg;              // [64][132]
    float* Cs = smg + 64*132;
    int z = blockIdx.x;
    int c = z & 31, b = z >> 5;
    int tid = threadIdx.x;
    size_t t0 = (size_t)(b*L_SEQ + c*CS);
    for (int idx = tid; idx < 64*128; idx += 256) {
        int l = idx >> 7, n = idx & 127;
        Bs[l*132 + n] = g_xc[(t0 + l)*CONV_DIM + D_INNER + n];
        Cs[l*132 + n] = g_xc[(t0 + l)*CONV_DIM + D_INNER + NDIM + n];
    }
    __syncthreads();
    int l = tid >> 2, sb = tid & 3;
    float acc[16];
#pragma unroll
    for (int i = 0; i < 16; i++) acc[i] = 0.f;
    for (int k = 0; k < 128; k++) {
        float cl = Cs[l*132 + k];
#pragma unroll
        for (int i = 0; i < 16; i++)
            acc[i] += cl * Bs[(sb*16 + i)*132 + k];
    }
    float* gout = g_Gt + (size_t)(b*NC + c)*CS*CS + l*CS + sb*16;
#pragma unroll
    for (int i = 0; i < 16; i++) gout[i] = acc[i];
}

// ---------------- fused chunk forward: Y_diag (+D*x) and states ------------
__global__ __launch_bounds__(256) void chunk_fwd_kernel(const float* __restrict__ Dp)
{
    extern __shared__ float smc[];
    float* XdtT = smc;             // [64][68]
    float* W    = smc + 64*68;     // [64][68]
    float* BT   = smc + 2*64*68;   // [128][68]
    float* Acs  = smc + 2*64*68 + 128*68;
    float* dts  = Acs + 64;
    float* dec  = dts + 64;

    int z = blockIdx.x;
    int h = z & 63, c = (z >> 6) & 31, b = z >> 11;
    int tid = threadIdx.x;
    size_t t0 = (size_t)(b*L_SEQ + c*CS);

    if (tid < 64) {
        Acs[tid] = g_Acum[((size_t)((b*NH + h)*NC + c))*CS + tid];
        dts[tid] = g_dtsp[(t0 + tid)*NH + h];
    }
    __syncthreads();
    if (tid < 64) dec[tid] = __expf(Acs[63] - Acs[tid]);

    {
        int p = tid & 63, lg = tid >> 6;
#pragma unroll
        for (int i = 0; i < 16; i++) {
            int l = lg*16 + i;
            float v = g_xc[(t0 + l)*CONV_DIM + h*64 + p] * dts[l];
            XdtT[p*68 + l] = f2tf(v);
        }
    }
    {
        int l = tid >> 2, sb = tid & 3;
        const float* grow = g_Gt + (size_t)(b*NC + c)*CS*CS + l*CS;
        float al = Acs[l];
        float dg = Dp[h] / fmaxf(dts[l], 1e-30f);
#pragma unroll
        for (int i = 0; i < 16; i++) {
            int s = sb*16 + i;
            float wv;
            if (s < l)       wv = f2tf(grow[s] * __expf(al - Acs[s]));
            else if (s == l) wv = f2tf(grow[s] + dg);
            else             wv = 0.f;
            W[l*68 + s] = wv;
        }
    }
    __syncthreads();
    {
        int n = tid & 127, lg = tid >> 7;
#pragma unroll
        for (int i = 0; i < 32; i++) {
            int l = lg*32 + i;
            float v = g_xc[(t0 + l)*CONV_DIM + D_INNER + n] * dec[l];
            BT[n*68 + l] = f2tf(v);
        }
    }
    __syncthreads();

    int warp = tid >> 5, lane = tid & 31;
    int g = lane >> 2, tg = lane & 3;

    {
        int wm = (warp & 3) * 16, wn = (warp >> 2) * 32;
        float acc[4][4];
#pragma unroll
        for (int ni = 0; ni < 4; ni++)
#pragma unroll
            for (int j = 0; j < 4; j++) acc[ni][j] = 0.f;
#pragma unroll
        for (int ks = 0; ks < 8; ks++) {
            int k0 = ks*8 + tg;
            unsigned a[4];
            a[0] = __float_as_uint(W[(wm + g    )*68 + k0    ]);
            a[1] = __float_as_uint(W[(wm + g + 8)*68 + k0    ]);
            a[2] = __float_as_uint(W[(wm + g    )*68 + k0 + 4]);
            a[3] = __float_as_uint(W[(wm + g + 8)*68 + k0 + 4]);
#pragma unroll
            for (int ni = 0; ni < 4; ni++) {
                unsigned bb[2];
                bb[0] = __float_as_uint(XdtT[(wn + ni*8 + g)*68 + k0    ]);
                bb[1] = __float_as_uint(XdtT[(wn + ni*8 + g)*68 + k0 + 4]);
                mma_tf32(acc[ni], a, bb);
            }
        }
        int r0 = wm + g, r1 = wm + g + 8;
#pragma unroll
        for (int ni = 0; ni < 4; ni++) {
            int col = wn + ni*8 + 2*tg;
            *(float2*)(g_y + (t0 + r0)*D_INNER + h*64 + col) =
                make_float2(acc[ni][0], acc[ni][1]);
            *(float2*)(g_y + (t0 + r1)*D_INNER + h*64 + col) =
                make_float2(acc[ni][2], acc[ni][3]);
        }
    }

    {
        int wm = (warp & 3) * 16, wn = (warp >> 2) * 64;
        float acc[8][4];
#pragma unroll
        for (int ni = 0; ni < 8; ni++)
#pragma unroll
            for (int j = 0; j < 4; j++) acc[ni][j] = 0.f;
#pragma unroll
        for (int ks = 0; ks < 8; ks++) {
            int k0 = ks*8 + tg;
            unsigned a[4];
            a[0] = __float_as_uint(XdtT[(wm + g    )*68 + k0    ]);
            a[1] = __float_as_uint(XdtT[(wm + g + 8)*68 + k0    ]);
            a[2] = __float_as_uint(XdtT[(wm + g    )*68 + k0 + 4]);
            a[3] = __float_as_uint(XdtT[(wm + g + 8)*68 + k0 + 4]);
#pragma unroll
            for (int ni = 0; ni < 8; ni++) {
                unsigned bb[2];
                bb[0] = __float_as_uint(BT[(wn + ni*8 + g)*68 + k0    ]);
                bb[1] = __float_as_uint(BT[(wn + ni*8 + g)*68 + k0 + 4]);
                mma_tf32(acc[ni], a, bb);
            }
        }
        float* sb = g_states + ((size_t)((b*NC + c)*NH + h))*PDIM*NDIM;
        int r0 = wm + g, r1 = wm + g + 8;
#pragma unroll
        for (int ni = 0; ni < 8; ni++) {
            int col = wn + ni*8 + 2*tg;
            *(float2*)(sb + (size_t)r0*NDIM + col) = make_float2(acc[ni][0], acc[ni][1]);
            *(float2*)(sb + (size_t)r1*NDIM + col) = make_float2(acc[ni][2], acc[ni][3]);
        }
    }
}

// ---------------- inter-chunk scan ------------------------------------------
__global__ __launch_bounds__(256) void scan_kernel()
{
    int idx = blockIdx.x * 256 + threadIdx.x;
    int n = idx & 127;
    int p = (idx >> 7) & 63;
    int h = (idx >> 13) & 63;
    int b = idx >> 19;
    float carry = 0.f;
    for (int c = 0; c < NC; c++) {
        size_t off = ((size_t)((b*NC + c)*NH + h))*PDIM*NDIM + (size_t)p*NDIM + n;
        float dal = g_Acum[((size_t)((b*NH + h)*NC + c))*CS + (CS-1)];
        float s = g_states[off];
        g_prev[off] = carry;
        carry = carry * __expf(dal) + s;
    }
}

// ---------------- inter-chunk contribution (fp32 SIMT) ---------------------
__global__ __launch_bounds__(256) void yoff_kernel()
{
    extern __shared__ float smo[];
    float* prevT = smo;             // [128][68]
    float* Cs    = smo + 128*68;    // [64][132]
    float* Acs   = smo + 128*68 + 64*132;
    int z = blockIdx.x;
    int h = z & 63, c = (z >> 6) & 31, b = z >> 11;
    int tid = threadIdx.x;
    size_t t0 = (size_t)(b*L_SEQ + c*CS);

    if (tid < 64) Acs[tid] = g_Acum[((size_t)((b*NH + h)*NC + c))*CS + tid];
    {
        int n = tid & 127, pg = tid >> 7;
        const float* pb = g_prev + ((size_t)((b*NC + c)*NH + h))*PDIM*NDIM;
#pragma unroll
        for (int i = 0; i < 32; i++) {
            int p = pg*32 + i;
            prevT[n*68 + p] = pb[(size_t)p*NDIM + n];
        }
    }
    {
        int n = tid & 127, lg = tid >> 7;
#pragma unroll
        for (int i = 0; i < 32; i++) {
            int l = lg*32 + i;
            Cs[l*132 + n] = g_xc[(t0 + l)*CONV_DIM + D_INNER + NDIM + n];
        }
    }
    __syncthreads();

    int l = tid >> 2, q = tid & 3;
    float4 acc[4];
#pragma unroll
    for (int j = 0; j < 4; j++) acc[j] = make_float4(0.f,0.f,0.f,0.f);
    for (int n = 0; n < 128; n++) {
        float cval = Cs[l*132 + n];
        const float4* pr = (const float4*)(prevT + n*68 + q*16);
#pragma unroll
        for (int j = 0; j < 4; j++) {
            float4 v = pr[j];
            acc[j].x += cval*v.x; acc[j].y += cval*v.y;
            acc[j].z += cval*v.z; acc[j].w += cval*v.w;
        }
    }
    float e = __expf(Acs[l]);
    float* yrow = g_y + (t0 + l)*D_INNER + h*64 + q*16;
#pragma unroll
    for (int j = 0; j < 4; j++) {
        float4 v = *(float4*)(yrow + j*4);
        v.x += e*acc[j].x; v.y += e*acc[j].y; v.z += e*acc[j].z; v.w += e*acc[j].w;
        *(float4*)(yrow + j*4) = v;
    }
}

// ---------------- gated RMSNorm (writes tf32-rounded output) ---------------
__global__ __launch_bounds__(256) void norm_kernel(const float* __restrict__ norm_w)
{
    __shared__ float gs[D_INNER];
    __shared__ float red[8];
    int t = blockIdx.x;
    int tid = threadIdx.x;
    const float* zrow = g_proj + (size_t)t * PROJ;
    float* yrow = g_y + (size_t)t * D_INNER;
    float sum = 0.f;
    for (int i = tid; i < D_INNER; i += 256) {
        float zv = zrow[i];
        float g = yrow[i] * (zv / (1.f + __expf(-zv)));
        gs[i] = g;
        sum += g*g;
    }
#pragma unroll
    for (int o = 16; o; o >>= 1) sum += __shfl_xor_sync(0xffffffffu, sum, o);
    if ((tid & 31) == 0) red[tid >> 5] = sum;
    __syncthreads();
    if (tid < 8) {
        float v = red[tid];
#pragma unroll
        for (int o = 4; o; o >>= 1) v += __shfl_xor_sync(0xffu, v, o);
        if (tid == 0) red[0] = v;
    }
    __syncthreads();
    float r = rsqrtf(red[0] / (float)D_INNER + 1e-5f);
    for (int i = tid; i < D_INNER; i += 256) yrow[i] = f2tf(gs[i] * r * norm_w[i]);
}

// ---------------- launch ---------------------------------------------------
extern "C" void kernel_launch(void* const* d_in, const int* in_sizes, int n_in,
                              void* d_out, int out_size)
{
    const float* hs      = (const float*)d_in[0];
    const float* W_in    = (const float*)d_in[1];
    const float* conv_w  = (const float*)d_in[2];
    const float* conv_b  = (const float*)d_in[3];
    const float* dt_bias = (const float*)d_in[4];
    const float* A_log   = (const float*)d_in[5];
    const float* Dp      = (const float*)d_in[6];
    const float* norm_w  = (const float*)d_in[7];
    const float* W_out   = (const float*)d_in[8];
    float* out = (float*)d_out;

    float *proj, *y, *hsr, *Wir, *Wor;
    cudaGetSymbolAddress((void**)&proj, g_proj);
    cudaGetSymbolAddress((void**)&y,    g_y);
    cudaGetSymbolAddress((void**)&hsr,  g_hsr);
    cudaGetSymbolAddress((void**)&Wir,  g_Wir);
    cudaGetSymbolAddress((void**)&Wor,  g_Wor);

    const int gemmsm  = STAGES * 2 * SSTRIDE * (int)sizeof(float);          // 98,304 B
    const int gtsm    = 2 * 64 * 132 * (int)sizeof(float);
    const int chunksm = (2*64*68 + 128*68 + 3*64) * (int)sizeof(float);
    const int yoffsm  = (128*68 + 64*132 + 64) * (int)sizeof(float);
    cudaFuncSetAttribute(gemm_tf32_pipe,   cudaFuncAttributeMaxDynamicSharedMemorySize, gemmsm);
    cudaFuncSetAttribute(gt_kernel,        cudaFuncAttributeMaxDynamicSharedMemorySize, gtsm);
    cudaFuncSetAttribute(chunk_fwd_kernel, cudaFuncAttributeMaxDynamicSharedMemorySize, chunksm);
    cudaFuncSetAttribute(yoff_kernel,      cudaFuncAttributeMaxDynamicSharedMemorySize, yoffsm);

    const int M = NBATCH * L_SEQ;   // 4096 tokens
    const int NBLK = 296;           // 2 per SM x 148 SMs (persistent)

    // 0) pre-round operands to tf32
    {
        int n1 = M * HIDDEN;
        round_kernel<<<(n1 + 255)/256, 256>>>(hs, hsr, n1);
        int n2 = PROJ_PAD * HIDDEN;
        round_pad_kernel<<<(n2 + 255)/256, 256>>>(W_in, Wir, PROJ, PROJ_PAD, HIDDEN);
        int n3 = HIDDEN * D_INNER;
        round_kernel<<<(n3 + 255)/256, 256>>>(W_out, Wor, n3);
    }

    // 1) in-proj (persistent tf32 mma GEMM)
    gemm_tf32_pipe<<<NBLK, GEMM_THREADS, gemmsm>>>(
        hsr, Wir, proj, M, PROJ, HIDDEN, HIDDEN, HIDDEN, PROJ);

    // 2) causal conv + SiLU
    conv_silu_kernel<<<(NBATCH*L_SEQ*CONV_DIM)/256, 256>>>(conv_w, conv_b);

    // 3) dt softplus + per-64-chunk cumsum
    dtscan_kernel<<<NBATCH*NH*8, 256>>>(dt_bias, A_log);

    // 4) G[l][s] = C[l]·B[s] per (b,chunk)
    gt_kernel<<<NBATCH*NC, 256, gtsm>>>();

    // 5) fused Y_diag (+D*x) and per-chunk states
    chunk_fwd_kernel<<<NBATCH*NC*NH, 256, chunksm>>>(Dp);

    // 6) inter-chunk scan
    scan_kernel<<<(NBATCH*NH*PDIM*NDIM)/256, 256>>>();

    // 7) inter-chunk contribution
    yoff_kernel<<<NBATCH*NC*NH, 256, yoffsm>>>();

    // 8) gated RMSNorm (emits tf32-rounded y)
    norm_kernel<<<M, 256>>>(norm_w);

    // 9) out-proj (persistent tf32 mma GEMM)
    gemm_tf32_pipe<<<NBLK, GEMM_THREADS, gemmsm>>>(
        y, Wor, out, M, HIDDEN, D_INNER, D_INNER, D_INNER, HIDDEN);
}

// round 9
// speedup vs baseline: 3.9378x; 1.2459x over previous
#include <cuda_runtime.h>
#include <math.h>
#include <stdint.h>

#define L_SEQ   2048
#define NBATCH  2
#define HIDDEN  2048
#define NH      64
#define PDIM    64
#define NDIM    128
#define CS      64
#define NC      32
#define D_INNER 4096
#define CONV_DIM 4352
#define PROJ    8512
#define PROJ_PAD 8576   // 67 * 128

// ---------------- scratch (device globals: allocation-free) ----------------
__device__ float g_proj  [NBATCH*L_SEQ*PROJ];
__device__ float g_xc    [NBATCH*L_SEQ*CONV_DIM];
__device__ float g_dtsp  [NBATCH*L_SEQ*NH];
__device__ float g_Acum  [NBATCH*NH*NC*CS];
__device__ float g_Gt    [NBATCH*NC*CS*CS];
__device__ float g_states[NBATCH*NC*NH*PDIM*NDIM];
__device__ float g_prev  [NBATCH*NC*NH*PDIM*NDIM];
__device__ float g_y     [NBATCH*L_SEQ*D_INNER];
__device__ float g_hsr   [NBATCH*L_SEQ*HIDDEN];
__device__ float g_Wir   [PROJ_PAD*HIDDEN];
__device__ float g_Wor   [HIDDEN*D_INNER];

// ---------------- tf32 helpers --------------------------------------------
__device__ __forceinline__ float f2tf(float f) {
    unsigned r;
    asm("cvt.rna.tf32.f32 %0, %1;" : "=r"(r) : "f"(f));
    return __uint_as_float(r);
}

__device__ __forceinline__ void mma_tf32(
    float* c, const unsigned* a, const unsigned* b)
{
    asm volatile(
        "mma.sync.aligned.m16n8k8.row.col.f32.tf32.tf32.f32 "
        "{%0,%1,%2,%3}, {%4,%5,%6,%7}, {%8,%9}, {%0,%1,%2,%3};"
        : "+f"(c[0]), "+f"(c[1]), "+f"(c[2]), "+f"(c[3])
        : "r"(a[0]), "r"(a[1]), "r"(a[2]), "r"(a[3]),
          "r"(b[0]), "r"(b[1]));
}

__device__ __forceinline__ void ldsm4(unsigned* r, uint32_t addr) {
    asm volatile(
        "ldmatrix.sync.aligned.m8n8.x4.shared.b16 {%0,%1,%2,%3}, [%4];"
        : "=r"(r[0]), "=r"(r[1]), "=r"(r[2]), "=r"(r[3]) : "r"(addr));
}

__device__ __forceinline__ void cp16(unsigned smem, const float* g) {
    asm volatile("cp.async.cg.shared.global [%0], [%1], 16;\n" :: "r"(smem), "l"(g));
}
__device__ __forceinline__ void cp_commit() {
    asm volatile("cp.async.commit_group;\n");
}
template<int N> __device__ __forceinline__ void cp_wait() {
    asm volatile("cp.async.wait_group %0;\n" :: "n"(N));
}

// ---------------- pre-round kernels ----------------------------------------
__global__ __launch_bounds__(256) void round_kernel(
    const float* __restrict__ src, float* __restrict__ dst, int n)
{
    int i = blockIdx.x * 256 + threadIdx.x;
    if (i < n) dst[i] = f2tf(src[i]);
}
__global__ __launch_bounds__(256) void round_pad_kernel(
    const float* __restrict__ src, float* __restrict__ dst, int rows, int rows_pad, int cols)
{
    int i = blockIdx.x * 256 + threadIdx.x;
    if (i < rows_pad * cols) {
        int r = i / cols;
        dst[i] = (r < rows) ? f2tf(src[i]) : 0.f;
    }
}

// ---------------- persistent pipelined tf32 NT GEMM -------------------------
// C[m,n] = sum_k A[m,k]*B[n,k].  BM=BN=128, BK=32, 3-stage cp.async,
// 4 warps (128 thr), warp tile 64x64, ONE barrier per k-tile.
#define STAGES 3
#define SSTRIDE (128*32)
#define GEMM_THREADS 128
__global__ __launch_bounds__(GEMM_THREADS, 2) void gemm_tf32_pipe(
    const float* __restrict__ A, const float* __restrict__ B, float* __restrict__ C,
    int M, int N, int K, int lda, int ldb, int ldc)
{
    extern __shared__ float sm[];
    float* As = sm;                        // [STAGES][128][32] swizzled
    float* Bs = sm + STAGES * SSTRIDE;
    int tid = threadIdx.x;
    int warp = tid >> 5, lane = tid & 31;
    int g = lane >> 2, tg = lane & 3;
    int wm = (warp & 1) * 64, wn = (warp >> 1) * 64;

    int grp = lane >> 3, rin = lane & 7;
    int rowA = (grp & 1) * 8 + rin;
    int bitA = grp >> 1;
    int rowB = (grp >> 1) * 8 + rin;
    int bitB = grp & 1;

    unsigned asBase = (unsigned)__cvta_generic_to_shared(As);
    unsigned bsBase = (unsigned)__cvta_generic_to_shared(Bs);

    const int KT = K >> 5;
    const int ntn = (N + 127) >> 7;
    const int ntiles = (M >> 7) * ntn;

    for (int tile = blockIdx.x; tile < ntiles; tile += gridDim.x) {
        int bm = (tile / ntn) * 128;
        int bn = (tile % ntn) * 128;

        float acc[4][8][4];
#pragma unroll
        for (int mi = 0; mi < 4; mi++)
#pragma unroll
            for (int ni = 0; ni < 8; ni++)
#pragma unroll
                for (int j = 0; j < 4; j++) acc[mi][ni][j] = 0.f;

        auto issue_stage = [&](int stage, int kt) {
            int kk = kt << 5;
            unsigned aS = asBase + (unsigned)(stage * SSTRIDE) * 4u;
            unsigned bS = bsBase + (unsigned)(stage * SSTRIDE) * 4u;
#pragma unroll
            for (int i = 0; i < 8; i++) {
                int id = tid + i * GEMM_THREADS;
                int row = id >> 3, c16 = id & 7;
                int pc = c16 ^ (row & 7);
                unsigned off = (unsigned)(row * 32 + pc * 4) * 4u;
                cp16(aS + off, A + (size_t)(bm + row) * lda + kk + c16 * 4);
                cp16(bS + off, B + (size_t)(bn + row) * ldb + kk + c16 * 4);
            }
            cp_commit();
        };

        issue_stage(0, 0);
        if (KT > 1) issue_stage(1, 1);

        for (int kt = 0; kt < KT; kt++) {
            if (kt < KT - 1) cp_wait<1>(); else cp_wait<0>();
            __syncthreads();    // single barrier per k-tile
            if (kt + 2 < KT) issue_stage((kt + 2) % STAGES, kt + 2);

            unsigned aS = asBase + (unsigned)((kt % STAGES) * SSTRIDE) * 4u;
            unsigned bS = bsBase + (unsigned)((kt % STAGES) * SSTRIDE) * 4u;
#pragma unroll
            for (int ks = 0; ks < 4; ks++) {
                unsigned af[4][4], bf[4][4];
#pragma unroll
                for (int mi = 0; mi < 4; mi++) {
                    unsigned addr = aS
                        + (unsigned)((wm + mi * 16 + rowA) * 128)
                        + (unsigned)((((2*ks + bitA) ^ rin) & 7) << 4);
                    ldsm4(af[mi], addr);
                }
#pragma unroll
                for (int np = 0; np < 4; np++) {
                    unsigned addr = bS
                        + (unsigned)((wn + np * 16 + rowB) * 128)
                        + (unsigned)((((2*ks + bitB) ^ rin) & 7) << 4);
                    ldsm4(bf[np], addr);
                }
#pragma unroll
                for (int mi = 0; mi < 4; mi++) {
#pragma unroll
                    for (int np = 0; np < 4; np++) {
                        mma_tf32(acc[mi][np*2    ], af[mi], &bf[np][0]);
                        mma_tf32(acc[mi][np*2 + 1], af[mi], &bf[np][2]);
                    }
                }
            }
        }

#pragma unroll
        for (int mi = 0; mi < 4; mi++) {
            int row0 = bm + wm + mi * 16 + g;
#pragma unroll
            for (int ni = 0; ni < 8; ni++) {
                int col = bn + wn + ni * 8 + 2 * tg;
                if (col < N) {
                    *(float2*)(C + (size_t)row0 * ldc + col) =
                        make_float2(acc[mi][ni][0], acc[mi][ni][1]);
                    *(float2*)(C + (size_t)(row0 + 8) * ldc + col) =
                        make_float2(acc[mi][ni][2], acc[mi][ni][3]);
                }
            }
        }
        __syncthreads();   // protect stage 0 before next tile's prologue
    }
}

// ---------------- causal depthwise conv (K=4) + bias + SiLU ----------------
__global__ __launch_bounds__(256) void conv_silu_kernel(
    const float* __restrict__ cw, const float* __restrict__ cb)
{
    int idx = blockIdx.x * 256 + threadIdx.x;
    int c = idx % CONV_DIM;
    int t = idx / CONV_DIM;
    int l = t % L_SEQ, b = t / L_SEQ;
    float acc = cb[c];
#pragma unroll
    for (int k = 0; k < 4; k++) {
        int ll = l - 3 + k;
        if (ll >= 0)
            acc += g_proj[((size_t)(b*L_SEQ + ll))*PROJ + D_INNER + c] * cw[c*4 + k];
    }
    acc = acc / (1.f + __expf(-acc));
    g_xc[(size_t)t*CONV_DIM + c] = acc;
}

// ------- dt softplus + per-64-chunk inclusive cumsum of dt*A ---------------
__global__ __launch_bounds__(256) void dtscan_kernel(
    const float* __restrict__ dt_bias, const float* __restrict__ A_log)
{
    __shared__ float s[256];
    int z = blockIdx.x;
    int q = z & 7, h = (z >> 3) & 63, b = z >> 9;
    int t = threadIdx.x;
    int gl = q*256 + t;
    float raw = g_proj[((size_t)(b*L_SEQ + gl))*PROJ + D_INNER + CONV_DIM + h] + dt_bias[h];
    float dts = (raw > 20.f) ? raw : log1pf(__expf(raw));
    g_dtsp[(size_t)(b*L_SEQ + gl)*NH + h] = dts;
    s[t] = -dts * __expf(A_log[h]);
    __syncthreads();
    for (int off = 1; off < 64; off <<= 1) {
        float v = ((t & 63) >= off) ? s[t - off] : 0.f;
        __syncthreads();
        s[t] += v;
        __syncthreads();
    }
    int c = gl >> 6;
    g_Acum[((size_t)((b*NH + h)*NC + c))*CS + (gl & 63)] = s[t];
}

// ---------------- G[l][s] = C[l]·B[s] per (b,chunk), fp32 ------------------
__global__ __launch_bounds__(256) void gt_kernel()
{
    extern __shared__ float smg[];
    float* Bs = smg;              // [64][132]
    float* Cs = smg + 64*132;
    int z = blockIdx.x;
    int c = z & 31, b = z >> 5;
    int tid = threadIdx.x;
    size_t t0 = (size_t)(b*L_SEQ + c*CS);
    for (int idx = tid; idx < 64*128; idx += 256) {
        int l = idx >> 7, n = idx & 127;
        Bs[l*132 + n] = g_xc[(t0 + l)*CONV_DIM + D_INNER + n];
        Cs[l*132 + n] = g_xc[(t0 + l)*CONV_DIM + D_INNER + NDIM + n];
    }
    __syncthreads();
    int l = tid >> 2, sb = tid & 3;
    float acc[16];
#pragma unroll
    for (int i = 0; i < 16; i++) acc[i] = 0.f;
    for (int k = 0; k < 128; k++) {
        float cl = Cs[l*132 + k];
#pragma unroll
        for (int i = 0; i < 16; i++)
            acc[i] += cl * Bs[(sb*16 + i)*132 + k];
    }
    float* gout = g_Gt + (size_t)(b*NC + c)*CS*CS + l*CS + sb*16;
#pragma unroll
    for (int i = 0; i < 16; i++) gout[i] = acc[i];
}

// ---------------- fused chunk forward: Y_diag (+D*x) and states ------------
__global__ __launch_bounds__(256) void chunk_fwd_kernel(const float* __restrict__ Dp)
{
    extern __shared__ float smc[];
    float* XdtT = smc;             // [64][68]
    float* W    = smc + 64*68;     // [64][68]
    float* BT   = smc + 2*64*68;   // [128][68]
    float* Acs  = smc + 2*64*68 + 128*68;
    float* dts  = Acs + 64;
    float* dec  = dts + 64;

    int z = blockIdx.x;
    int h = z & 63, c = (z >> 6) & 31, b = z >> 11;
    int tid = threadIdx.x;
    size_t t0 = (size_t)(b*L_SEQ + c*CS);

    if (tid < 64) {
        Acs[tid] = g_Acum[((size_t)((b*NH + h)*NC + c))*CS + tid];
        dts[tid] = g_dtsp[(t0 + tid)*NH + h];
    }
    __syncthreads();
    if (tid < 64) dec[tid] = __expf(Acs[63] - Acs[tid]);

    {
        int p = tid & 63, lg = tid >> 6;
#pragma unroll
        for (int i = 0; i < 16; i++) {
            int l = lg*16 + i;
            float v = g_xc[(t0 + l)*CONV_DIM + h*64 + p] * dts[l];
            XdtT[p*68 + l] = f2tf(v);
        }
    }
    {
        int l = tid >> 2, sb = tid & 3;
        const float* grow = g_Gt + (size_t)(b*NC + c)*CS*CS + l*CS;
        float al = Acs[l];
        float dg = Dp[h] / fmaxf(dts[l], 1e-30f);
#pragma unroll
        for (int i = 0; i < 16; i++) {
            int s = sb*16 + i;
            float wv;
            if (s < l)       wv = f2tf(grow[s] * __expf(al - Acs[s]));
            else if (s == l) wv = f2tf(grow[s] + dg);
            else             wv = 0.f;
            W[l*68 + s] = wv;
        }
    }
    __syncthreads();
    {
        int n = tid & 127, lg = tid >> 7;
#pragma unroll
        for (int i = 0; i < 32; i++) {
            int l = lg*32 + i;
            float v = g_xc[(t0 + l)*CONV_DIM + D_INNER + n] * dec[l];
            BT[n*68 + l] = f2tf(v);
        }
    }
    __syncthreads();

    int warp = tid >> 5, lane = tid & 31;
    int g = lane >> 2, tg = lane & 3;

    {
        int wm = (warp & 3) * 16, wn = (warp >> 2) * 32;
        float acc[4][4];
#pragma unroll
        for (int ni = 0; ni < 4; ni++)
#pragma unroll
            for (int j = 0; j < 4; j++) acc[ni][j] = 0.f;
#pragma unroll
        for (int ks = 0; ks < 8; ks++) {
            int k0 = ks*8 + tg;
            unsigned a[4];
            a[0] = __float_as_uint(W[(wm + g    )*68 + k0    ]);
            a[1] = __float_as_uint(W[(wm + g + 8)*68 + k0    ]);
            a[2] = __float_as_uint(W[(wm + g    )*68 + k0 + 4]);
            a[3] = __float_as_uint(W[(wm + g + 8)*68 + k0 + 4]);
#pragma unroll
            for (int ni = 0; ni < 4; ni++) {
                unsigned bb[2];
                bb[0] = __float_as_uint(XdtT[(wn + ni*8 + g)*68 + k0    ]);
                bb[1] = __float_as_uint(XdtT[(wn + ni*8 + g)*68 + k0 + 4]);
                mma_tf32(acc[ni], a, bb);
            }
        }
        int r0 = wm + g, r1 = wm + g + 8;
#pragma unroll
        for (int ni = 0; ni < 4; ni++) {
            int col = wn + ni*8 + 2*tg;
            *(float2*)(g_y + (t0 + r0)*D_INNER + h*64 + col) =
                make_float2(acc[ni][0], acc[ni][1]);
            *(float2*)(g_y + (t0 + r1)*D_INNER + h*64 + col) =
                make_float2(acc[ni][2], acc[ni][3]);
        }
    }

    {
        int wm = (warp & 3) * 16, wn = (warp >> 2) * 64;
        float acc[8][4];
#pragma unroll
        for (int ni = 0; ni < 8; ni++)
#pragma unroll
            for (int j = 0; j < 4; j++) acc[ni][j] = 0.f;
#pragma unroll
        for (int ks = 0; ks < 8; ks++) {
            int k0 = ks*8 + tg;
            unsigned a[4];
            a[0] = __float_as_uint(XdtT[(wm + g    )*68 + k0    ]);
            a[1] = __float_as_uint(XdtT[(wm + g + 8)*68 + k0    ]);
            a[2] = __float_as_uint(XdtT[(wm + g    )*68 + k0 + 4]);
            a[3] = __float_as_uint(XdtT[(wm + g + 8)*68 + k0 + 4]);
#pragma unroll
            for (int ni = 0; ni < 8; ni++) {
                unsigned bb[2];
                bb[0] = __float_as_uint(BT[(wn + ni*8 + g)*68 + k0    ]);
                bb[1] = __float_as_uint(BT[(wn + ni*8 + g)*68 + k0 + 4]);
                mma_tf32(acc[ni], a, bb);
            }
        }
        float* sb = g_states + ((size_t)((b*NC + c)*NH + h))*PDIM*NDIM;
        int r0 = wm + g, r1 = wm + g + 8;
#pragma unroll
        for (int ni = 0; ni < 8; ni++) {
            int col = wn + ni*8 + 2*tg;
            *(float2*)(sb + (size_t)r0*NDIM + col) = make_float2(acc[ni][0], acc[ni][1]);
            *(float2*)(sb + (size_t)r1*NDIM + col) = make_float2(acc[ni][2], acc[ni][3]);
        }
    }
}

// ---------------- inter-chunk scan ------------------------------------------
__global__ __launch_bounds__(256) void scan_kernel()
{
    int idx = blockIdx.x * 256 + threadIdx.x;
    int n = idx & 127;
    int p = (idx >> 7) & 63;
    int h = (idx >> 13) & 63;
    int b = idx >> 19;
    float carry = 0.f;
    for (int c = 0; c < NC; c++) {
        size_t off = ((size_t)((b*NC + c)*NH + h))*PDIM*NDIM + (size_t)p*NDIM + n;
        float dal = g_Acum[((size_t)((b*NH + h)*NC + c))*CS + (CS-1)];
        float s = g_states[off];
        g_prev[off] = carry;
        carry = carry * __expf(dal) + s;
    }
}

// ---------------- inter-chunk contribution (tf32 mma) -----------------------
// Y_off[l,p] = exp(Acum[l]) * sum_n C[l,n]*prev[p,n];  M=64(l) N=64(p) K=128(n)
__global__ __launch_bounds__(256) void yoff_kernel()
{
    extern __shared__ float smo[];
    float* Cs  = smo;             // [64][132] tf32, n fast
    float* Pv  = smo + 64*132;    // [64][132] prev[p][n] tf32
    float* Acs = smo + 2*64*132;  // [64]
    int z = blockIdx.x;
    int h = z & 63, c = (z >> 6) & 31, b = z >> 11;
    int tid = threadIdx.x;
    size_t t0 = (size_t)(b*L_SEQ + c*CS);

    if (tid < 64) Acs[tid] = g_Acum[((size_t)((b*NH + h)*NC + c))*CS + tid];
    {
        int n = tid & 127, rg = tid >> 7;
        const float* pb = g_prev + ((size_t)((b*NC + c)*NH + h))*PDIM*NDIM;
#pragma unroll
        for (int i = 0; i < 32; i++) {
            int row = rg*32 + i;
            Cs[row*132 + n] = f2tf(g_xc[(t0 + row)*CONV_DIM + D_INNER + NDIM + n]);
            Pv[row*132 + n] = f2tf(pb[(size_t)row*NDIM + n]);
        }
    }
    __syncthreads();

    int warp = tid >> 5, lane = tid & 31;
    int g = lane >> 2, tg = lane & 3;
    int wm = (warp & 3) * 16;     // l block
    int wn = (warp >> 2) * 32;    // p block

    float acc[4][4];
#pragma unroll
    for (int ni = 0; ni < 4; ni++)
#pragma unroll
        for (int j = 0; j < 4; j++) acc[ni][j] = 0.f;

#pragma unroll
    for (int ks = 0; ks < 16; ks++) {
        int k0 = ks*8 + tg;
        unsigned a[4];
        a[0] = __float_as_uint(Cs[(wm + g    )*132 + k0    ]);
        a[1] = __float_as_uint(Cs[(wm + g + 8)*132 + k0    ]);
        a[2] = __float_as_uint(Cs[(wm + g    )*132 + k0 + 4]);
        a[3] = __float_as_uint(Cs[(wm + g + 8)*132 + k0 + 4]);
#pragma unroll
        for (int ni = 0; ni < 4; ni++) {
            unsigned bb[2];
            bb[0] = __float_as_uint(Pv[(wn + ni*8 + g)*132 + k0    ]);
            bb[1] = __float_as_uint(Pv[(wn + ni*8 + g)*132 + k0 + 4]);
            mma_tf32(acc[ni], a, bb);
        }
    }

    float e0 = __expf(Acs[wm + g]);
    float e1 = __expf(Acs[wm + g + 8]);
#pragma unroll
    for (int ni = 0; ni < 4; ni++) {
        int col = wn + ni*8 + 2*tg;
        float* y0 = g_y + (t0 + wm + g)*D_INNER + h*64 + col;
        float* y1 = g_y + (t0 + wm + g + 8)*D_INNER + h*64 + col;
        float2 v0 = *(float2*)y0;
        float2 v1 = *(float2*)y1;
        v0.x += e0*acc[ni][0]; v0.y += e0*acc[ni][1];
        v1.x += e1*acc[ni][2]; v1.y += e1*acc[ni][3];
        *(float2*)y0 = v0;
        *(float2*)y1 = v1;
    }
}

// ---------------- gated RMSNorm (writes tf32-rounded output) ---------------
__global__ __launch_bounds__(256) void norm_kernel(const float* __restrict__ norm_w)
{
    __shared__ float gs[D_INNER];
    __shared__ float red[8];
    int t = blockIdx.x;
    int tid = threadIdx.x;
    const float* zrow = g_proj + (size_t)t * PROJ;
    float* yrow = g_y + (size_t)t * D_INNER;
    float sum = 0.f;
    for (int i = tid; i < D_INNER; i += 256) {
        float zv = zrow[i];
        float g = yrow[i] * (zv / (1.f + __expf(-zv)));
        gs[i] = g;
        sum += g*g;
    }
#pragma unroll
    for (int o = 16; o; o >>= 1) sum += __shfl_xor_sync(0xffffffffu, sum, o);
    if ((tid & 31) == 0) red[tid >> 5] = sum;
    __syncthreads();
    if (tid < 8) {
        float v = red[tid];
#pragma unroll
        for (int o = 4; o; o >>= 1) v += __shfl_xor_sync(0xffu, v, o);
        if (tid == 0) red[0] = v;
    }
    __syncthreads();
    float r = rsqrtf(red[0] / (float)D_INNER + 1e-5f);
    for (int i = tid; i < D_INNER; i += 256) yrow[i] = f2tf(gs[i] * r * norm_w[i]);
}

// ---------------- launch ---------------------------------------------------
extern "C" void kernel_launch(void* const* d_in, const int* in_sizes, int n_in,
                              void* d_out, int out_size)
{
    const float* hs      = (const float*)d_in[0];
    const float* W_in    = (const float*)d_in[1];
    const float* conv_w  = (const float*)d_in[2];
    const float* conv_b  = (const float*)d_in[3];
    const float* dt_bias = (const float*)d_in[4];
    const float* A_log   = (const float*)d_in[5];
    const float* Dp      = (const float*)d_in[6];
    const float* norm_w  = (const float*)d_in[7];
    const float* W_out   = (const float*)d_in[8];
    float* out = (float*)d_out;

    float *proj, *y, *hsr, *Wir, *Wor;
    cudaGetSymbolAddress((void**)&proj, g_proj);
    cudaGetSymbolAddress((void**)&y,    g_y);
    cudaGetSymbolAddress((void**)&hsr,  g_hsr);
    cudaGetSymbolAddress((void**)&Wir,  g_Wir);
    cudaGetSymbolAddress((void**)&Wor,  g_Wor);

    const int gemmsm  = STAGES * 2 * SSTRIDE * (int)sizeof(float);          // 98,304 B
    const int gtsm    = 2 * 64 * 132 * (int)sizeof(float);
    const int chunksm = (2*64*68 + 128*68 + 3*64) * (int)sizeof(float);
    const int yoffsm  = (2*64*132 + 64) * (int)sizeof(float);               // 67,840 B
    cudaFuncSetAttribute(gemm_tf32_pipe,   cudaFuncAttributeMaxDynamicSharedMemorySize, gemmsm);
    cudaFuncSetAttribute(gt_kernel,        cudaFuncAttributeMaxDynamicSharedMemorySize, gtsm);
    cudaFuncSetAttribute(chunk_fwd_kernel, cudaFuncAttributeMaxDynamicSharedMemorySize, chunksm);
    cudaFuncSetAttribute(yoff_kernel,      cudaFuncAttributeMaxDynamicSharedMemorySize, yoffsm);

    const int M = NBATCH * L_SEQ;   // 4096 tokens
    const int NBLK = 296;           // persistent grid: 2 per SM x 148 SMs

    // 0) pre-round operands to tf32
    {
        int n1 = M * HIDDEN;
        round_kernel<<<(n1 + 255)/256, 256>>>(hs, hsr, n1);
        int n2 = PROJ_PAD * HIDDEN;
        round_pad_kernel<<<(n2 + 255)/256, 256>>>(W_in, Wir, PROJ, PROJ_PAD, HIDDEN);
        int n3 = HIDDEN * D_INNER;
        round_kernel<<<(n3 + 255)/256, 256>>>(W_out, Wor, n3);
    }

    // 1) in-proj
    gemm_tf32_pipe<<<NBLK, GEMM_THREADS, gemmsm>>>(
        hsr, Wir, proj, M, PROJ, HIDDEN, HIDDEN, HIDDEN, PROJ);

    // 2) causal conv + SiLU
    conv_silu_kernel<<<(NBATCH*L_SEQ*CONV_DIM)/256, 256>>>(conv_w, conv_b);

    // 3) dt softplus + per-64-chunk cumsum
    dtscan_kernel<<<NBATCH*NH*8, 256>>>(dt_bias, A_log);

    // 4) G[l][s] = C[l]·B[s] per (b,chunk)
    gt_kernel<<<NBATCH*NC, 256, gtsm>>>();

    // 5) fused Y_diag (+D*x) and per-chunk states
    chunk_fwd_kernel<<<NBATCH*NC*NH, 256, chunksm>>>(Dp);

    // 6) inter-chunk scan
    scan_kernel<<<(NBATCH*NH*PDIM*NDIM)/256, 256>>>();

    // 7) inter-chunk contribution (tf32 mma)
    yoff_kernel<<<NBATCH*NC*NH, 256, yoffsm>>>();

    // 8) gated RMSNorm (emits tf32-rounded y)
    norm_kernel<<<M, 256>>>(norm_w);

    // 9) out-proj
    gemm_tf32_pipe<<<NBLK, GEMM_THREADS, gemmsm>>>(
        y, Wor, out, M, HIDDEN, D_INNER, D_INNER, D_INNER, HIDDEN);
}

// round 10
// speedup vs baseline: 5.0774x; 1.2894x over previous
#include <cuda_runtime.h>
#include <cuda_fp16.h>
#include <math.h>
#include <stdint.h>

#define L_SEQ   2048
#define NBATCH  2
#define HIDDEN  2048
#define NH      64
#define PDIM    64
#define NDIM    128
#define CS      64
#define NC      32
#define D_INNER 4096
#define CONV_DIM 4352
#define PROJ    8512
#define PROJ_PAD 8576   // 67 * 128

// ---------------- scratch (device globals: allocation-free) ----------------
__device__ float g_proj  [NBATCH*L_SEQ*PROJ];
__device__ float g_xc    [NBATCH*L_SEQ*CONV_DIM];
__device__ float g_dtsp  [NBATCH*L_SEQ*NH];
__device__ float g_Acum  [NBATCH*NH*NC*CS];
__device__ float g_Gt    [NBATCH*NC*CS*CS];
__device__ float g_states[NBATCH*NC*NH*PDIM*NDIM];
__device__ float g_prev  [NBATCH*NC*NH*PDIM*NDIM];
__device__ float g_y     [NBATCH*L_SEQ*D_INNER];
// fp16 GEMM operands
__device__ __half g_hsh  [NBATCH*L_SEQ*HIDDEN];
__device__ __half g_Wih  [PROJ_PAD*HIDDEN];
__device__ __half g_Woh  [HIDDEN*D_INNER];
__device__ __half g_yh   [NBATCH*L_SEQ*D_INNER];

// ---------------- helpers ---------------------------------------------------
__device__ __forceinline__ float f2tf(float f) {
    unsigned r;
    asm("cvt.rna.tf32.f32 %0, %1;" : "=r"(r) : "f"(f));
    return __uint_as_float(r);
}

__device__ __forceinline__ void mma_tf32(
    float* c, const unsigned* a, const unsigned* b)
{
    asm volatile(
        "mma.sync.aligned.m16n8k8.row.col.f32.tf32.tf32.f32 "
        "{%0,%1,%2,%3}, {%4,%5,%6,%7}, {%8,%9}, {%0,%1,%2,%3};"
        : "+f"(c[0]), "+f"(c[1]), "+f"(c[2]), "+f"(c[3])
        : "r"(a[0]), "r"(a[1]), "r"(a[2]), "r"(a[3]),
          "r"(b[0]), "r"(b[1]));
}

__device__ __forceinline__ void mma_f16(
    float* c, const unsigned* a, unsigned b0, unsigned b1)
{
    asm volatile(
        "mma.sync.aligned.m16n8k16.row.col.f32.f16.f16.f32 "
        "{%0,%1,%2,%3}, {%4,%5,%6,%7}, {%8,%9}, {%0,%1,%2,%3};"
        : "+f"(c[0]), "+f"(c[1]), "+f"(c[2]), "+f"(c[3])
        : "r"(a[0]), "r"(a[1]), "r"(a[2]), "r"(a[3]),
          "r"(b0), "r"(b1));
}

__device__ __forceinline__ void ldsm4(unsigned* r, uint32_t addr) {
    asm volatile(
        "ldmatrix.sync.aligned.m8n8.x4.shared.b16 {%0,%1,%2,%3}, [%4];"
        : "=r"(r[0]), "=r"(r[1]), "=r"(r[2]), "=r"(r[3]) : "r"(addr));
}

__device__ __forceinline__ void cp16(unsigned smem, const void* g) {
    asm volatile("cp.async.cg.shared.global [%0], [%1], 16;\n" :: "r"(smem), "l"(g));
}
__device__ __forceinline__ void cp_commit() {
    asm volatile("cp.async.commit_group;\n");
}
template<int N> __device__ __forceinline__ void cp_wait() {
    asm volatile("cp.async.wait_group %0;\n" :: "n"(N));
}

// ---------------- convert kernels (fp32 -> fp16) ----------------------------
__global__ __launch_bounds__(256) void tohalf_kernel(
    const float* __restrict__ src, __half* __restrict__ dst, int n)
{
    int i = blockIdx.x * 256 + threadIdx.x;
    if (i < n) dst[i] = __float2half(src[i]);
}
__global__ __launch_bounds__(256) void tohalf_pad_kernel(
    const float* __restrict__ src, __half* __restrict__ dst, int rows, int rows_pad, int cols)
{
    int i = blockIdx.x * 256 + threadIdx.x;
    if (i < rows_pad * cols) {
        int r = i / cols;
        dst[i] = (r < rows) ? __float2half(src[i]) : __float2half(0.f);
    }
}

// ---------------- persistent pipelined fp16 NT GEMM -------------------------
// C[m,n] = sum_k A[m,k]*B[n,k], A/B fp16, C fp32.  BM=BN=128, BK=64 halves
// (128B rows), 3-stage cp.async, 4 warps, warp tile 64x64, 1 barrier/k-tile.
// Smem 16B chunks XOR-swizzled (chunk^(row&7)).
#define STAGES 3
#define SSTRIDE_H (128*64)         // halves per stage per operand
#define GEMM_THREADS 128
__global__ __launch_bounds__(GEMM_THREADS, 2) void gemm_f16_pipe(
    const __half* __restrict__ A, const __half* __restrict__ B, float* __restrict__ C,
    int M, int N, int K, int lda, int ldb, int ldc)
{
    extern __shared__ __half smh[];
    __half* As = smh;                          // [STAGES][128][64] swizzled
    __half* Bs = smh + STAGES * SSTRIDE_H;
    int tid = threadIdx.x;
    int warp = tid >> 5, lane = tid & 31;
    int g = lane >> 2, tg = lane & 3;
    int wm = (warp & 1) * 64, wn = (warp >> 1) * 64;

    // ldmatrix addressing (same for A and B): row=(grp&1)*8+rin, chunk bit=grp>>1
    int grp = lane >> 3, rin = lane & 7;
    int rowF = (grp & 1) * 8 + rin;
    int bitF = grp >> 1;

    unsigned asBase = (unsigned)__cvta_generic_to_shared(As);
    unsigned bsBase = (unsigned)__cvta_generic_to_shared(Bs);

    const int KT = K >> 6;                 // k-tiles of 64 halves
    const int ntn = (N + 127) >> 7;
    const int ntiles = (M >> 7) * ntn;

    for (int tile = blockIdx.x; tile < ntiles; tile += gridDim.x) {
        int bm = (tile / ntn) * 128;
        int bn = (tile % ntn) * 128;

        float acc[4][8][4];
#pragma unroll
        for (int mi = 0; mi < 4; mi++)
#pragma unroll
            for (int ni = 0; ni < 8; ni++)
#pragma unroll
                for (int j = 0; j < 4; j++) acc[mi][ni][j] = 0.f;

        auto issue_stage = [&](int stage, int kt) {
            int kk = kt << 6;
            unsigned aS = asBase + (unsigned)(stage * SSTRIDE_H) * 2u;
            unsigned bS = bsBase + (unsigned)(stage * SSTRIDE_H) * 2u;
#pragma unroll
            for (int i = 0; i < 8; i++) {
                int id = tid + i * GEMM_THREADS;    // 0..1023
                int row = id >> 3, c16 = id & 7;    // 128 rows x 8 chunks of 16B
                int pc = c16 ^ (row & 7);
                unsigned off = (unsigned)(row * 128 + pc * 16);
                cp16(aS + off, A + (size_t)(bm + row) * lda + kk + c16 * 8);
                cp16(bS + off, B + (size_t)(bn + row) * ldb + kk + c16 * 8);
            }
            cp_commit();
        };

        issue_stage(0, 0);
        if (KT > 1) issue_stage(1, 1);

        for (int kt = 0; kt < KT; kt++) {
            if (kt < KT - 1) cp_wait<1>(); else cp_wait<0>();
            __syncthreads();
            if (kt + 2 < KT) issue_stage((kt + 2) % STAGES, kt + 2);

            unsigned aS = asBase + (unsigned)((kt % STAGES) * SSTRIDE_H) * 2u;
            unsigned bS = bsBase + (unsigned)((kt % STAGES) * SSTRIDE_H) * 2u;
#pragma unroll
            for (int ks = 0; ks < 4; ks++) {       // 4 k-steps of 16 halves
                unsigned af[4][4], bf[4][4];
#pragma unroll
                for (int mi = 0; mi < 4; mi++) {
                    unsigned addr = aS
                        + (unsigned)((wm + mi * 16 + rowF) * 128)
                        + (unsigned)((((2*ks + bitF) ^ rin) & 7) << 4);
                    ldsm4(af[mi], addr);
                }
#pragma unroll
                for (int np = 0; np < 4; np++) {
                    unsigned addr = bS
                        + (unsigned)((wn + np * 16 + rowF) * 128)
                        + (unsigned)((((2*ks + bitF) ^ rin) & 7) << 4);
                    ldsm4(bf[np], addr);
                }
#pragma unroll
                for (int mi = 0; mi < 4; mi++) {
#pragma unroll
                    for (int np = 0; np < 4; np++) {
                        mma_f16(acc[mi][np*2    ], af[mi], bf[np][0], bf[np][2]);
                        mma_f16(acc[mi][np*2 + 1], af[mi], bf[np][1], bf[np][3]);
                    }
                }
            }
        }

#pragma unroll
        for (int mi = 0; mi < 4; mi++) {
            int row0 = bm + wm + mi * 16 + g;
#pragma unroll
            for (int ni = 0; ni < 8; ni++) {
                int col = bn + wn + ni * 8 + 2 * tg;
                if (col < N) {
                    *(float2*)(C + (size_t)row0 * ldc + col) =
                        make_float2(acc[mi][ni][0], acc[mi][ni][1]);
                    *(float2*)(C + (size_t)(row0 + 8) * ldc + col) =
                        make_float2(acc[mi][ni][2], acc[mi][ni][3]);
                }
            }
        }
        __syncthreads();   // protect stage 0 before next tile's prologue
    }
}

// ---------------- causal depthwise conv (K=4) + bias + SiLU ----------------
__global__ __launch_bounds__(256) void conv_silu_kernel(
    const float* __restrict__ cw, const float* __restrict__ cb)
{
    int idx = blockIdx.x * 256 + threadIdx.x;
    int c = idx % CONV_DIM;
    int t = idx / CONV_DIM;
    int l = t % L_SEQ, b = t / L_SEQ;
    float acc = cb[c];
#pragma unroll
    for (int k = 0; k < 4; k++) {
        int ll = l - 3 + k;
        if (ll >= 0)
            acc += g_proj[((size_t)(b*L_SEQ + ll))*PROJ + D_INNER + c] * cw[c*4 + k];
    }
    acc = acc / (1.f + __expf(-acc));
    g_xc[(size_t)t*CONV_DIM + c] = acc;
}

// ------- dt softplus + per-64-chunk inclusive cumsum of dt*A ---------------
__global__ __launch_bounds__(256) void dtscan_kernel(
    const float* __restrict__ dt_bias, const float* __restrict__ A_log)
{
    __shared__ float s[256];
    int z = blockIdx.x;
    int q = z & 7, h = (z >> 3) & 63, b = z >> 9;
    int t = threadIdx.x;
    int gl = q*256 + t;
    float raw = g_proj[((size_t)(b*L_SEQ + gl))*PROJ + D_INNER + CONV_DIM + h] + dt_bias[h];
    float dts = (raw > 20.f) ? raw : log1pf(__expf(raw));
    g_dtsp[(size_t)(b*L_SEQ + gl)*NH + h] = dts;
    s[t] = -dts * __expf(A_log[h]);
    __syncthreads();
    for (int off = 1; off < 64; off <<= 1) {
        float v = ((t & 63) >= off) ? s[t - off] : 0.f;
        __syncthreads();
        s[t] += v;
        __syncthreads();
    }
    int c = gl >> 6;
    g_Acum[((size_t)((b*NH + h)*NC + c))*CS + (gl & 63)] = s[t];
}

// ---------------- G[l][s] = C[l]·B[s] per (b,chunk), fp32 ------------------
__global__ __launch_bounds__(256) void gt_kernel()
{
    extern __shared__ float smg[];
    float* Bs = smg;              // [64][132]
    float* Cs = smg + 64*132;
    int z = blockIdx.x;
    int c = z & 31, b = z >> 5;
    int tid = threadIdx.x;
    size_t t0 = (size_t)(b*L_SEQ + c*CS);
    for (int idx = tid; idx < 64*128; idx += 256) {
        int l = idx >> 7, n = idx & 127;
        Bs[l*132 + n] = g_xc[(t0 + l)*CONV_DIM + D_INNER + n];
        Cs[l*132 + n] = g_xc[(t0 + l)*CONV_DIM + D_INNER + NDIM + n];
    }
    __syncthreads();
    int l = tid >> 2, sb = tid & 3;
    float acc[16];
#pragma unroll
    for (int i = 0; i < 16; i++) acc[i] = 0.f;
    for (int k = 0; k < 128; k++) {
        float cl = Cs[l*132 + k];
#pragma unroll
        for (int i = 0; i < 16; i++)
            acc[i] += cl * Bs[(sb*16 + i)*132 + k];
    }
    float* gout = g_Gt + (size_t)(b*NC + c)*CS*CS + l*CS + sb*16;
#pragma unroll
    for (int i = 0; i < 16; i++) gout[i] = acc[i];
}

// ---------------- fused chunk forward: Y_diag (+D*x) and states ------------
__global__ __launch_bounds__(256) void chunk_fwd_kernel(const float* __restrict__ Dp)
{
    extern __shared__ float smc[];
    float* XdtT = smc;             // [64][68]
    float* W    = smc + 64*68;     // [64][68]
    float* BT   = smc + 2*64*68;   // [128][68]
    float* Acs  = smc + 2*64*68 + 128*68;
    float* dts  = Acs + 64;
    float* dec  = dts + 64;

    int z = blockIdx.x;
    int h = z & 63, c = (z >> 6) & 31, b = z >> 11;
    int tid = threadIdx.x;
    size_t t0 = (size_t)(b*L_SEQ + c*CS);

    if (tid < 64) {
        Acs[tid] = g_Acum[((size_t)((b*NH + h)*NC + c))*CS + tid];
        dts[tid] = g_dtsp[(t0 + tid)*NH + h];
    }
    __syncthreads();
    if (tid < 64) dec[tid] = __expf(Acs[63] - Acs[tid]);

    {
        int p = tid & 63, lg = tid >> 6;
#pragma unroll
        for (int i = 0; i < 16; i++) {
            int l = lg*16 + i;
            float v = g_xc[(t0 + l)*CONV_DIM + h*64 + p] * dts[l];
            XdtT[p*68 + l] = f2tf(v);
        }
    }
    {
        int l = tid >> 2, sb = tid & 3;
        const float* grow = g_Gt + (size_t)(b*NC + c)*CS*CS + l*CS;
        float al = Acs[l];
        float dg = Dp[h] / fmaxf(dts[l], 1e-30f);
#pragma unroll
        for (int i = 0; i < 16; i++) {
            int s = sb*16 + i;
            float wv;
            if (s < l)       wv = f2tf(grow[s] * __expf(al - Acs[s]));
            else if (s == l) wv = f2tf(grow[s] + dg);
            else             wv = 0.f;
            W[l*68 + s] = wv;
        }
    }
    __syncthreads();
    {
        int n = tid & 127, lg = tid >> 7;
#pragma unroll
        for (int i = 0; i < 32; i++) {
            int l = lg*32 + i;
            float v = g_xc[(t0 + l)*CONV_DIM + D_INNER + n] * dec[l];
            BT[n*68 + l] = f2tf(v);
        }
    }
    __syncthreads();

    int warp = tid >> 5, lane = tid & 31;
    int g = lane >> 2, tg = lane & 3;

    {
        int wm = (warp & 3) * 16, wn = (warp >> 2) * 32;
        float acc[4][4];
#pragma unroll
        for (int ni = 0; ni < 4; ni++)
#pragma unroll
            for (int j = 0; j < 4; j++) acc[ni][j] = 0.f;
#pragma unroll
        for (int ks = 0; ks < 8; ks++) {
            int k0 = ks*8 + tg;
            unsigned a[4];
            a[0] = __float_as_uint(W[(wm + g    )*68 + k0    ]);
            a[1] = __float_as_uint(W[(wm + g + 8)*68 + k0    ]);
            a[2] = __float_as_uint(W[(wm + g    )*68 + k0 + 4]);
            a[3] = __float_as_uint(W[(wm + g + 8)*68 + k0 + 4]);
#pragma unroll
            for (int ni = 0; ni < 4; ni++) {
                unsigned bb[2];
                bb[0] = __float_as_uint(XdtT[(wn + ni*8 + g)*68 + k0    ]);
                bb[1] = __float_as_uint(XdtT[(wn + ni*8 + g)*68 + k0 + 4]);
                mma_tf32(acc[ni], a, bb);
            }
        }
        int r0 = wm + g, r1 = wm + g + 8;
#pragma unroll
        for (int ni = 0; ni < 4; ni++) {
            int col = wn + ni*8 + 2*tg;
            *(float2*)(g_y + (t0 + r0)*D_INNER + h*64 + col) =
                make_float2(acc[ni][0], acc[ni][1]);
            *(float2*)(g_y + (t0 + r1)*D_INNER + h*64 + col) =
                make_float2(acc[ni][2], acc[ni][3]);
        }
    }

    {
        int wm = (warp & 3) * 16, wn = (warp >> 2) * 64;
        float acc[8][4];
#pragma unroll
        for (int ni = 0; ni < 8; ni++)
#pragma unroll
            for (int j = 0; j < 4; j++) acc[ni][j] = 0.f;
#pragma unroll
        for (int ks = 0; ks < 8; ks++) {
            int k0 = ks*8 + tg;
            unsigned a[4];
            a[0] = __float_as_uint(XdtT[(wm + g    )*68 + k0    ]);
            a[1] = __float_as_uint(XdtT[(wm + g + 8)*68 + k0    ]);
            a[2] = __float_as_uint(XdtT[(wm + g    )*68 + k0 + 4]);
            a[3] = __float_as_uint(XdtT[(wm + g + 8)*68 + k0 + 4]);
#pragma unroll
            for (int ni = 0; ni < 8; ni++) {
                unsigned bb[2];
                bb[0] = __float_as_uint(BT[(wn + ni*8 + g)*68 + k0    ]);
                bb[1] = __float_as_uint(BT[(wn + ni*8 + g)*68 + k0 + 4]);
                mma_tf32(acc[ni], a, bb);
            }
        }
        float* sb = g_states + ((size_t)((b*NC + c)*NH + h))*PDIM*NDIM;
        int r0 = wm + g, r1 = wm + g + 8;
#pragma unroll
        for (int ni = 0; ni < 8; ni++) {
            int col = wn + ni*8 + 2*tg;
            *(float2*)(sb + (size_t)r0*NDIM + col) = make_float2(acc[ni][0], acc[ni][1]);
            *(float2*)(sb + (size_t)r1*NDIM + col) = make_float2(acc[ni][2], acc[ni][3]);
        }
    }
}

// ---------------- inter-chunk scan ------------------------------------------
__global__ __launch_bounds__(256) void scan_kernel()
{
    int idx = blockIdx.x * 256 + threadIdx.x;
    int n = idx & 127;
    int p = (idx >> 7) & 63;
    int h = (idx >> 13) & 63;
    int b = idx >> 19;
    float carry = 0.f;
    for (int c = 0; c < NC; c++) {
        size_t off = ((size_t)((b*NC + c)*NH + h))*PDIM*NDIM + (size_t)p*NDIM + n;
        float dal = g_Acum[((size_t)((b*NH + h)*NC + c))*CS + (CS-1)];
        float s = g_states[off];
        g_prev[off] = carry;
        carry = carry * __expf(dal) + s;
    }
}

// ---------------- inter-chunk contribution (tf32 mma) -----------------------
__global__ __launch_bounds__(256) void yoff_kernel()
{
    extern __shared__ float smo[];
    float* Cs  = smo;             // [64][132] tf32, n fast
    float* Pv  = smo + 64*132;    // [64][132] prev[p][n] tf32
    float* Acs = smo + 2*64*132;  // [64]
    int z = blockIdx.x;
    int h = z & 63, c = (z >> 6) & 31, b = z >> 11;
    int tid = threadIdx.x;
    size_t t0 = (size_t)(b*L_SEQ + c*CS);

    if (tid < 64) Acs[tid] = g_Acum[((size_t)((b*NH + h)*NC + c))*CS + tid];
    {
        int n = tid & 127, rg = tid >> 7;
        const float* pb = g_prev + ((size_t)((b*NC + c)*NH + h))*PDIM*NDIM;
#pragma unroll
        for (int i = 0; i < 32; i++) {
            int row = rg*32 + i;
            Cs[row*132 + n] = f2tf(g_xc[(t0 + row)*CONV_DIM + D_INNER + NDIM + n]);
            Pv[row*132 + n] = f2tf(pb[(size_t)row*NDIM + n]);
        }
    }
    __syncthreads();

    int warp = tid >> 5, lane = tid & 31;
    int g = lane >> 2, tg = lane & 3;
    int wm = (warp & 3) * 16;
    int wn = (warp >> 2) * 32;

    float acc[4][4];
#pragma unroll
    for (int ni = 0; ni < 4; ni++)
#pragma unroll
        for (int j = 0; j < 4; j++) acc[ni][j] = 0.f;

#pragma unroll
    for (int ks = 0; ks < 16; ks++) {
        int k0 = ks*8 + tg;
        unsigned a[4];
        a[0] = __float_as_uint(Cs[(wm + g    )*132 + k0    ]);
        a[1] = __float_as_uint(Cs[(wm + g + 8)*132 + k0    ]);
        a[2] = __float_as_uint(Cs[(wm + g    )*132 + k0 + 4]);
        a[3] = __float_as_uint(Cs[(wm + g + 8)*132 + k0 + 4]);
#pragma unroll
        for (int ni = 0; ni < 4; ni++) {
            unsigned bb[2];
            bb[0] = __float_as_uint(Pv[(wn + ni*8 + g)*132 + k0    ]);
            bb[1] = __float_as_uint(Pv[(wn + ni*8 + g)*132 + k0 + 4]);
            mma_tf32(acc[ni], a, bb);
        }
    }

    float e0 = __expf(Acs[wm + g]);
    float e1 = __expf(Acs[wm + g + 8]);
#pragma unroll
    for (int ni = 0; ni < 4; ni++) {
        int col = wn + ni*8 + 2*tg;
        float* y0 = g_y + (t0 + wm + g)*D_INNER + h*64 + col;
        float* y1 = g_y + (t0 + wm + g + 8)*D_INNER + h*64 + col;
        float2 v0 = *(float2*)y0;
        float2 v1 = *(float2*)y1;
        v0.x += e0*acc[ni][0]; v0.y += e0*acc[ni][1];
        v1.x += e1*acc[ni][2]; v1.y += e1*acc[ni][3];
        *(float2*)y0 = v0;
        *(float2*)y1 = v1;
    }
}

// ---------------- gated RMSNorm (writes fp16 output for out-proj) ----------
__global__ __launch_bounds__(256) void norm_kernel(const float* __restrict__ norm_w)
{
    __shared__ float gs[D_INNER];
    __shared__ float red[8];
    int t = blockIdx.x;
    int tid = threadIdx.x;
    const float* zrow = g_proj + (size_t)t * PROJ;
    const float* yrow = g_y + (size_t)t * D_INNER;
    __half* orow = g_yh + (size_t)t * D_INNER;
    float sum = 0.f;
    for (int i = tid; i < D_INNER; i += 256) {
        float zv = zrow[i];
        float g = yrow[i] * (zv / (1.f + __expf(-zv)));
        gs[i] = g;
        sum += g*g;
    }
#pragma unroll
    for (int o = 16; o; o >>= 1) sum += __shfl_xor_sync(0xffffffffu, sum, o);
    if ((tid & 31) == 0) red[tid >> 5] = sum;
    __syncthreads();
    if (tid < 8) {
        float v = red[tid];
#pragma unroll
        for (int o = 4; o; o >>= 1) v += __shfl_xor_sync(0xffu, v, o);
        if (tid == 0) red[0] = v;
    }
    __syncthreads();
    float r = rsqrtf(red[0] / (float)D_INNER + 1e-5f);
    for (int i = tid; i < D_INNER; i += 256)
        orow[i] = __float2half(gs[i] * r * norm_w[i]);
}

// ---------------- launch ---------------------------------------------------
extern "C" void kernel_launch(void* const* d_in, const int* in_sizes, int n_in,
                              void* d_out, int out_size)
{
    const float* hs      = (const float*)d_in[0];
    const float* W_in    = (const float*)d_in[1];
    const float* conv_w  = (const float*)d_in[2];
    const float* conv_b  = (const float*)d_in[3];
    const float* dt_bias = (const float*)d_in[4];
    const float* A_log   = (const float*)d_in[5];
    const float* Dp      = (const float*)d_in[6];
    const float* norm_w  = (const float*)d_in[7];
    const float* W_out   = (const float*)d_in[8];
    float* out = (float*)d_out;

    float *proj;
    __half *hsh, *Wih, *Woh, *yh;
    cudaGetSymbolAddress((void**)&proj, g_proj);
    cudaGetSymbolAddress((void**)&hsh,  g_hsh);
    cudaGetSymbolAddress((void**)&Wih,  g_Wih);
    cudaGetSymbolAddress((void**)&Woh,  g_Woh);
    cudaGetSymbolAddress((void**)&yh,   g_yh);

    const int gemmsm  = STAGES * 2 * SSTRIDE_H * (int)sizeof(__half);       // 98,304 B
    const int gtsm    = 2 * 64 * 132 * (int)sizeof(float);
    const int chunksm = (2*64*68 + 128*68 + 3*64) * (int)sizeof(float);
    const int yoffsm  = (2*64*132 + 64) * (int)sizeof(float);
    cudaFuncSetAttribute(gemm_f16_pipe,    cudaFuncAttributeMaxDynamicSharedMemorySize, gemmsm);
    cudaFuncSetAttribute(gt_kernel,        cudaFuncAttributeMaxDynamicSharedMemorySize, gtsm);
    cudaFuncSetAttribute(chunk_fwd_kernel, cudaFuncAttributeMaxDynamicSharedMemorySize, chunksm);
    cudaFuncSetAttribute(yoff_kernel,      cudaFuncAttributeMaxDynamicSharedMemorySize, yoffsm);

    const int M = NBATCH * L_SEQ;   // 4096 tokens
    const int NBLK = 296;           // persistent grid

    // 0) convert operands to fp16
    {
        int n1 = M * HIDDEN;
        tohalf_kernel<<<(n1 + 255)/256, 256>>>(hs, hsh, n1);
        int n2 = PROJ_PAD * HIDDEN;
        tohalf_pad_kernel<<<(n2 + 255)/256, 256>>>(W_in, Wih, PROJ, PROJ_PAD, HIDDEN);
        int n3 = HIDDEN * D_INNER;
        tohalf_kernel<<<(n3 + 255)/256, 256>>>(W_out, Woh, n3);
    }

    // 1) in-proj (fp16 tensor cores, fp32 accum)
    gemm_f16_pipe<<<NBLK, GEMM_THREADS, gemmsm>>>(
        hsh, Wih, proj, M, PROJ, HIDDEN, HIDDEN, HIDDEN, PROJ);

    // 2) causal conv + SiLU
    conv_silu_kernel<<<(NBATCH*L_SEQ*CONV_DIM)/256, 256>>>(conv_w, conv_b);

    // 3) dt softplus + per-64-chunk cumsum
    dtscan_kernel<<<NBATCH*NH*8, 256>>>(dt_bias, A_log);

    // 4) G[l][s] = C[l]·B[s] per (b,chunk)
    gt_kernel<<<NBATCH*NC, 256, gtsm>>>();

    // 5) fused Y_diag (+D*x) and per-chunk states
    chunk_fwd_kernel<<<NBATCH*NC*NH, 256, chunksm>>>(Dp);

    // 6) inter-chunk scan
    scan_kernel<<<(NBATCH*NH*PDIM*NDIM)/256, 256>>>();

    // 7) inter-chunk contribution (tf32 mma)
    yoff_kernel<<<NBATCH*NC*NH, 256, yoffsm>>>();

    // 8) gated RMSNorm (emits fp16 y)
    norm_kernel<<<M, 256>>>(norm_w);

    // 9) out-proj (fp16 tensor cores, fp32 accum)
    gemm_f16_pipe<<<NBLK, GEMM_THREADS, gemmsm>>>(
        yh, Woh, out, M, HIDDEN, D_INNER, D_INNER, D_INNER, HIDDEN);
}